// round 3
// baseline (speedup 1.0000x reference)
#include <cuda_runtime.h>
#include <cstdint>
#include <cstddef>

#define EPS 1e-5f

// ---------------- problem constants ----------------
#define B   4096
#define TT  60
#define TS  30          // sequence length after pooling
#define H   512
#define NL  2
#define LAT 128
#define OUT 14
#define NH  4
#define DH  128
#define NG  2560        // 5 gates * H
#define K2H 1024        // 2*H

// ---------------- device scratch (no allocation allowed) ----------------
__device__ float d_combined[(size_t)B * TS * H];     // 251.7 MB
__device__ float d_seq     [(size_t)B * TS * H];     // 251.7 MB
__device__ float d_G       [(size_t)B * NG];         // 42 MB
__device__ float d_state   [(size_t)4 * B * H];      // h0,c0,h1,c1
__device__ float d_kv      [(size_t)B * TS * K2H];   // 503 MB (k|v per row)
__device__ float d_q       [(size_t)B * H];
__device__ float d_att     [(size_t)B * H];
__device__ float d_fin     [(size_t)B * H];
__device__ float d_lat     [(size_t)B * LAT];

// ---------------- zero init ----------------
__global__ void zero_kernel(float* __restrict__ p, int n) {
    int i = blockIdx.x * blockDim.x + threadIdx.x;
    int stride = gridDim.x * blockDim.x;
    for (; i < n; i += stride) p[i] = 0.0f;
}

// ---------------- frontend: conv + bn + pool + comp + projection ----------------
__global__ __launch_bounds__(256) void frontend_kernel(
    const float* __restrict__ x,
    const float* __restrict__ conv_w, const float* __restrict__ conv_b,
    const float* __restrict__ bn1_g, const float* __restrict__ bn1_b,
    const float* __restrict__ bn1_rm, const float* __restrict__ bn1_rv,
    const float* __restrict__ comp_w, const float* __restrict__ comp_b,
    const float* __restrict__ proj_w, const float* __restrict__ proj_b,
    float* __restrict__ combined)
{
    __shared__ float xs[TT][17];
    __shared__ float cw[24 * 9 * 3];
    __shared__ float cbias[24], cscale[24], cshift[24];
    __shared__ float cpw[20 * 8], cpb[20];
    __shared__ float feat[TS][44];

    const int b = blockIdx.x;
    const int tid = threadIdx.x;
    const float* xb = x + (size_t)b * TT * 17;

    for (int i = tid; i < TT * 17; i += 256) xs[i / 17][i % 17] = xb[i];
    for (int i = tid; i < 648; i += 256) cw[i] = conv_w[i];
    if (tid < 24) {
        cbias[tid] = conv_b[tid];
        float s = bn1_g[tid] * rsqrtf(bn1_rv[tid] + EPS);
        cscale[tid] = s;
        cshift[tid] = bn1_b[tid] - bn1_rm[tid] * s;
    }
    for (int i = tid; i < 160; i += 256) cpw[i] = comp_w[i];
    if (tid < 20) cpb[tid] = comp_b[tid];
    __syncthreads();

    // conv -> +bias -> relu -> bn -> maxpool(2): feat[th][o], o<24
    for (int idx = tid; idx < 24 * TS; idx += 256) {
        int o = idx % 24, th = idx / 24;
        float mx = -1e30f;
        #pragma unroll
        for (int s = 0; s < 2; s++) {
            int t = th * 2 + s;
            float acc = cbias[o];
            #pragma unroll
            for (int k = 0; k < 3; k++) {
                int tt = t + k - 1;
                if (tt >= 0 && tt < TT) {
                    #pragma unroll
                    for (int i2 = 0; i2 < 9; i2++)
                        acc += xs[tt][i2] * cw[o * 27 + i2 * 3 + k];
                }
            }
            acc = fmaxf(acc, 0.0f);
            acc = acc * cscale[o] + cshift[o];
            mx = fmaxf(mx, acc);
        }
        feat[th][o] = mx;
    }
    // comp: relu(x[:, :30, 9:] @ comp_w.T + b) -> feat[t][24+j]
    for (int idx = tid; idx < TS * 20; idx += 256) {
        int j = idx % 20, t = idx / 20;
        float acc = cpb[j];
        #pragma unroll
        for (int i2 = 0; i2 < 8; i2++) acc += xs[t][9 + i2] * cpw[j * 8 + i2];
        feat[t][24 + j] = fmaxf(acc, 0.0f);
    }
    __syncthreads();

    // projection 44 -> 512 for all 30 timesteps
    for (int h = tid; h < H; h += 256) {
        float w[44];
        #pragma unroll
        for (int f = 0; f < 44; f++) w[f] = proj_w[h * 44 + f];
        float pb = proj_b[h];
        for (int t = 0; t < TS; t++) {
            float acc = pb;
            #pragma unroll
            for (int f = 0; f < 44; f++) acc += feat[t][f] * w[f];
            combined[((size_t)b * TS + t) * H + h] = acc;
        }
    }
}

// ---------------- generic fp32 GEMM with bias: C[M,N] = [A1|A2] @ W^T + bias ----------------
// W is row-major N x Ktot. A is split: first K1 cols from A1 (row stride lda1),
// remaining from A2 (row stride lda2). Tiles: 128x128x8, 256 threads, 8x8 microtile.
#define TBM 128
#define TBN 128
#define TBK 8

__global__ __launch_bounds__(256) void gemm_bias(
    const float* __restrict__ A1, int lda1, int K1,
    const float* __restrict__ A2, int lda2,
    const float* __restrict__ W, int Ktot,
    const float* __restrict__ bias,
    float* __restrict__ C, int N)
{
    __shared__ float As[2][TBK][TBM];
    __shared__ float Bs[2][TBK][TBN];

    const int tid = threadIdx.x;
    const int m0 = blockIdx.x * TBM;
    const int n0 = blockIdx.y * TBN;
    const int tx = tid & 15, ty = tid >> 4;
    const int tm = ty * 8, tn = tx * 8;
    const int lrow = tid >> 1;           // 0..127
    const int lcol = (tid & 1) * 4;      // 0 or 4

    float acc[8][8];
    #pragma unroll
    for (int i = 0; i < 8; i++)
        #pragma unroll
        for (int j = 0; j < 8; j++) acc[i][j] = 0.0f;

    const int nt = Ktot / TBK;

    // prologue: load tile 0
    {
        int k = lcol;
        const float* pa = (k < K1) ? (A1 + (size_t)(m0 + lrow) * lda1 + k)
                                   : (A2 + (size_t)(m0 + lrow) * lda2 + (k - K1));
        float4 ra = *reinterpret_cast<const float4*>(pa);
        float4 rb = *reinterpret_cast<const float4*>(W + (size_t)(n0 + lrow) * Ktot + k);
        As[0][lcol + 0][lrow] = ra.x; As[0][lcol + 1][lrow] = ra.y;
        As[0][lcol + 2][lrow] = ra.z; As[0][lcol + 3][lrow] = ra.w;
        Bs[0][lcol + 0][lrow] = rb.x; Bs[0][lcol + 1][lrow] = rb.y;
        Bs[0][lcol + 2][lrow] = rb.z; Bs[0][lcol + 3][lrow] = rb.w;
    }
    __syncthreads();

    int cur = 0;
    for (int kt = 0; kt < nt; kt++) {
        float4 na, nb;
        const bool more = (kt + 1 < nt);
        if (more) {
            int k = (kt + 1) * TBK + lcol;
            const float* pa = (k < K1) ? (A1 + (size_t)(m0 + lrow) * lda1 + k)
                                       : (A2 + (size_t)(m0 + lrow) * lda2 + (k - K1));
            na = *reinterpret_cast<const float4*>(pa);
            nb = *reinterpret_cast<const float4*>(W + (size_t)(n0 + lrow) * Ktot + k);
        }
        #pragma unroll
        for (int k = 0; k < TBK; k++) {
            float a[8], bb[8];
            *reinterpret_cast<float4*>(&a[0]) = *reinterpret_cast<const float4*>(&As[cur][k][tm]);
            *reinterpret_cast<float4*>(&a[4]) = *reinterpret_cast<const float4*>(&As[cur][k][tm + 4]);
            *reinterpret_cast<float4*>(&bb[0]) = *reinterpret_cast<const float4*>(&Bs[cur][k][tn]);
            *reinterpret_cast<float4*>(&bb[4]) = *reinterpret_cast<const float4*>(&Bs[cur][k][tn + 4]);
            #pragma unroll
            for (int i = 0; i < 8; i++)
                #pragma unroll
                for (int j = 0; j < 8; j++)
                    acc[i][j] += a[i] * bb[j];
        }
        if (more) {
            int nx = cur ^ 1;
            As[nx][lcol + 0][lrow] = na.x; As[nx][lcol + 1][lrow] = na.y;
            As[nx][lcol + 2][lrow] = na.z; As[nx][lcol + 3][lrow] = na.w;
            Bs[nx][lcol + 0][lrow] = nb.x; Bs[nx][lcol + 1][lrow] = nb.y;
            Bs[nx][lcol + 2][lrow] = nb.z; Bs[nx][lcol + 3][lrow] = nb.w;
        }
        __syncthreads();
        cur ^= 1;
    }

    // epilogue with bias, vectorized stores
    #pragma unroll
    for (int i = 0; i < 8; i++) {
        size_t row = (size_t)(m0 + tm + i) * N + (n0 + tn);
        float4 v0, v1;
        v0.x = acc[i][0] + bias[n0 + tn + 0];
        v0.y = acc[i][1] + bias[n0 + tn + 1];
        v0.z = acc[i][2] + bias[n0 + tn + 2];
        v0.w = acc[i][3] + bias[n0 + tn + 3];
        v1.x = acc[i][4] + bias[n0 + tn + 4];
        v1.y = acc[i][5] + bias[n0 + tn + 5];
        v1.z = acc[i][6] + bias[n0 + tn + 6];
        v1.w = acc[i][7] + bias[n0 + tn + 7];
        *reinterpret_cast<float4*>(&C[row])     = v0;
        *reinterpret_cast<float4*>(&C[row + 4]) = v1;
    }
}

// ---------------- gate math + two layernorms, block per batch row ----------------
__device__ __forceinline__ float sigm(float v) { return 1.0f / (1.0f + expf(-v)); }

__device__ __forceinline__ void ln_stats(float v, float* red, float& mean, float& var) {
    float s = v, q = v * v;
    #pragma unroll
    for (int o = 16; o > 0; o >>= 1) {
        s += __shfl_down_sync(0xffffffffu, s, o);
        q += __shfl_down_sync(0xffffffffu, q, o);
    }
    int w = threadIdx.x >> 5;
    if ((threadIdx.x & 31) == 0) { red[w] = s; red[16 + w] = q; }
    __syncthreads();
    if (threadIdx.x == 0) {
        float ss = 0.0f, qq = 0.0f;
        #pragma unroll
        for (int i = 0; i < 16; i++) { ss += red[i]; qq += red[16 + i]; }
        red[32] = ss; red[33] = qq;
    }
    __syncthreads();
    mean = red[32] * (1.0f / 512.0f);
    var  = red[33] * (1.0f / 512.0f) - mean * mean;
    __syncthreads();
}

__global__ __launch_bounds__(512) void gate_kernel(
    const float* __restrict__ G,
    float* __restrict__ h, float* __restrict__ c,
    const float* __restrict__ ret,
    const float* __restrict__ eg, const float* __restrict__ ebb,
    const float* __restrict__ lg, const float* __restrict__ lbb,
    float* __restrict__ seq_out)  // may be null (layer 0)
{
    __shared__ float red[34];
    const int b = blockIdx.x;
    const int hh = threadIdx.x;
    const float* g = G + (size_t)b * NG;

    float gf = g[0 * H + hh];
    float gi = g[1 * H + hh];
    float go = g[2 * H + hh];
    float gc = g[3 * H + hh];
    float gm = g[4 * H + hh];

    float f = sigm(gf), i = sigm(gi), m = sigm(gm);
    float o = sigm(go);               // FIX: sigmoid BEFORE the layernorm
    float cc = tanhf(gc);
    float cp = c[(size_t)b * H + hh];

    float cn = f * cp + i * cc;
    float r = ret[hh];
    cn = cn * r + (1.0f - r) * cp;
    cn = m * cn + (1.0f - m) * cp;

    // o_exp = sigmoid(LN(sigmoid(g_o)))
    float mu, var;
    ln_stats(o, red, mu, var);
    float on = (o - mu) * rsqrtf(var + EPS) * eg[hh] + ebb[hh];
    float oe = sigm(on);
    float u = oe * tanhf(cn);

    float mu2, var2;
    ln_stats(u, red, mu2, var2);
    float hn = (u - mu2) * rsqrtf(var2 + EPS) * lg[hh] + lbb[hh];

    c[(size_t)b * H + hh] = cn;
    h[(size_t)b * H + hh] = hn;
    if (seq_out) seq_out[(size_t)b * TS * H + hh] = hn;
}

// ---------------- last-query attention: block per (b, head) ----------------
__global__ __launch_bounds__(128) void attn_kernel(
    const float* __restrict__ q,   // B x H
    const float* __restrict__ kv,  // (B*TS) x 1024, [k(512)|v(512)]
    float* __restrict__ att)       // B x H
{
    __shared__ float qs[DH];
    __shared__ float sc[TS];
    const int b = blockIdx.x, hd = blockIdx.y;
    const int tid = threadIdx.x;

    qs[tid] = q[(size_t)b * H + hd * DH + tid];
    __syncthreads();

    if (tid < TS) {
        const float* kr = kv + ((size_t)b * TS + tid) * K2H + hd * DH;
        float s = 0.0f;
        #pragma unroll 16
        for (int d = 0; d < DH; d++) s += qs[d] * kr[d];
        sc[tid] = s * 0.08838834764831845f;  // 1/sqrt(128)
    }
    __syncthreads();

    float mx = -1e30f;
    #pragma unroll
    for (int t = 0; t < TS; t++) mx = fmaxf(mx, sc[t]);
    float p[TS], ssum = 0.0f;
    #pragma unroll
    for (int t = 0; t < TS; t++) { p[t] = expf(sc[t] - mx); ssum += p[t]; }
    float inv = 1.0f / ssum;

    float acc = 0.0f;
    #pragma unroll
    for (int t = 0; t < TS; t++)
        acc += p[t] * kv[((size_t)b * TS + t) * K2H + H + hd * DH + tid];
    att[(size_t)b * H + hd * DH + tid] = acc * inv;
}

// ---------------- bn2 + output head ----------------
__global__ __launch_bounds__(256) void head_kernel(
    const float* __restrict__ latent,  // B x LAT (bias already applied)
    const float* __restrict__ bn2_g, const float* __restrict__ bn2_b,
    const float* __restrict__ bn2_rm, const float* __restrict__ bn2_rv,
    const float* __restrict__ out_w, const float* __restrict__ out_b,
    float* __restrict__ out)
{
    __shared__ float lw[OUT * LAT];
    __shared__ float ls[16][LAT];
    __shared__ float scale[LAT], shift[LAT];
    const int b0 = blockIdx.x * 16;
    const int tid = threadIdx.x;

    if (tid < LAT) {
        float s = bn2_g[tid] * rsqrtf(bn2_rv[tid] + EPS);
        scale[tid] = s;
        shift[tid] = bn2_b[tid] - bn2_rm[tid] * s;
    }
    for (int i = tid; i < OUT * LAT; i += 256) lw[i] = out_w[i];
    __syncthreads();

    for (int i = tid; i < 16 * LAT; i += 256) {
        int r = i / LAT, j = i % LAT;
        ls[r][j] = latent[(size_t)(b0 + r) * LAT + j] * scale[j] + shift[j];
    }
    __syncthreads();

    for (int idx = tid; idx < 16 * OUT; idx += 256) {
        int r = idx / OUT, o = idx % OUT;
        float acc = out_b[o];
        #pragma unroll 16
        for (int j = 0; j < LAT; j++) acc += ls[r][j] * lw[o * LAT + j];
        out[(size_t)(b0 + r) * OUT + o] = acc;
    }
}

// ---------------- host launch ----------------
extern "C" void kernel_launch(void* const* d_in, const int* in_sizes, int n_in,
                              void* d_out, int out_size)
{
    const float* x        = (const float*)d_in[0];
    const float* conv1_w  = (const float*)d_in[1];
    const float* conv1_b  = (const float*)d_in[2];
    const float* bn1_g    = (const float*)d_in[3];
    const float* bn1_b    = (const float*)d_in[4];
    const float* bn1_rm   = (const float*)d_in[5];
    const float* bn1_rv   = (const float*)d_in[6];
    const float* comp_w   = (const float*)d_in[7];
    const float* comp_b   = (const float*)d_in[8];
    const float* proj_w   = (const float*)d_in[9];
    const float* proj_b   = (const float*)d_in[10];
    const float* gates_w  = (const float*)d_in[11];  // (2,5,512,1024)
    const float* gates_b  = (const float*)d_in[12];  // (2,5,512)
    const float* retention= (const float*)d_in[13];
    const float* expln_g  = (const float*)d_in[14];
    const float* expln_b  = (const float*)d_in[15];
    const float* ln_g     = (const float*)d_in[16];
    const float* ln_b     = (const float*)d_in[17];
    const float* attn_in_w= (const float*)d_in[18];  // (1536,512)
    const float* attn_in_b= (const float*)d_in[19];
    const float* attn_out_w=(const float*)d_in[20];
    const float* attn_out_b=(const float*)d_in[21];
    const float* bneck_w  = (const float*)d_in[22];
    const float* bneck_b  = (const float*)d_in[23];
    const float* bn2_g    = (const float*)d_in[24];
    const float* bn2_b    = (const float*)d_in[25];
    const float* bn2_rm   = (const float*)d_in[26];
    const float* bn2_rv   = (const float*)d_in[27];
    const float* out_w    = (const float*)d_in[28];
    const float* out_b    = (const float*)d_in[29];
    float* out = (float*)d_out;

    float *combined, *seq, *G, *state, *kv, *q, *att, *fin, *lat;
    cudaGetSymbolAddress((void**)&combined, d_combined);
    cudaGetSymbolAddress((void**)&seq,      d_seq);
    cudaGetSymbolAddress((void**)&G,        d_G);
    cudaGetSymbolAddress((void**)&state,    d_state);
    cudaGetSymbolAddress((void**)&kv,       d_kv);
    cudaGetSymbolAddress((void**)&q,        d_q);
    cudaGetSymbolAddress((void**)&att,      d_att);
    cudaGetSymbolAddress((void**)&fin,      d_fin);
    cudaGetSymbolAddress((void**)&lat,      d_lat);

    const size_t NH1 = (size_t)B * H;
    float* h0 = state;
    float* c0 = state + NH1;
    float* h1 = state + 2 * NH1;
    float* c1 = state + 3 * NH1;

    // zero recurrent state
    zero_kernel<<<2048, 512>>>(state, (int)(4 * NH1));

    // frontend -> combined (B,30,512)
    frontend_kernel<<<B, 256>>>(x, conv1_w, conv1_b, bn1_g, bn1_b, bn1_rm, bn1_rv,
                                comp_w, comp_b, proj_w, proj_b, combined);

    // recurrent scan
    const float* W0 = gates_w;                       // (2560,1024)
    const float* W1 = gates_w + (size_t)NG * K2H;    // layer 1
    const float* b0 = gates_b;
    const float* b1 = gates_b + NG;

    dim3 gemm_grid(B / TBM, NG / TBN);  // 32 x 20
    for (int t = 0; t < TS; t++) {
        // layer 0: A = [combined[:,t,:] | h0]
        gemm_bias<<<gemm_grid, 256>>>(combined + (size_t)t * H, TS * H, H,
                                      h0, H, W0, K2H, b0, G, NG);
        gate_kernel<<<B, 512>>>(G, h0, c0, retention, expln_g, expln_b,
                                ln_g, ln_b, nullptr);
        // layer 1: A = [h0_new | h1]
        gemm_bias<<<gemm_grid, 256>>>(h0, H, H, h1, H, W1, K2H, b1, G, NG);
        gate_kernel<<<B, 512>>>(G, h1, c1, retention + H, expln_g + H, expln_b + H,
                                ln_g + H, ln_b + H, seq + (size_t)t * H);
    }

    // k,v for all timesteps: (B*30, 512) @ (512, 1024)
    gemm_bias<<<dim3(B * TS / TBM, K2H / TBN), 256>>>(
        seq, H, H, seq, H, attn_in_w + (size_t)H * H, H, attn_in_b + H, kv, K2H);
    // q at last timestep: (B, 512) @ (512, 512)
    gemm_bias<<<dim3(B / TBM, H / TBN), 256>>>(
        seq + (size_t)(TS - 1) * H, TS * H, H, seq, H, attn_in_w, H, attn_in_b, q, H);
    // attention
    attn_kernel<<<dim3(B, NH), 128>>>(q, kv, att);
    // output projection
    gemm_bias<<<dim3(B / TBM, H / TBN), 256>>>(
        att, H, H, att, H, attn_out_w, H, attn_out_b, fin, H);
    // bottleneck
    gemm_bias<<<dim3(B / TBM, LAT / TBN), 256>>>(
        fin, H, H, fin, H, bneck_w, H, bneck_b, lat, LAT);
    // bn2 + output head
    head_kernel<<<B / 16, 256>>>(lat, bn2_g, bn2_b, bn2_rm, bn2_rv, out_w, out_b, out);
}

// round 5
// speedup vs baseline: 1.9767x; 1.9767x over previous
#include <cuda_runtime.h>
#include <cstdint>
#include <cstddef>

#define EPS 1e-5f

// ---------------- problem constants ----------------
#define B   4096
#define TT  60
#define TS  30          // sequence length after pooling
#define H   512
#define LAT 128
#define OUT 14
#define NH  4
#define DH  128
#define NG  2560        // 5 gates * H
#define K2H 1024        // 2*H

// ---------------- device scratch (no allocation allowed) ----------------
__device__ float d_combined[(size_t)B * TS * H];
__device__ float d_seq     [(size_t)B * TS * H];
__device__ float d_G       [(size_t)B * NG];
__device__ float d_state   [(size_t)4 * B * H];
__device__ float d_kv      [(size_t)B * TS * K2H];
__device__ float d_q       [(size_t)B * H];
__device__ float d_att     [(size_t)B * H];
__device__ float d_fin     [(size_t)B * H];
__device__ float d_lat     [(size_t)B * LAT];

// pre-split tf32 weights (hi/lo), packed: W0 | W1 | attn_in | attn_out | bneck
#define OFF_W0   0
#define OFF_W1   2621440
#define OFF_AIN  5242880
#define OFF_AOUT 6029312
#define OFF_BNK  6291456
#define W_TOTAL  6356992
__device__ float d_Wh[(size_t)W_TOTAL];
__device__ float d_Wl[(size_t)W_TOTAL];

// ---------------- helpers ----------------
__device__ __forceinline__ float tf32r(float x) {
    float r;
    asm("cvt.rna.tf32.f32 %0, %1;" : "=f"(r) : "f"(x));
    return r;
}

// swizzled word index within a 128x32 tile (conflict-free fragment loads)
#define SWIDX(row, k) ((row) * 32 + ((k) ^ (((row) & 7) << 2)))

#define MMA8(d, a, b) \
    asm volatile( \
        "mma.sync.aligned.m16n8k8.row.col.f32.tf32.tf32.f32 " \
        "{%0,%1,%2,%3}, {%4,%5,%6,%7}, {%8,%9}, {%0,%1,%2,%3};" \
        : "+f"((d)[0]), "+f"((d)[1]), "+f"((d)[2]), "+f"((d)[3]) \
        : "r"((a)[0]), "r"((a)[1]), "r"((a)[2]), "r"((a)[3]), \
          "r"((b)[0]), "r"((b)[1]))

#define GEMM_SMEM_BYTES 131072

// ---------------- zero init ----------------
__global__ void zero_kernel(float* __restrict__ p, int n) {
    int i = blockIdx.x * blockDim.x + threadIdx.x;
    int stride = gridDim.x * blockDim.x;
    for (; i < n; i += stride) p[i] = 0.0f;
}

// ---------------- tf32 hi/lo weight split ----------------
__global__ void split_kernel(const float* __restrict__ src,
                             float* __restrict__ hi, float* __restrict__ lo, int n) {
    int i = blockIdx.x * blockDim.x + threadIdx.x;
    int stride = gridDim.x * blockDim.x;
    for (; i < n; i += stride) {
        float v = src[i];
        float h = tf32r(v);
        hi[i] = h;
        lo[i] = tf32r(v - h);
    }
}

// ================= mma.sync tf32x3 GEMM: C[M,N] = [A1|A2] @ W^T + bias =================
// 128x128 CTA tile, 256 threads (2x4 warps, 64x32 warp tiles), K-block 32,
// double-buffered smem with Ah|Al|Bh|Bl (weights pre-split in global).
__global__ __launch_bounds__(256) void gemm_mma(
    const float* __restrict__ A1, int lda1, int K1,
    const float* __restrict__ A2, int lda2,
    const float* __restrict__ Wh, const float* __restrict__ Wl, int Ktot,
    const float* __restrict__ bias,
    float* __restrict__ C, int N)
{
    extern __shared__ float sm[];   // 2 stages x (Ah|Al|Bh|Bl) x 4096 floats

    const int tid = threadIdx.x;
    const int wid = tid >> 5, lane = tid & 31;
    const int g = lane >> 2, t4 = lane & 3;
    const int warp_m = wid >> 2, warp_n = wid & 3;
    const int m0 = blockIdx.x * 128, n0 = blockIdx.y * 128;
    const int r = tid >> 1;              // loader row 0..127
    const int c4b = (tid & 1) * 4;       // loader float4 index base

    float acc[4][4][4];
    #pragma unroll
    for (int i = 0; i < 4; i++)
        #pragma unroll
        for (int j = 0; j < 4; j++)
            #pragma unroll
            for (int e = 0; e < 4; e++) acc[i][j][e] = 0.0f;

    const int NKB = Ktot / 32;
    float4 pa[4], pbh[4], pbl[4];

    // prefetch k-block 0
    {
        const float* arow = (0 < K1) ? (A1 + (size_t)(m0 + r) * lda1)
                                     : (A2 + (size_t)(m0 + r) * lda2 - K1);
        const float* bh = Wh + (size_t)(n0 + r) * Ktot;
        const float* bl = Wl + (size_t)(n0 + r) * Ktot;
        #pragma unroll
        for (int j = 0; j < 4; j++) {
            pa[j]  = *(const float4*)(arow + (c4b + j) * 4);
            pbh[j] = *(const float4*)(bh + (c4b + j) * 4);
            pbl[j] = *(const float4*)(bl + (c4b + j) * 4);
        }
    }

    for (int kb = 0; kb < NKB; kb++) {
        const int s = kb & 1;
        float* Sah = sm + s * 16384;
        float* Sal = Sah + 4096;
        float* Sbh = Sah + 8192;
        float* Sbl = Sah + 12288;

        // stage prefetched block (split A on the fly)
        #pragma unroll
        for (int j = 0; j < 4; j++) {
            const int cc = c4b + j;
            const int o = r * 32 + ((cc * 4) ^ ((r & 7) << 2));
            float4 a = pa[j], ah, al;
            ah.x = tf32r(a.x); al.x = tf32r(a.x - ah.x);
            ah.y = tf32r(a.y); al.y = tf32r(a.y - ah.y);
            ah.z = tf32r(a.z); al.z = tf32r(a.z - ah.z);
            ah.w = tf32r(a.w); al.w = tf32r(a.w - ah.w);
            *(float4*)(Sah + o) = ah;
            *(float4*)(Sal + o) = al;
            *(float4*)(Sbh + o) = pbh[j];
            *(float4*)(Sbl + o) = pbl[j];
        }
        __syncthreads();

        // prefetch next block (overlaps with mma below)
        if (kb + 1 < NKB) {
            const int kbase = (kb + 1) * 32;
            const float* arow = (kbase < K1)
                ? (A1 + (size_t)(m0 + r) * lda1 + kbase)
                : (A2 + (size_t)(m0 + r) * lda2 + (kbase - K1));
            const float* bh = Wh + (size_t)(n0 + r) * Ktot + kbase;
            const float* bl = Wl + (size_t)(n0 + r) * Ktot + kbase;
            #pragma unroll
            for (int j = 0; j < 4; j++) {
                pa[j]  = *(const float4*)(arow + (c4b + j) * 4);
                pbh[j] = *(const float4*)(bh + (c4b + j) * 4);
                pbl[j] = *(const float4*)(bl + (c4b + j) * 4);
            }
        }

        // compute on stage s
        #pragma unroll
        for (int kc = 0; kc < 4; kc++) {
            const int k0 = kc * 8 + t4, k1 = k0 + 4;
            uint32_t Ah[4][4], Al[4][4];
            #pragma unroll
            for (int tm = 0; tm < 4; tm++) {
                const int r0 = warp_m * 64 + tm * 16 + g, r1 = r0 + 8;
                Ah[tm][0] = __float_as_uint(Sah[SWIDX(r0, k0)]);
                Ah[tm][1] = __float_as_uint(Sah[SWIDX(r1, k0)]);
                Ah[tm][2] = __float_as_uint(Sah[SWIDX(r0, k1)]);
                Ah[tm][3] = __float_as_uint(Sah[SWIDX(r1, k1)]);
                Al[tm][0] = __float_as_uint(Sal[SWIDX(r0, k0)]);
                Al[tm][1] = __float_as_uint(Sal[SWIDX(r1, k0)]);
                Al[tm][2] = __float_as_uint(Sal[SWIDX(r0, k1)]);
                Al[tm][3] = __float_as_uint(Sal[SWIDX(r1, k1)]);
            }
            uint32_t Bh[4][2], Bl[4][2];
            #pragma unroll
            for (int tn = 0; tn < 4; tn++) {
                const int n = warp_n * 32 + tn * 8 + g;
                Bh[tn][0] = __float_as_uint(Sbh[SWIDX(n, k0)]);
                Bh[tn][1] = __float_as_uint(Sbh[SWIDX(n, k1)]);
                Bl[tn][0] = __float_as_uint(Sbl[SWIDX(n, k0)]);
                Bl[tn][1] = __float_as_uint(Sbl[SWIDX(n, k1)]);
            }
            #pragma unroll
            for (int tm = 0; tm < 4; tm++)
                #pragma unroll
                for (int tn = 0; tn < 4; tn++) {
                    MMA8(acc[tm][tn], Ah[tm], Bh[tn]);
                    MMA8(acc[tm][tn], Ah[tm], Bl[tn]);
                    MMA8(acc[tm][tn], Al[tm], Bh[tn]);
                }
        }
        __syncthreads();
    }

    // epilogue with bias
    #pragma unroll
    for (int tm = 0; tm < 4; tm++) {
        const int row0 = m0 + warp_m * 64 + tm * 16 + g;
        #pragma unroll
        for (int tn = 0; tn < 4; tn++) {
            const int col = n0 + warp_n * 32 + tn * 8 + t4 * 2;
            const float b0 = bias[col], b1 = bias[col + 1];
            float2 v0, v1;
            v0.x = acc[tm][tn][0] + b0; v0.y = acc[tm][tn][1] + b1;
            v1.x = acc[tm][tn][2] + b0; v1.y = acc[tm][tn][3] + b1;
            *(float2*)(C + (size_t)row0 * N + col)       = v0;
            *(float2*)(C + (size_t)(row0 + 8) * N + col) = v1;
        }
    }
}

// ---------------- frontend: conv + bn + pool + comp + projection ----------------
__global__ __launch_bounds__(256) void frontend_kernel(
    const float* __restrict__ x,
    const float* __restrict__ conv_w, const float* __restrict__ conv_b,
    const float* __restrict__ bn1_g, const float* __restrict__ bn1_b,
    const float* __restrict__ bn1_rm, const float* __restrict__ bn1_rv,
    const float* __restrict__ comp_w, const float* __restrict__ comp_b,
    const float* __restrict__ proj_w, const float* __restrict__ proj_b,
    float* __restrict__ combined)
{
    __shared__ float xs[TT][17];
    __shared__ float cw[24 * 9 * 3];
    __shared__ float cbias[24], cscale[24], cshift[24];
    __shared__ float cpw[20 * 8], cpb[20];
    __shared__ float feat[TS][44];

    const int b = blockIdx.x;
    const int tid = threadIdx.x;
    const float* xb = x + (size_t)b * TT * 17;

    for (int i = tid; i < TT * 17; i += 256) xs[i / 17][i % 17] = xb[i];
    for (int i = tid; i < 648; i += 256) cw[i] = conv_w[i];
    if (tid < 24) {
        cbias[tid] = conv_b[tid];
        float s = bn1_g[tid] * rsqrtf(bn1_rv[tid] + EPS);
        cscale[tid] = s;
        cshift[tid] = bn1_b[tid] - bn1_rm[tid] * s;
    }
    for (int i = tid; i < 160; i += 256) cpw[i] = comp_w[i];
    if (tid < 20) cpb[tid] = comp_b[tid];
    __syncthreads();

    for (int idx = tid; idx < 24 * TS; idx += 256) {
        int o = idx % 24, th = idx / 24;
        float mx = -1e30f;
        #pragma unroll
        for (int s = 0; s < 2; s++) {
            int t = th * 2 + s;
            float acc = cbias[o];
            #pragma unroll
            for (int k = 0; k < 3; k++) {
                int tt = t + k - 1;
                if (tt >= 0 && tt < TT) {
                    #pragma unroll
                    for (int i2 = 0; i2 < 9; i2++)
                        acc += xs[tt][i2] * cw[o * 27 + i2 * 3 + k];
                }
            }
            acc = fmaxf(acc, 0.0f);
            acc = acc * cscale[o] + cshift[o];
            mx = fmaxf(mx, acc);
        }
        feat[th][o] = mx;
    }
    for (int idx = tid; idx < TS * 20; idx += 256) {
        int j = idx % 20, t = idx / 20;
        float acc = cpb[j];
        #pragma unroll
        for (int i2 = 0; i2 < 8; i2++) acc += xs[t][9 + i2] * cpw[j * 8 + i2];
        feat[t][24 + j] = fmaxf(acc, 0.0f);
    }
    __syncthreads();

    for (int hh = tid; hh < H; hh += 256) {
        float w[44];
        #pragma unroll
        for (int f = 0; f < 44; f++) w[f] = proj_w[hh * 44 + f];
        float pb = proj_b[hh];
        for (int t = 0; t < TS; t++) {
            float acc = pb;
            #pragma unroll
            for (int f = 0; f < 44; f++) acc += feat[t][f] * w[f];
            combined[((size_t)b * TS + t) * H + hh] = acc;
        }
    }
}

// ---------------- gate math + two layernorms: warp per batch row ----------------
__device__ __forceinline__ float sigm(float v) { return 1.0f / (1.0f + expf(-v)); }

__device__ __forceinline__ void warp_ln(const float* v, float& mu, float& rs) {
    float s = 0.0f, q = 0.0f;
    #pragma unroll
    for (int i = 0; i < 16; i++) { s += v[i]; q += v[i] * v[i]; }
    #pragma unroll
    for (int o = 16; o > 0; o >>= 1) {
        s += __shfl_xor_sync(0xffffffffu, s, o);
        q += __shfl_xor_sync(0xffffffffu, q, o);
    }
    mu = s * (1.0f / 512.0f);
    rs = rsqrtf(q * (1.0f / 512.0f) - mu * mu + EPS);
}

__global__ __launch_bounds__(256) void gate_kernel(
    const float* __restrict__ G,
    float* __restrict__ h, float* __restrict__ c,
    const float* __restrict__ ret,
    const float* __restrict__ eg, const float* __restrict__ ebb,
    const float* __restrict__ lg, const float* __restrict__ lbb,
    float* __restrict__ seq_out)  // may be null (layer 0)
{
    const int wid = threadIdx.x >> 5, lid = threadIdx.x & 31;
    const size_t b = (size_t)blockIdx.x * 8 + wid;
    const float* g = G + b * NG;
    float* crow = c + b * H;
    float* hrow = h + b * H;

    float o_[16], cn_[16];
    #pragma unroll
    for (int j = 0; j < 4; j++) {
        const int col = lid * 4 + j * 128;
        float4 vf = *(const float4*)(g + 0 * H + col);
        float4 vi = *(const float4*)(g + 1 * H + col);
        float4 vo = *(const float4*)(g + 2 * H + col);
        float4 vc = *(const float4*)(g + 3 * H + col);
        float4 vm = *(const float4*)(g + 4 * H + col);
        float4 cp = *(const float4*)(crow + col);
        float4 rr = *(const float4*)(ret + col);
        float bf[4], bi[4], bo[4], bc[4], bm[4], bp[4], br[4];
        *(float4*)bf = vf; *(float4*)bi = vi; *(float4*)bo = vo;
        *(float4*)bc = vc; *(float4*)bm = vm; *(float4*)bp = cp; *(float4*)br = rr;
        #pragma unroll
        for (int e = 0; e < 4; e++) {
            float f = sigm(bf[e]), iv = sigm(bi[e]), m = sigm(bm[e]);
            float ccv = tanhf(bc[e]);
            float cpv = bp[e], rv = br[e];
            float cn = f * cpv + iv * ccv;
            cn = cn * rv + (1.0f - rv) * cpv;
            cn = m * cn + (1.0f - m) * cpv;
            cn_[j * 4 + e] = cn;
            o_[j * 4 + e] = sigm(bo[e]);
        }
    }

    float mu1, rs1;
    warp_ln(o_, mu1, rs1);
    float u_[16];
    #pragma unroll
    for (int j = 0; j < 4; j++) {
        const int col = lid * 4 + j * 128;
        float4 ge = *(const float4*)(eg + col);
        float4 be = *(const float4*)(ebb + col);
        float g_[4], b_[4];
        *(float4*)g_ = ge; *(float4*)b_ = be;
        #pragma unroll
        for (int e = 0; e < 4; e++) {
            float on = (o_[j * 4 + e] - mu1) * rs1 * g_[e] + b_[e];
            u_[j * 4 + e] = sigm(on) * tanhf(cn_[j * 4 + e]);
        }
    }

    float mu2, rs2;
    warp_ln(u_, mu2, rs2);
    #pragma unroll
    for (int j = 0; j < 4; j++) {
        const int col = lid * 4 + j * 128;
        float4 gl = *(const float4*)(lg + col);
        float4 bl = *(const float4*)(lbb + col);
        float g_[4], b_[4], hn[4], cv[4];
        *(float4*)g_ = gl; *(float4*)b_ = bl;
        #pragma unroll
        for (int e = 0; e < 4; e++) {
            hn[e] = (u_[j * 4 + e] - mu2) * rs2 * g_[e] + b_[e];
            cv[e] = cn_[j * 4 + e];
        }
        *(float4*)(crow + col) = *(float4*)cv;
        *(float4*)(hrow + col) = *(float4*)hn;
        if (seq_out) *(float4*)(seq_out + b * TS * H + col) = *(float4*)hn;
    }
}

// ---------------- last-query attention: block per (b, head) ----------------
__global__ __launch_bounds__(128) void attn_kernel(
    const float* __restrict__ q,
    const float* __restrict__ kv,
    float* __restrict__ att)
{
    __shared__ float qs[DH];
    __shared__ float sc[TS];
    const int b = blockIdx.x, hd = blockIdx.y;
    const int tid = threadIdx.x;

    qs[tid] = q[(size_t)b * H + hd * DH + tid];
    __syncthreads();

    if (tid < TS) {
        const float* kr = kv + ((size_t)b * TS + tid) * K2H + hd * DH;
        float s = 0.0f;
        #pragma unroll 16
        for (int d = 0; d < DH; d++) s += qs[d] * kr[d];
        sc[tid] = s * 0.08838834764831845f;
    }
    __syncthreads();

    float mx = -1e30f;
    #pragma unroll
    for (int t = 0; t < TS; t++) mx = fmaxf(mx, sc[t]);
    float p[TS], ssum = 0.0f;
    #pragma unroll
    for (int t = 0; t < TS; t++) { p[t] = expf(sc[t] - mx); ssum += p[t]; }
    float inv = 1.0f / ssum;

    float acc = 0.0f;
    #pragma unroll
    for (int t = 0; t < TS; t++)
        acc += p[t] * kv[((size_t)b * TS + t) * K2H + H + hd * DH + tid];
    att[(size_t)b * H + hd * DH + tid] = acc * inv;
}

// ---------------- bn2 + output head ----------------
__global__ __launch_bounds__(256) void head_kernel(
    const float* __restrict__ latent,
    const float* __restrict__ bn2_g, const float* __restrict__ bn2_b,
    const float* __restrict__ bn2_rm, const float* __restrict__ bn2_rv,
    const float* __restrict__ out_w, const float* __restrict__ out_b,
    float* __restrict__ out)
{
    __shared__ float lw[OUT * LAT];
    __shared__ float ls[16][LAT];
    __shared__ float scale[LAT], shift[LAT];
    const int b0 = blockIdx.x * 16;
    const int tid = threadIdx.x;

    if (tid < LAT) {
        float s = bn2_g[tid] * rsqrtf(bn2_rv[tid] + EPS);
        scale[tid] = s;
        shift[tid] = bn2_b[tid] - bn2_rm[tid] * s;
    }
    for (int i = tid; i < OUT * LAT; i += 256) lw[i] = out_w[i];
    __syncthreads();

    for (int i = tid; i < 16 * LAT; i += 256) {
        int r = i / LAT, j = i % LAT;
        ls[r][j] = latent[(size_t)(b0 + r) * LAT + j] * scale[j] + shift[j];
    }
    __syncthreads();

    for (int idx = tid; idx < 16 * OUT; idx += 256) {
        int r = idx / OUT, o = idx % OUT;
        float acc = out_b[o];
        #pragma unroll 16
        for (int j = 0; j < LAT; j++) acc += ls[r][j] * lw[o * LAT + j];
        out[(size_t)(b0 + r) * OUT + o] = acc;
    }
}

// ---------------- host launch ----------------
extern "C" void kernel_launch(void* const* d_in, const int* in_sizes, int n_in,
                              void* d_out, int out_size)
{
    const float* x        = (const float*)d_in[0];
    const float* conv1_w  = (const float*)d_in[1];
    const float* conv1_b  = (const float*)d_in[2];
    const float* bn1_g    = (const float*)d_in[3];
    const float* bn1_b    = (const float*)d_in[4];
    const float* bn1_rm   = (const float*)d_in[5];
    const float* bn1_rv   = (const float*)d_in[6];
    const float* comp_w   = (const float*)d_in[7];
    const float* comp_b   = (const float*)d_in[8];
    const float* proj_w   = (const float*)d_in[9];
    const float* proj_b   = (const float*)d_in[10];
    const float* gates_w  = (const float*)d_in[11];
    const float* gates_b  = (const float*)d_in[12];
    const float* retention= (const float*)d_in[13];
    const float* expln_g  = (const float*)d_in[14];
    const float* expln_b  = (const float*)d_in[15];
    const float* ln_g     = (const float*)d_in[16];
    const float* ln_b     = (const float*)d_in[17];
    const float* attn_in_w= (const float*)d_in[18];
    const float* attn_in_b= (const float*)d_in[19];
    const float* attn_out_w=(const float*)d_in[20];
    const float* attn_out_b=(const float*)d_in[21];
    const float* bneck_w  = (const float*)d_in[22];
    const float* bneck_b  = (const float*)d_in[23];
    const float* bn2_g    = (const float*)d_in[24];
    const float* bn2_b    = (const float*)d_in[25];
    const float* bn2_rm   = (const float*)d_in[26];
    const float* bn2_rv   = (const float*)d_in[27];
    const float* out_w    = (const float*)d_in[28];
    const float* out_b    = (const float*)d_in[29];
    float* out = (float*)d_out;

    cudaFuncSetAttribute(gemm_mma, cudaFuncAttributeMaxDynamicSharedMemorySize,
                         GEMM_SMEM_BYTES);

    float *combined, *seq, *G, *state, *kv, *q, *att, *fin, *lat, *Wh, *Wl;
    cudaGetSymbolAddress((void**)&combined, d_combined);
    cudaGetSymbolAddress((void**)&seq,      d_seq);
    cudaGetSymbolAddress((void**)&G,        d_G);
    cudaGetSymbolAddress((void**)&state,    d_state);
    cudaGetSymbolAddress((void**)&kv,       d_kv);
    cudaGetSymbolAddress((void**)&q,        d_q);
    cudaGetSymbolAddress((void**)&att,      d_att);
    cudaGetSymbolAddress((void**)&fin,      d_fin);
    cudaGetSymbolAddress((void**)&lat,      d_lat);
    cudaGetSymbolAddress((void**)&Wh,       d_Wh);
    cudaGetSymbolAddress((void**)&Wl,       d_Wl);

    const size_t NH1 = (size_t)B * H;
    float* h0 = state;
    float* c0 = state + NH1;
    float* h1 = state + 2 * NH1;
    float* c1 = state + 3 * NH1;

    zero_kernel<<<2048, 512>>>(state, (int)(4 * NH1));

    // pre-split all GEMM weights into tf32 hi/lo
    split_kernel<<<2048, 256>>>(gates_w,    Wh + OFF_W0,   Wl + OFF_W0,   2 * NG * K2H);
    split_kernel<<<1024, 256>>>(attn_in_w,  Wh + OFF_AIN,  Wl + OFF_AIN,  3 * H * H);
    split_kernel<<<512, 256>>>(attn_out_w,  Wh + OFF_AOUT, Wl + OFF_AOUT, H * H);
    split_kernel<<<128, 256>>>(bneck_w,     Wh + OFF_BNK,  Wl + OFF_BNK,  LAT * H);

    frontend_kernel<<<B, 256>>>(x, conv1_w, conv1_b, bn1_g, bn1_b, bn1_rm, bn1_rv,
                                comp_w, comp_b, proj_w, proj_b, combined);

    const float* gb0 = gates_b;
    const float* gb1 = gates_b + NG;

    dim3 gemm_grid(B / 128, NG / 128);  // 32 x 20
    for (int t = 0; t < TS; t++) {
        gemm_mma<<<gemm_grid, 256, GEMM_SMEM_BYTES>>>(
            combined + (size_t)t * H, TS * H, H, h0, H,
            Wh + OFF_W0, Wl + OFF_W0, K2H, gb0, G, NG);
        gate_kernel<<<B / 8, 256>>>(G, h0, c0, retention, expln_g, expln_b,
                                    ln_g, ln_b, nullptr);
        gemm_mma<<<gemm_grid, 256, GEMM_SMEM_BYTES>>>(
            h0, H, H, h1, H, Wh + OFF_W1, Wl + OFF_W1, K2H, gb1, G, NG);
        gate_kernel<<<B / 8, 256>>>(G, h1, c1, retention + H, expln_g + H, expln_b + H,
                                    ln_g + H, ln_b + H, seq + (size_t)t * H);
    }

    // k,v for all timesteps: (B*30, 512) @ (512, 1024); attn_in rows 512..1535
    gemm_mma<<<dim3(B * TS / 128, K2H / 128), 256, GEMM_SMEM_BYTES>>>(
        seq, H, H, seq, H,
        Wh + OFF_AIN + (size_t)H * H, Wl + OFF_AIN + (size_t)H * H, H,
        attn_in_b + H, kv, K2H);
    // q at last timestep: (B, 512) @ (512, 512); attn_in rows 0..511
    gemm_mma<<<dim3(B / 128, H / 128), 256, GEMM_SMEM_BYTES>>>(
        seq + (size_t)(TS - 1) * H, TS * H, H, seq, H,
        Wh + OFF_AIN, Wl + OFF_AIN, H, attn_in_b, q, H);
    attn_kernel<<<dim3(B, NH), 128>>>(q, kv, att);
    gemm_mma<<<dim3(B / 128, H / 128), 256, GEMM_SMEM_BYTES>>>(
        att, H, H, att, H, Wh + OFF_AOUT, Wl + OFF_AOUT, H, attn_out_b, fin, H);
    gemm_mma<<<dim3(B / 128, LAT / 128), 256, GEMM_SMEM_BYTES>>>(
        fin, H, H, fin, H, Wh + OFF_BNK, Wl + OFF_BNK, H, bneck_b, lat, LAT);
    head_kernel<<<B / 16, 256>>>(lat, bn2_g, bn2_b, bn2_rm, bn2_rv, out_w, out_b, out);
}

// round 6
// speedup vs baseline: 3.1957x; 1.6167x over previous
#include <cuda_runtime.h>
#include <cuda_bf16.h>
#include <cstdint>
#include <cstddef>

#define EPS 1e-5f

// ---------------- problem constants ----------------
#define B   4096
#define TT  60
#define TS  30          // sequence length after pooling
#define H   512
#define LAT 128
#define OUT 14
#define NH  4
#define DH  128
#define NG  2560        // 5 gates * H
#define K2H 1024        // 2*H

// ---------------- device scratch (no allocation allowed) ----------------
__device__ float d_combined[(size_t)B * TS * H];
__device__ float d_seq     [(size_t)B * TS * H];
__device__ float d_G       [(size_t)B * NG];
__device__ float d_state   [(size_t)4 * B * H];
__device__ float d_kv      [(size_t)B * TS * K2H];
__device__ float d_q       [(size_t)B * H];
__device__ float d_att     [(size_t)B * H];
__device__ float d_fin     [(size_t)B * H];
__device__ float d_lat     [(size_t)B * LAT];

// pre-split packed-bf16x2 weights (hi/lo). Offsets in uint32 words (= 2 floats).
#define OFF_W0   0
#define OFF_W1   1310720
#define OFF_AIN  2621440
#define OFF_AOUT 3014656
#define OFF_BNK  3145728
#define W_WORDS  3178496
__device__ uint32_t d_Wh[(size_t)W_WORDS];
__device__ uint32_t d_Wl[(size_t)W_WORDS];

// ---------------- helpers ----------------
__device__ __forceinline__ uint32_t pack_bf(float a, float b) {
    __nv_bfloat162 t = __floats2bfloat162_rn(a, b);
    return *reinterpret_cast<uint32_t*>(&t);
}
__device__ __forceinline__ float bf_hi(float x) {
    return __bfloat162float(__float2bfloat16_rn(x));
}

#define MMA16(d, a, b) \
    asm volatile( \
        "mma.sync.aligned.m16n8k16.row.col.f32.bf16.bf16.f32 " \
        "{%0,%1,%2,%3}, {%4,%5,%6,%7}, {%8,%9}, {%0,%1,%2,%3};" \
        : "+f"((d)[0]), "+f"((d)[1]), "+f"((d)[2]), "+f"((d)[3]) \
        : "r"((a)[0]), "r"((a)[1]), "r"((a)[2]), "r"((a)[3]), \
          "r"((b)[0]), "r"((b)[1]))

// 2 stages x (Ah|Al|Bh|Bl) x 2048 words = 65536 B
#define GEMM_SMEM_BYTES 65536

// ---------------- zero init ----------------
__global__ void zero_kernel(float* __restrict__ p, int n) {
    int i = blockIdx.x * blockDim.x + threadIdx.x;
    int stride = gridDim.x * blockDim.x;
    for (; i < n; i += stride) p[i] = 0.0f;
}

// ---------------- bf16 hi/lo packed weight split ----------------
__global__ void split_kernel(const float* __restrict__ src,
                             uint32_t* __restrict__ hi, uint32_t* __restrict__ lo,
                             int nwords) {
    int i = blockIdx.x * blockDim.x + threadIdx.x;
    int stride = gridDim.x * blockDim.x;
    for (; i < nwords; i += stride) {
        float2 v = *(const float2*)(src + 2 * (size_t)i);
        float h0 = bf_hi(v.x), h1 = bf_hi(v.y);
        hi[i] = pack_bf(h0, h1);
        lo[i] = pack_bf(v.x - h0, v.y - h1);
    }
}

// ================= mma.sync bf16x3 GEMM: C[M,N] = [A1|A2] @ W^T + bias =================
// 128x128 CTA tile, 256 threads (2x4 warps, 64x32 warp tiles), K-block 32,
// double-buffered smem, packed bf16x2 operands, AhBh+AhBl+AlBh (fp32-grade accuracy).
__global__ __launch_bounds__(256) void gemm_bf16(
    const float* __restrict__ A1, int lda1, int K1,
    const float* __restrict__ A2, int lda2,
    const uint32_t* __restrict__ Wh, const uint32_t* __restrict__ Wl, int Ktot,
    const float* __restrict__ bias,
    float* __restrict__ C, int N)
{
    extern __shared__ uint32_t sm[];

    const int tid = threadIdx.x;
    const int wid = tid >> 5, lane = tid & 31;
    const int g = lane >> 2, t4 = lane & 3;
    const int warp_m = wid >> 2, warp_n = wid & 3;
    const int m0 = blockIdx.x * 128, n0 = blockIdx.y * 128;
    const int r = tid >> 1;              // loader row 0..127
    const int half = tid & 1;            // which 16-float half of the 32-wide row
    const int swz = ((r >> 1) & 3) << 2; // word swizzle for this loader row
    const int Kw = Ktot >> 1;            // packed words per W row

    float acc[4][4][4];
    #pragma unroll
    for (int i = 0; i < 4; i++)
        #pragma unroll
        for (int j = 0; j < 4; j++)
            #pragma unroll
            for (int e = 0; e < 4; e++) acc[i][j][e] = 0.0f;

    const int NKB = Ktot / 32;
    float4 pa[4];
    uint4 pbh[2], pbl[2];

    // prefetch k-block 0
    {
        const float* arow = (0 < K1) ? (A1 + (size_t)(m0 + r) * lda1)
                                     : (A2 + (size_t)(m0 + r) * lda2 - K1);
        arow += half * 16;
        #pragma unroll
        for (int j = 0; j < 4; j++) pa[j] = *(const float4*)(arow + j * 4);
        const uint32_t* bh = Wh + (size_t)(n0 + r) * Kw + half * 8;
        const uint32_t* bl = Wl + (size_t)(n0 + r) * Kw + half * 8;
        pbh[0] = *(const uint4*)bh;       pbh[1] = *(const uint4*)(bh + 4);
        pbl[0] = *(const uint4*)bl;       pbl[1] = *(const uint4*)(bl + 4);
    }

    for (int kb = 0; kb < NKB; kb++) {
        const int s = kb & 1;
        uint32_t* Sah = sm + s * 8192;
        uint32_t* Sal = Sah + 2048;
        uint32_t* Sbh = Sah + 4096;
        uint32_t* Sbl = Sah + 6144;

        // stage prefetched block (split A on the fly; B already split+packed)
        {
            const int wb = half * 8;
            #pragma unroll
            for (int pr = 0; pr < 2; pr++) {
                float4 x = pa[2 * pr], y = pa[2 * pr + 1];
                float hx0 = bf_hi(x.x), hx1 = bf_hi(x.y), hx2 = bf_hi(x.z), hx3 = bf_hi(x.w);
                float hy0 = bf_hi(y.x), hy1 = bf_hi(y.y), hy2 = bf_hi(y.z), hy3 = bf_hi(y.w);
                uint4 hw, lw;
                hw.x = pack_bf(hx0, hx1);       hw.y = pack_bf(hx2, hx3);
                hw.z = pack_bf(hy0, hy1);       hw.w = pack_bf(hy2, hy3);
                lw.x = pack_bf(x.x - hx0, x.y - hx1);
                lw.y = pack_bf(x.z - hx2, x.w - hx3);
                lw.z = pack_bf(y.x - hy0, y.y - hy1);
                lw.w = pack_bf(y.z - hy2, y.w - hy3);
                const int o = r * 16 + ((wb + pr * 4) ^ swz);
                *(uint4*)(Sah + o) = hw;
                *(uint4*)(Sal + o) = lw;
            }
            const int o0 = r * 16 + (wb ^ swz);
            const int o1 = r * 16 + ((wb + 4) ^ swz);
            *(uint4*)(Sbh + o0) = pbh[0];   *(uint4*)(Sbh + o1) = pbh[1];
            *(uint4*)(Sbl + o0) = pbl[0];   *(uint4*)(Sbl + o1) = pbl[1];
        }
        __syncthreads();

        // prefetch next block (overlaps the mma section)
        if (kb + 1 < NKB) {
            const int kbase = (kb + 1) * 32;
            const float* arow = (kbase < K1)
                ? (A1 + (size_t)(m0 + r) * lda1 + kbase)
                : (A2 + (size_t)(m0 + r) * lda2 + (kbase - K1));
            arow += half * 16;
            #pragma unroll
            for (int j = 0; j < 4; j++) pa[j] = *(const float4*)(arow + j * 4);
            const uint32_t* bh = Wh + (size_t)(n0 + r) * Kw + kbase / 2 + half * 8;
            const uint32_t* bl = Wl + (size_t)(n0 + r) * Kw + kbase / 2 + half * 8;
            pbh[0] = *(const uint4*)bh;   pbh[1] = *(const uint4*)(bh + 4);
            pbl[0] = *(const uint4*)bl;   pbl[1] = *(const uint4*)(bl + 4);
        }

        // compute: 2 chunks of k16
        #pragma unroll
        for (int kc = 0; kc < 2; kc++) {
            const int wc = kc * 8;
            uint32_t Ah[4][4], Al[4][4];
            #pragma unroll
            for (int tm = 0; tm < 4; tm++) {
                const int r0 = warp_m * 64 + tm * 16 + g, r1 = r0 + 8;
                const int s0 = ((r0 >> 1) & 3) << 2, s1 = ((r1 >> 1) & 3) << 2;
                Ah[tm][0] = Sah[r0 * 16 + ((wc + t4) ^ s0)];
                Ah[tm][1] = Sah[r1 * 16 + ((wc + t4) ^ s1)];
                Ah[tm][2] = Sah[r0 * 16 + ((wc + t4 + 4) ^ s0)];
                Ah[tm][3] = Sah[r1 * 16 + ((wc + t4 + 4) ^ s1)];
                Al[tm][0] = Sal[r0 * 16 + ((wc + t4) ^ s0)];
                Al[tm][1] = Sal[r1 * 16 + ((wc + t4) ^ s1)];
                Al[tm][2] = Sal[r0 * 16 + ((wc + t4 + 4) ^ s0)];
                Al[tm][3] = Sal[r1 * 16 + ((wc + t4 + 4) ^ s1)];
            }
            uint32_t Bh[4][2], Bl[4][2];
            #pragma unroll
            for (int tn = 0; tn < 4; tn++) {
                const int n = warp_n * 32 + tn * 8 + g;
                const int sn = ((n >> 1) & 3) << 2;
                Bh[tn][0] = Sbh[n * 16 + ((wc + t4) ^ sn)];
                Bh[tn][1] = Sbh[n * 16 + ((wc + t4 + 4) ^ sn)];
                Bl[tn][0] = Sbl[n * 16 + ((wc + t4) ^ sn)];
                Bl[tn][1] = Sbl[n * 16 + ((wc + t4 + 4) ^ sn)];
            }
            #pragma unroll
            for (int tm = 0; tm < 4; tm++)
                #pragma unroll
                for (int tn = 0; tn < 4; tn++) {
                    MMA16(acc[tm][tn], Ah[tm], Bh[tn]);
                    MMA16(acc[tm][tn], Ah[tm], Bl[tn]);
                    MMA16(acc[tm][tn], Al[tm], Bh[tn]);
                }
        }
        __syncthreads();
    }

    // epilogue with bias
    #pragma unroll
    for (int tm = 0; tm < 4; tm++) {
        const int row0 = m0 + warp_m * 64 + tm * 16 + g;
        #pragma unroll
        for (int tn = 0; tn < 4; tn++) {
            const int col = n0 + warp_n * 32 + tn * 8 + t4 * 2;
            const float b0 = bias[col], b1 = bias[col + 1];
            float2 v0, v1;
            v0.x = acc[tm][tn][0] + b0; v0.y = acc[tm][tn][1] + b1;
            v1.x = acc[tm][tn][2] + b0; v1.y = acc[tm][tn][3] + b1;
            *(float2*)(C + (size_t)row0 * N + col)       = v0;
            *(float2*)(C + (size_t)(row0 + 8) * N + col) = v1;
        }
    }
}

// ---------------- frontend: conv + bn + pool + comp + projection ----------------
__global__ __launch_bounds__(256) void frontend_kernel(
    const float* __restrict__ x,
    const float* __restrict__ conv_w, const float* __restrict__ conv_b,
    const float* __restrict__ bn1_g, const float* __restrict__ bn1_b,
    const float* __restrict__ bn1_rm, const float* __restrict__ bn1_rv,
    const float* __restrict__ comp_w, const float* __restrict__ comp_b,
    const float* __restrict__ proj_w, const float* __restrict__ proj_b,
    float* __restrict__ combined)
{
    __shared__ float xs[TT][17];
    __shared__ float cw[24 * 9 * 3];
    __shared__ float cbias[24], cscale[24], cshift[24];
    __shared__ float cpw[20 * 8], cpb[20];
    __shared__ float feat[TS][44];

    const int b = blockIdx.x;
    const int tid = threadIdx.x;
    const float* xb = x + (size_t)b * TT * 17;

    for (int i = tid; i < TT * 17; i += 256) xs[i / 17][i % 17] = xb[i];
    for (int i = tid; i < 648; i += 256) cw[i] = conv_w[i];
    if (tid < 24) {
        cbias[tid] = conv_b[tid];
        float s = bn1_g[tid] * rsqrtf(bn1_rv[tid] + EPS);
        cscale[tid] = s;
        cshift[tid] = bn1_b[tid] - bn1_rm[tid] * s;
    }
    for (int i = tid; i < 160; i += 256) cpw[i] = comp_w[i];
    if (tid < 20) cpb[tid] = comp_b[tid];
    __syncthreads();

    for (int idx = tid; idx < 24 * TS; idx += 256) {
        int o = idx % 24, th = idx / 24;
        float mx = -1e30f;
        #pragma unroll
        for (int s = 0; s < 2; s++) {
            int t = th * 2 + s;
            float acc = cbias[o];
            #pragma unroll
            for (int k = 0; k < 3; k++) {
                int tt = t + k - 1;
                if (tt >= 0 && tt < TT) {
                    #pragma unroll
                    for (int i2 = 0; i2 < 9; i2++)
                        acc += xs[tt][i2] * cw[o * 27 + i2 * 3 + k];
                }
            }
            acc = fmaxf(acc, 0.0f);
            acc = acc * cscale[o] + cshift[o];
            mx = fmaxf(mx, acc);
        }
        feat[th][o] = mx;
    }
    for (int idx = tid; idx < TS * 20; idx += 256) {
        int j = idx % 20, t = idx / 20;
        float acc = cpb[j];
        #pragma unroll
        for (int i2 = 0; i2 < 8; i2++) acc += xs[t][9 + i2] * cpw[j * 8 + i2];
        feat[t][24 + j] = fmaxf(acc, 0.0f);
    }
    __syncthreads();

    for (int hh = tid; hh < H; hh += 256) {
        float w[44];
        #pragma unroll
        for (int f = 0; f < 44; f++) w[f] = proj_w[hh * 44 + f];
        float pb = proj_b[hh];
        for (int t = 0; t < TS; t++) {
            float acc = pb;
            #pragma unroll
            for (int f = 0; f < 44; f++) acc += feat[t][f] * w[f];
            combined[((size_t)b * TS + t) * H + hh] = acc;
        }
    }
}

// ---------------- gate math + two layernorms: warp per batch row ----------------
__device__ __forceinline__ float sigm(float v) { return 1.0f / (1.0f + expf(-v)); }

__device__ __forceinline__ void warp_ln(const float* v, float& mu, float& rs) {
    float s = 0.0f, q = 0.0f;
    #pragma unroll
    for (int i = 0; i < 16; i++) { s += v[i]; q += v[i] * v[i]; }
    #pragma unroll
    for (int o = 16; o > 0; o >>= 1) {
        s += __shfl_xor_sync(0xffffffffu, s, o);
        q += __shfl_xor_sync(0xffffffffu, q, o);
    }
    mu = s * (1.0f / 512.0f);
    rs = rsqrtf(q * (1.0f / 512.0f) - mu * mu + EPS);
}

__global__ __launch_bounds__(256) void gate_kernel(
    const float* __restrict__ G,
    float* __restrict__ h, float* __restrict__ c,
    const float* __restrict__ ret,
    const float* __restrict__ eg, const float* __restrict__ ebb,
    const float* __restrict__ lg, const float* __restrict__ lbb,
    float* __restrict__ seq_out)  // may be null (layer 0)
{
    const int wid = threadIdx.x >> 5, lid = threadIdx.x & 31;
    const size_t b = (size_t)blockIdx.x * 8 + wid;
    const float* g = G + b * NG;
    float* crow = c + b * H;
    float* hrow = h + b * H;

    float o_[16], cn_[16];
    #pragma unroll
    for (int j = 0; j < 4; j++) {
        const int col = lid * 4 + j * 128;
        float4 vf = *(const float4*)(g + 0 * H + col);
        float4 vi = *(const float4*)(g + 1 * H + col);
        float4 vo = *(const float4*)(g + 2 * H + col);
        float4 vc = *(const float4*)(g + 3 * H + col);
        float4 vm = *(const float4*)(g + 4 * H + col);
        float4 cp = *(const float4*)(crow + col);
        float4 rr = *(const float4*)(ret + col);
        float bf[4], bi[4], bo[4], bc[4], bm[4], bp[4], br[4];
        *(float4*)bf = vf; *(float4*)bi = vi; *(float4*)bo = vo;
        *(float4*)bc = vc; *(float4*)bm = vm; *(float4*)bp = cp; *(float4*)br = rr;
        #pragma unroll
        for (int e = 0; e < 4; e++) {
            float f = sigm(bf[e]), iv = sigm(bi[e]), m = sigm(bm[e]);
            float ccv = tanhf(bc[e]);
            float cpv = bp[e], rv = br[e];
            float cn = f * cpv + iv * ccv;
            cn = cn * rv + (1.0f - rv) * cpv;
            cn = m * cn + (1.0f - m) * cpv;
            cn_[j * 4 + e] = cn;
            o_[j * 4 + e] = sigm(bo[e]);
        }
    }

    float mu1, rs1;
    warp_ln(o_, mu1, rs1);
    float u_[16];
    #pragma unroll
    for (int j = 0; j < 4; j++) {
        const int col = lid * 4 + j * 128;
        float4 ge = *(const float4*)(eg + col);
        float4 be = *(const float4*)(ebb + col);
        float g_[4], b_[4];
        *(float4*)g_ = ge; *(float4*)b_ = be;
        #pragma unroll
        for (int e = 0; e < 4; e++) {
            float on = (o_[j * 4 + e] - mu1) * rs1 * g_[e] + b_[e];
            u_[j * 4 + e] = sigm(on) * tanhf(cn_[j * 4 + e]);
        }
    }

    float mu2, rs2;
    warp_ln(u_, mu2, rs2);
    #pragma unroll
    for (int j = 0; j < 4; j++) {
        const int col = lid * 4 + j * 128;
        float4 gl = *(const float4*)(lg + col);
        float4 bl = *(const float4*)(lbb + col);
        float g_[4], b_[4], hn[4], cv[4];
        *(float4*)g_ = gl; *(float4*)b_ = bl;
        #pragma unroll
        for (int e = 0; e < 4; e++) {
            hn[e] = (u_[j * 4 + e] - mu2) * rs2 * g_[e] + b_[e];
            cv[e] = cn_[j * 4 + e];
        }
        *(float4*)(crow + col) = *(float4*)cv;
        *(float4*)(hrow + col) = *(float4*)hn;
        if (seq_out) *(float4*)(seq_out + b * TS * H + col) = *(float4*)hn;
    }
}

// ---------------- last-query attention: block per (b, head) ----------------
__global__ __launch_bounds__(128) void attn_kernel(
    const float* __restrict__ q,
    const float* __restrict__ kv,
    float* __restrict__ att)
{
    __shared__ float qs[DH];
    __shared__ float sc[TS];
    const int b = blockIdx.x, hd = blockIdx.y;
    const int tid = threadIdx.x;

    qs[tid] = q[(size_t)b * H + hd * DH + tid];
    __syncthreads();

    if (tid < TS) {
        const float* kr = kv + ((size_t)b * TS + tid) * K2H + hd * DH;
        float s = 0.0f;
        #pragma unroll 16
        for (int d = 0; d < DH; d++) s += qs[d] * kr[d];
        sc[tid] = s * 0.08838834764831845f;
    }
    __syncthreads();

    float mx = -1e30f;
    #pragma unroll
    for (int t = 0; t < TS; t++) mx = fmaxf(mx, sc[t]);
    float p[TS], ssum = 0.0f;
    #pragma unroll
    for (int t = 0; t < TS; t++) { p[t] = expf(sc[t] - mx); ssum += p[t]; }
    float inv = 1.0f / ssum;

    float acc = 0.0f;
    #pragma unroll
    for (int t = 0; t < TS; t++)
        acc += p[t] * kv[((size_t)b * TS + t) * K2H + H + hd * DH + tid];
    att[(size_t)b * H + hd * DH + tid] = acc * inv;
}

// ---------------- bn2 + output head ----------------
__global__ __launch_bounds__(256) void head_kernel(
    const float* __restrict__ latent,
    const float* __restrict__ bn2_g, const float* __restrict__ bn2_b,
    const float* __restrict__ bn2_rm, const float* __restrict__ bn2_rv,
    const float* __restrict__ out_w, const float* __restrict__ out_b,
    float* __restrict__ out)
{
    __shared__ float lw[OUT * LAT];
    __shared__ float ls[16][LAT];
    __shared__ float scale[LAT], shift[LAT];
    const int b0 = blockIdx.x * 16;
    const int tid = threadIdx.x;

    if (tid < LAT) {
        float s = bn2_g[tid] * rsqrtf(bn2_rv[tid] + EPS);
        scale[tid] = s;
        shift[tid] = bn2_b[tid] - bn2_rm[tid] * s;
    }
    for (int i = tid; i < OUT * LAT; i += 256) lw[i] = out_w[i];
    __syncthreads();

    for (int i = tid; i < 16 * LAT; i += 256) {
        int r = i / LAT, j = i % LAT;
        ls[r][j] = latent[(size_t)(b0 + r) * LAT + j] * scale[j] + shift[j];
    }
    __syncthreads();

    for (int idx = tid; idx < 16 * OUT; idx += 256) {
        int r = idx / OUT, o = idx % OUT;
        float acc = out_b[o];
        #pragma unroll 16
        for (int j = 0; j < LAT; j++) acc += ls[r][j] * lw[o * LAT + j];
        out[(size_t)(b0 + r) * OUT + o] = acc;
    }
}

// ---------------- host launch ----------------
extern "C" void kernel_launch(void* const* d_in, const int* in_sizes, int n_in,
                              void* d_out, int out_size)
{
    const float* x        = (const float*)d_in[0];
    const float* conv1_w  = (const float*)d_in[1];
    const float* conv1_b  = (const float*)d_in[2];
    const float* bn1_g    = (const float*)d_in[3];
    const float* bn1_b    = (const float*)d_in[4];
    const float* bn1_rm   = (const float*)d_in[5];
    const float* bn1_rv   = (const float*)d_in[6];
    const float* comp_w   = (const float*)d_in[7];
    const float* comp_b   = (const float*)d_in[8];
    const float* proj_w   = (const float*)d_in[9];
    const float* proj_b   = (const float*)d_in[10];
    const float* gates_w  = (const float*)d_in[11];
    const float* gates_b  = (const float*)d_in[12];
    const float* retention= (const float*)d_in[13];
    const float* expln_g  = (const float*)d_in[14];
    const float* expln_b  = (const float*)d_in[15];
    const float* ln_g     = (const float*)d_in[16];
    const float* ln_b     = (const float*)d_in[17];
    const float* attn_in_w= (const float*)d_in[18];
    const float* attn_in_b= (const float*)d_in[19];
    const float* attn_out_w=(const float*)d_in[20];
    const float* attn_out_b=(const float*)d_in[21];
    const float* bneck_w  = (const float*)d_in[22];
    const float* bneck_b  = (const float*)d_in[23];
    const float* bn2_g    = (const float*)d_in[24];
    const float* bn2_b    = (const float*)d_in[25];
    const float* bn2_rm   = (const float*)d_in[26];
    const float* bn2_rv   = (const float*)d_in[27];
    const float* out_w    = (const float*)d_in[28];
    const float* out_b    = (const float*)d_in[29];
    float* out = (float*)d_out;

    cudaFuncSetAttribute(gemm_bf16, cudaFuncAttributeMaxDynamicSharedMemorySize,
                         GEMM_SMEM_BYTES);

    float *combined, *seq, *G, *state, *kv, *q, *att, *fin, *lat;
    uint32_t *Wh, *Wl;
    cudaGetSymbolAddress((void**)&combined, d_combined);
    cudaGetSymbolAddress((void**)&seq,      d_seq);
    cudaGetSymbolAddress((void**)&G,        d_G);
    cudaGetSymbolAddress((void**)&state,    d_state);
    cudaGetSymbolAddress((void**)&kv,       d_kv);
    cudaGetSymbolAddress((void**)&q,        d_q);
    cudaGetSymbolAddress((void**)&att,      d_att);
    cudaGetSymbolAddress((void**)&fin,      d_fin);
    cudaGetSymbolAddress((void**)&lat,      d_lat);
    cudaGetSymbolAddress((void**)&Wh,       d_Wh);
    cudaGetSymbolAddress((void**)&Wl,       d_Wl);

    const size_t NH1 = (size_t)B * H;
    float* h0 = state;
    float* c0 = state + NH1;
    float* h1 = state + 2 * NH1;
    float* c1 = state + 3 * NH1;

    zero_kernel<<<2048, 512>>>(state, (int)(4 * NH1));

    // pre-split all GEMM weights into packed bf16 hi/lo (word counts)
    split_kernel<<<2048, 256>>>(gates_w,    Wh + OFF_W0,   Wl + OFF_W0,   NG * K2H);
    split_kernel<<<1024, 256>>>(attn_in_w,  Wh + OFF_AIN,  Wl + OFF_AIN,  3 * H * H / 2);
    split_kernel<<<512, 256>>>(attn_out_w,  Wh + OFF_AOUT, Wl + OFF_AOUT, H * H / 2);
    split_kernel<<<128, 256>>>(bneck_w,     Wh + OFF_BNK,  Wl + OFF_BNK,  LAT * H / 2);

    frontend_kernel<<<B, 256>>>(x, conv1_w, conv1_b, bn1_g, bn1_b, bn1_rm, bn1_rv,
                                comp_w, comp_b, proj_w, proj_b, combined);

    const float* gb0 = gates_b;
    const float* gb1 = gates_b + NG;

    dim3 gemm_grid(B / 128, NG / 128);  // 32 x 20
    for (int t = 0; t < TS; t++) {
        gemm_bf16<<<gemm_grid, 256, GEMM_SMEM_BYTES>>>(
            combined + (size_t)t * H, TS * H, H, h0, H,
            Wh + OFF_W0, Wl + OFF_W0, K2H, gb0, G, NG);
        gate_kernel<<<B / 8, 256>>>(G, h0, c0, retention, expln_g, expln_b,
                                    ln_g, ln_b, nullptr);
        gemm_bf16<<<gemm_grid, 256, GEMM_SMEM_BYTES>>>(
            h0, H, H, h1, H, Wh + OFF_W1, Wl + OFF_W1, K2H, gb1, G, NG);
        gate_kernel<<<B / 8, 256>>>(G, h1, c1, retention + H, expln_g + H, expln_b + H,
                                    ln_g + H, ln_b + H, seq + (size_t)t * H);
    }

    // k,v for all timesteps: (B*30, 512) @ (512, 1024); attn_in rows 512..1535
    gemm_bf16<<<dim3(B * TS / 128, K2H / 128), 256, GEMM_SMEM_BYTES>>>(
        seq, H, H, seq, H,
        Wh + OFF_AIN + (size_t)H * H / 2, Wl + OFF_AIN + (size_t)H * H / 2, H,
        attn_in_b + H, kv, K2H);
    // q at last timestep: (B, 512) @ (512, 512); attn_in rows 0..511
    gemm_bf16<<<dim3(B / 128, H / 128), 256, GEMM_SMEM_BYTES>>>(
        seq + (size_t)(TS - 1) * H, TS * H, H, seq, H,
        Wh + OFF_AIN, Wl + OFF_AIN, H, attn_in_b, q, H);
    attn_kernel<<<dim3(B, NH), 128>>>(q, kv, att);
    gemm_bf16<<<dim3(B / 128, H / 128), 256, GEMM_SMEM_BYTES>>>(
        att, H, H, att, H, Wh + OFF_AOUT, Wl + OFF_AOUT, H, attn_out_b, fin, H);
    gemm_bf16<<<dim3(B / 128, LAT / 128), 256, GEMM_SMEM_BYTES>>>(
        fin, H, H, fin, H, Wh + OFF_BNK, Wl + OFF_BNK, H, bneck_b, lat, LAT);
    head_kernel<<<B / 16, 256>>>(lat, bn2_g, bn2_b, bn2_rm, bn2_rv, out_w, out_b, out);
}

// round 7
// speedup vs baseline: 4.2187x; 1.3202x over previous
#include <cuda_runtime.h>
#include <cuda_bf16.h>
#include <cstdint>
#include <cstddef>

#define EPS 1e-5f

// ---------------- problem constants ----------------
#define B   4096
#define TT  60
#define TS  30          // sequence length after pooling
#define H   512
#define LAT 128
#define OUT 14
#define NH  4
#define DH  128
#define NG  2560        // 5 gates * H
#define K2H 1024        // 2*H

// ---------------- device scratch (no allocation allowed) ----------------
__device__ float d_combined[(size_t)B * TS * H];      // fp32 frontend out
__device__ float d_seq     [(size_t)B * TS * H];      // fp32 scan out
__device__ float d_G       [(size_t)B * NG];
__device__ float d_c       [(size_t)2 * B * H];       // c0,c1 fp32
__device__ float d_kv      [(size_t)B * TS * K2H];
__device__ float d_q       [(size_t)B * H];
__device__ float d_lat     [(size_t)B * LAT];

// packed bf16x2 hi/lo activations (word = 2 floats)
#define HW  256                                        // words per H row
__device__ uint32_t d_combH[(size_t)B * TS * HW];
__device__ uint32_t d_combL[(size_t)B * TS * HW];
__device__ uint32_t d_seqH [(size_t)B * TS * HW];
__device__ uint32_t d_seqL [(size_t)B * TS * HW];
__device__ uint32_t d_hH   [(size_t)2 * B * HW];       // h0,h1
__device__ uint32_t d_hL   [(size_t)2 * B * HW];
__device__ uint32_t d_attH [(size_t)B * HW];
__device__ uint32_t d_attL [(size_t)B * HW];
__device__ uint32_t d_finH [(size_t)B * HW];
__device__ uint32_t d_finL [(size_t)B * HW];

// pre-split packed-bf16x2 weights (hi/lo). Offsets in uint32 words.
#define OFF_W0   0
#define OFF_W1   1310720
#define OFF_AIN  2621440
#define OFF_AOUT 3014656
#define OFF_BNK  3145728
#define W_WORDS  3178496
__device__ uint32_t d_Wh[(size_t)W_WORDS];
__device__ uint32_t d_Wl[(size_t)W_WORDS];

// ---------------- helpers ----------------
__device__ __forceinline__ uint32_t pack_bf(float a, float b) {
    __nv_bfloat162 t = __floats2bfloat162_rn(a, b);
    return *reinterpret_cast<uint32_t*>(&t);
}
__device__ __forceinline__ float bf_hi(float x) {
    return __bfloat162float(__float2bfloat16_rn(x));
}
__device__ __forceinline__ uint32_t smem_u32(const void* p) {
    uint32_t a;
    asm("{ .reg .u64 t; cvta.to.shared.u64 t, %1; cvt.u32.u64 %0, t; }" : "=r"(a) : "l"(p));
    return a;
}

#define MMA16(d, a, b) \
    asm volatile( \
        "mma.sync.aligned.m16n8k16.row.col.f32.bf16.bf16.f32 " \
        "{%0,%1,%2,%3}, {%4,%5,%6,%7}, {%8,%9}, {%0,%1,%2,%3};" \
        : "+f"((d)[0]), "+f"((d)[1]), "+f"((d)[2]), "+f"((d)[3]) \
        : "r"((a)[0]), "r"((a)[1]), "r"((a)[2]), "r"((a)[3]), \
          "r"((b)[0]), "r"((b)[1]))

#define LDSM4(v, addr) \
    asm volatile("ldmatrix.sync.aligned.m8n8.x4.shared.b16 {%0,%1,%2,%3}, [%4];" \
        : "=r"((v)[0]), "=r"((v)[1]), "=r"((v)[2]), "=r"((v)[3]) : "r"(addr))

#define CP16(dst, src) \
    asm volatile("cp.async.cg.shared.global [%0], [%1], 16;" :: "r"(dst), "l"(src))
#define CPCOMMIT() asm volatile("cp.async.commit_group;" ::: "memory")
#define CPWAIT1()  asm volatile("cp.async.wait_group 1;" ::: "memory")

// per-stage: Ah(2048) Al(2048) Bh(2048) Bl(2048) words = 32KB; 3 stages
#define STG_WORDS 8192
#define GEMM_SMEM_BYTES (3 * STG_WORDS * 4)

// ---------------- zero init ----------------
__global__ void zero_kernel(float* __restrict__ p, int n) {
    int i = blockIdx.x * blockDim.x + threadIdx.x;
    int stride = gridDim.x * blockDim.x;
    for (; i < n; i += stride) p[i] = 0.0f;
}

// ---------------- bf16 hi/lo packed split (weights + activations) ----------------
__global__ void split_kernel(const float* __restrict__ src,
                             uint32_t* __restrict__ hi, uint32_t* __restrict__ lo,
                             int nwords) {
    int i = blockIdx.x * blockDim.x + threadIdx.x;
    int stride = gridDim.x * blockDim.x;
    for (; i < nwords; i += stride) {
        float2 v = *(const float2*)(src + 2 * (size_t)i);
        float h0 = bf_hi(v.x), h1 = bf_hi(v.y);
        hi[i] = pack_bf(h0, h1);
        lo[i] = pack_bf(v.x - h0, v.y - h1);
    }
}

// ================= bf16x3 GEMM, all-packed operands, cp.async + ldmatrix ==========
// C[M,N] = [A1|A2] @ W^T + bias  with A,W as packed bf16x2 hi/lo.
// 128x128 CTA tile, 256 threads (2x4 warps, 64x32 warp tiles), K-block 16 words.
__global__ __launch_bounds__(256) void gemm_bf16(
    const uint32_t* __restrict__ A1h, const uint32_t* __restrict__ A1l,
    int lda1, int K1w,
    const uint32_t* __restrict__ A2h, const uint32_t* __restrict__ A2l,
    int lda2,
    const uint32_t* __restrict__ Wh, const uint32_t* __restrict__ Wl, int Kw,
    const float* __restrict__ bias,
    float* __restrict__ C, uint32_t* __restrict__ Ch, uint32_t* __restrict__ Cl,
    int N)
{
    extern __shared__ uint32_t sm[];
    const uint32_t smb = smem_u32(sm);

    const int tid = threadIdx.x;
    const int wid = tid >> 5, lane = tid & 31;
    const int g = lane >> 2, t4 = lane & 3;
    const int warp_m = wid >> 2, warp_n = wid & 3;
    const int m0 = blockIdx.x * 128, n0 = blockIdx.y * 128;

    // ---- loader geometry: thread -> (row, 8-word half) ----
    const int r = tid >> 1, half = tid & 1;
    const int wb = half * 8;
    const int swz = ((r >> 1) & 3) << 2;
    const int so0 = r * 16 + ((wb) ^ swz);
    const int so1 = r * 16 + ((wb + 4) ^ swz);

    // ---- ldmatrix lane geometry ----
    const int a_r = lane & 15;
    const int a_k = (lane >> 4) << 2;                   // word add 0/4
    int aoff[4], aswz[4];
    #pragma unroll
    for (int tm = 0; tm < 4; tm++) {
        const int row = warp_m * 64 + tm * 16 + a_r;
        aoff[tm] = row * 16;
        aswz[tm] = ((row >> 1) & 3) << 2;
    }
    const int b_r = (lane & 7) + ((lane >> 4) << 3);
    const int b_k = ((lane >> 3) & 1) << 2;
    int boff[2], bswz[2];
    #pragma unroll
    for (int tp = 0; tp < 2; tp++) {
        const int row = warp_n * 32 + tp * 16 + b_r;
        boff[tp] = row * 16;
        bswz[tp] = ((row >> 1) & 3) << 2;
    }

    float acc[4][4][4];
    #pragma unroll
    for (int i = 0; i < 4; i++)
        #pragma unroll
        for (int j = 0; j < 4; j++)
            #pragma unroll
            for (int e = 0; e < 4; e++) acc[i][j][e] = 0.0f;

    const int NKB = Kw / 16;

    // ---- async stage issue ----
    auto issue = [&](int kb, int stage) {
        const int kbw = kb * 16 + wb;
        const uint32_t *ah, *al;
        if (kbw < K1w) {
            ah = A1h + (size_t)(m0 + r) * lda1 + kbw;
            al = A1l + (size_t)(m0 + r) * lda1 + kbw;
        } else {
            ah = A2h + (size_t)(m0 + r) * lda2 + (kbw - K1w);
            al = A2l + (size_t)(m0 + r) * lda2 + (kbw - K1w);
        }
        const uint32_t* bh = Wh + (size_t)(n0 + r) * Kw + kbw;
        const uint32_t* bl = Wl + (size_t)(n0 + r) * Kw + kbw;
        const uint32_t sb = smb + (uint32_t)(stage * STG_WORDS) * 4;
        CP16(sb + so0 * 4, ah);                 CP16(sb + so1 * 4, ah + 4);
        CP16(sb + (2048 + so0) * 4, al);        CP16(sb + (2048 + so1) * 4, al + 4);
        CP16(sb + (4096 + so0) * 4, bh);        CP16(sb + (4096 + so1) * 4, bh + 4);
        CP16(sb + (6144 + so0) * 4, bl);        CP16(sb + (6144 + so1) * 4, bl + 4);
    };

    issue(0, 0); CPCOMMIT();
    issue(1, 1); CPCOMMIT();

    for (int kb = 0; kb < NKB; kb++) {
        CPWAIT1();
        __syncthreads();
        const uint32_t sbase = smb + (uint32_t)((kb % 3) * STG_WORDS) * 4;

        #pragma unroll
        for (int kc = 0; kc < 2; kc++) {
            const int akw = kc * 8 + a_k;
            const int bkw = kc * 8 + b_k;
            uint32_t Ah[4][4], Al[4][4];
            #pragma unroll
            for (int tm = 0; tm < 4; tm++) {
                const uint32_t ad = sbase + (uint32_t)(aoff[tm] + (akw ^ aswz[tm])) * 4;
                LDSM4(Ah[tm], ad);
                LDSM4(Al[tm], ad + 2048 * 4);
            }
            uint32_t Bh[2][4], Bl[2][4];
            #pragma unroll
            for (int tp = 0; tp < 2; tp++) {
                const uint32_t bd = sbase + (uint32_t)(4096 + boff[tp] + (bkw ^ bswz[tp])) * 4;
                LDSM4(Bh[tp], bd);
                LDSM4(Bl[tp], bd + 2048 * 4);
            }
            #pragma unroll
            for (int tm = 0; tm < 4; tm++)
                #pragma unroll
                for (int tn = 0; tn < 4; tn++) {
                    uint32_t* bh = &Bh[tn >> 1][(tn & 1) * 2];
                    uint32_t* bl = &Bl[tn >> 1][(tn & 1) * 2];
                    MMA16(acc[tm][tn], Ah[tm], bh);
                    MMA16(acc[tm][tn], Ah[tm], bl);
                    MMA16(acc[tm][tn], Al[tm], bh);
                }
        }
        if (kb + 2 < NKB) issue(kb + 2, (kb + 2) % 3);
        CPCOMMIT();
    }

    // ---- epilogue ----
    const int Nw = N >> 1;
    #pragma unroll
    for (int tm = 0; tm < 4; tm++) {
        const int row0 = m0 + warp_m * 64 + tm * 16 + g;
        #pragma unroll
        for (int tn = 0; tn < 4; tn++) {
            const int col = n0 + warp_n * 32 + tn * 8 + t4 * 2;
            const float b0 = bias[col], b1 = bias[col + 1];
            const float v00 = acc[tm][tn][0] + b0, v01 = acc[tm][tn][1] + b1;
            const float v10 = acc[tm][tn][2] + b0, v11 = acc[tm][tn][3] + b1;
            if (C) {
                *(float2*)(C + (size_t)row0 * N + col)       = make_float2(v00, v01);
                *(float2*)(C + (size_t)(row0 + 8) * N + col) = make_float2(v10, v11);
            }
            if (Ch) {
                const int w = (col >> 1);
                float h00 = bf_hi(v00), h01 = bf_hi(v01);
                float h10 = bf_hi(v10), h11 = bf_hi(v11);
                Ch[(size_t)row0 * Nw + w]       = pack_bf(h00, h01);
                Cl[(size_t)row0 * Nw + w]       = pack_bf(v00 - h00, v01 - h01);
                Ch[(size_t)(row0 + 8) * Nw + w] = pack_bf(h10, h11);
                Cl[(size_t)(row0 + 8) * Nw + w] = pack_bf(v10 - h10, v11 - h11);
            }
        }
    }
}

// ---------------- frontend: conv + bn + pool + comp + projection ----------------
__global__ __launch_bounds__(256) void frontend_kernel(
    const float* __restrict__ x,
    const float* __restrict__ conv_w, const float* __restrict__ conv_b,
    const float* __restrict__ bn1_g, const float* __restrict__ bn1_b,
    const float* __restrict__ bn1_rm, const float* __restrict__ bn1_rv,
    const float* __restrict__ comp_w, const float* __restrict__ comp_b,
    const float* __restrict__ proj_w, const float* __restrict__ proj_b,
    float* __restrict__ combined)
{
    __shared__ float xs[TT][17];
    __shared__ float cw[24 * 9 * 3];
    __shared__ float cbias[24], cscale[24], cshift[24];
    __shared__ float cpw[20 * 8], cpb[20];
    __shared__ float feat[TS][44];

    const int b = blockIdx.x;
    const int tid = threadIdx.x;
    const float* xb = x + (size_t)b * TT * 17;

    for (int i = tid; i < TT * 17; i += 256) xs[i / 17][i % 17] = xb[i];
    for (int i = tid; i < 648; i += 256) cw[i] = conv_w[i];
    if (tid < 24) {
        cbias[tid] = conv_b[tid];
        float s = bn1_g[tid] * rsqrtf(bn1_rv[tid] + EPS);
        cscale[tid] = s;
        cshift[tid] = bn1_b[tid] - bn1_rm[tid] * s;
    }
    for (int i = tid; i < 160; i += 256) cpw[i] = comp_w[i];
    if (tid < 20) cpb[tid] = comp_b[tid];
    __syncthreads();

    for (int idx = tid; idx < 24 * TS; idx += 256) {
        int o = idx % 24, th = idx / 24;
        float mx = -1e30f;
        #pragma unroll
        for (int s = 0; s < 2; s++) {
            int t = th * 2 + s;
            float acc = cbias[o];
            #pragma unroll
            for (int k = 0; k < 3; k++) {
                int tt = t + k - 1;
                if (tt >= 0 && tt < TT) {
                    #pragma unroll
                    for (int i2 = 0; i2 < 9; i2++)
                        acc += xs[tt][i2] * cw[o * 27 + i2 * 3 + k];
                }
            }
            acc = fmaxf(acc, 0.0f);
            acc = acc * cscale[o] + cshift[o];
            mx = fmaxf(mx, acc);
        }
        feat[th][o] = mx;
    }
    for (int idx = tid; idx < TS * 20; idx += 256) {
        int j = idx % 20, t = idx / 20;
        float acc = cpb[j];
        #pragma unroll
        for (int i2 = 0; i2 < 8; i2++) acc += xs[t][9 + i2] * cpw[j * 8 + i2];
        feat[t][24 + j] = fmaxf(acc, 0.0f);
    }
    __syncthreads();

    for (int hh = tid; hh < H; hh += 256) {
        float w[44];
        #pragma unroll
        for (int f = 0; f < 44; f++) w[f] = proj_w[hh * 44 + f];
        float pb = proj_b[hh];
        for (int t = 0; t < TS; t++) {
            float acc = pb;
            #pragma unroll
            for (int f = 0; f < 44; f++) acc += feat[t][f] * w[f];
            combined[((size_t)b * TS + t) * H + hh] = acc;
        }
    }
}

// ---------------- gate math + two layernorms: warp per batch row ----------------
__device__ __forceinline__ float sigm(float v) { return 1.0f / (1.0f + expf(-v)); }

__device__ __forceinline__ void warp_ln(const float* v, float& mu, float& rs) {
    float s = 0.0f, q = 0.0f;
    #pragma unroll
    for (int i = 0; i < 16; i++) { s += v[i]; q += v[i] * v[i]; }
    #pragma unroll
    for (int o = 16; o > 0; o >>= 1) {
        s += __shfl_xor_sync(0xffffffffu, s, o);
        q += __shfl_xor_sync(0xffffffffu, q, o);
    }
    mu = s * (1.0f / 512.0f);
    rs = rsqrtf(q * (1.0f / 512.0f) - mu * mu + EPS);
}

__global__ __launch_bounds__(256) void gate_kernel(
    const float* __restrict__ G,
    uint32_t* __restrict__ hH, uint32_t* __restrict__ hL,
    float* __restrict__ c,
    const float* __restrict__ ret,
    const float* __restrict__ eg, const float* __restrict__ ebb,
    const float* __restrict__ lg, const float* __restrict__ lbb,
    float* __restrict__ seq_out)  // fp32, may be null (layer 0)
{
    const int wid = threadIdx.x >> 5, lid = threadIdx.x & 31;
    const size_t b = (size_t)blockIdx.x * 8 + wid;
    const float* g = G + b * NG;
    float* crow = c + b * H;

    float o_[16], cn_[16];
    #pragma unroll
    for (int j = 0; j < 4; j++) {
        const int col = lid * 4 + j * 128;
        float4 vf = *(const float4*)(g + 0 * H + col);
        float4 vi = *(const float4*)(g + 1 * H + col);
        float4 vo = *(const float4*)(g + 2 * H + col);
        float4 vc = *(const float4*)(g + 3 * H + col);
        float4 vm = *(const float4*)(g + 4 * H + col);
        float4 cp = *(const float4*)(crow + col);
        float4 rr = *(const float4*)(ret + col);
        float bf[4], bi[4], bo[4], bc[4], bm[4], bp[4], br[4];
        *(float4*)bf = vf; *(float4*)bi = vi; *(float4*)bo = vo;
        *(float4*)bc = vc; *(float4*)bm = vm; *(float4*)bp = cp; *(float4*)br = rr;
        #pragma unroll
        for (int e = 0; e < 4; e++) {
            float f = sigm(bf[e]), iv = sigm(bi[e]), m = sigm(bm[e]);
            float ccv = tanhf(bc[e]);
            float cpv = bp[e], rv = br[e];
            float cn = f * cpv + iv * ccv;
            cn = cn * rv + (1.0f - rv) * cpv;
            cn = m * cn + (1.0f - m) * cpv;
            cn_[j * 4 + e] = cn;
            o_[j * 4 + e] = sigm(bo[e]);
        }
    }

    float mu1, rs1;
    warp_ln(o_, mu1, rs1);
    float u_[16];
    #pragma unroll
    for (int j = 0; j < 4; j++) {
        const int col = lid * 4 + j * 128;
        float4 ge = *(const float4*)(eg + col);
        float4 be = *(const float4*)(ebb + col);
        float g_[4], b_[4];
        *(float4*)g_ = ge; *(float4*)b_ = be;
        #pragma unroll
        for (int e = 0; e < 4; e++) {
            float on = (o_[j * 4 + e] - mu1) * rs1 * g_[e] + b_[e];
            u_[j * 4 + e] = sigm(on) * tanhf(cn_[j * 4 + e]);
        }
    }

    float mu2, rs2;
    warp_ln(u_, mu2, rs2);
    #pragma unroll
    for (int j = 0; j < 4; j++) {
        const int col = lid * 4 + j * 128;
        float4 gl = *(const float4*)(lg + col);
        float4 bl = *(const float4*)(lbb + col);
        float g_[4], b_[4], hn[4], cv[4];
        *(float4*)g_ = gl; *(float4*)b_ = bl;
        #pragma unroll
        for (int e = 0; e < 4; e++) {
            hn[e] = (u_[j * 4 + e] - mu2) * rs2 * g_[e] + b_[e];
            cv[e] = cn_[j * 4 + e];
        }
        *(float4*)(crow + col) = *(float4*)cv;
        // packed hi/lo h
        float h0 = bf_hi(hn[0]), h1 = bf_hi(hn[1]), h2 = bf_hi(hn[2]), h3 = bf_hi(hn[3]);
        uint2 wh, wl;
        wh.x = pack_bf(h0, h1);              wh.y = pack_bf(h2, h3);
        wl.x = pack_bf(hn[0] - h0, hn[1] - h1);
        wl.y = pack_bf(hn[2] - h2, hn[3] - h3);
        *(uint2*)(hH + b * HW + (col >> 1)) = wh;
        *(uint2*)(hL + b * HW + (col >> 1)) = wl;
        if (seq_out) *(float4*)(seq_out + b * TS * H + col) = *(float4*)hn;
    }
}

// ---------------- last-query attention: block per (b, head), packed output -------
__global__ __launch_bounds__(128) void attn_kernel(
    const float* __restrict__ q,
    const float* __restrict__ kv,
    uint32_t* __restrict__ attH, uint32_t* __restrict__ attL)
{
    __shared__ float qs[DH];
    __shared__ float sc[TS];
    const int b = blockIdx.x, hd = blockIdx.y;
    const int tid = threadIdx.x;

    qs[tid] = q[(size_t)b * H + hd * DH + tid];
    __syncthreads();

    if (tid < TS) {
        const float* kr = kv + ((size_t)b * TS + tid) * K2H + hd * DH;
        float s = 0.0f;
        #pragma unroll 16
        for (int d = 0; d < DH; d++) s += qs[d] * kr[d];
        sc[tid] = s * 0.08838834764831845f;
    }
    __syncthreads();

    float mx = -1e30f;
    #pragma unroll
    for (int t = 0; t < TS; t++) mx = fmaxf(mx, sc[t]);
    float p[TS], ssum = 0.0f;
    #pragma unroll
    for (int t = 0; t < TS; t++) { p[t] = expf(sc[t] - mx); ssum += p[t]; }
    float inv = 1.0f / ssum;

    float acc = 0.0f;
    #pragma unroll
    for (int t = 0; t < TS; t++)
        acc += p[t] * kv[((size_t)b * TS + t) * K2H + H + hd * DH + tid];
    float v = acc * inv;

    float pv = __shfl_down_sync(0xffffffffu, v, 1);
    if (!(tid & 1)) {
        float h0 = bf_hi(v), h1 = bf_hi(pv);
        const size_t w = (size_t)b * HW + hd * (DH / 2) + (tid >> 1);
        attH[w] = pack_bf(h0, h1);
        attL[w] = pack_bf(v - h0, pv - h1);
    }
}

// ---------------- bn2 + output head ----------------
__global__ __launch_bounds__(256) void head_kernel(
    const float* __restrict__ latent,
    const float* __restrict__ bn2_g, const float* __restrict__ bn2_b,
    const float* __restrict__ bn2_rm, const float* __restrict__ bn2_rv,
    const float* __restrict__ out_w, const float* __restrict__ out_b,
    float* __restrict__ out)
{
    __shared__ float lw[OUT * LAT];
    __shared__ float ls[16][LAT];
    __shared__ float scale[LAT], shift[LAT];
    const int b0 = blockIdx.x * 16;
    const int tid = threadIdx.x;

    if (tid < LAT) {
        float s = bn2_g[tid] * rsqrtf(bn2_rv[tid] + EPS);
        scale[tid] = s;
        shift[tid] = bn2_b[tid] - bn2_rm[tid] * s;
    }
    for (int i = tid; i < OUT * LAT; i += 256) lw[i] = out_w[i];
    __syncthreads();

    for (int i = tid; i < 16 * LAT; i += 256) {
        int r = i / LAT, j = i % LAT;
        ls[r][j] = latent[(size_t)(b0 + r) * LAT + j] * scale[j] + shift[j];
    }
    __syncthreads();

    for (int idx = tid; idx < 16 * OUT; idx += 256) {
        int r = idx / OUT, o = idx % OUT;
        float acc = out_b[o];
        #pragma unroll 16
        for (int j = 0; j < LAT; j++) acc += ls[r][j] * lw[o * LAT + j];
        out[(size_t)(b0 + r) * OUT + o] = acc;
    }
}

// ---------------- host launch ----------------
extern "C" void kernel_launch(void* const* d_in, const int* in_sizes, int n_in,
                              void* d_out, int out_size)
{
    const float* x        = (const float*)d_in[0];
    const float* conv1_w  = (const float*)d_in[1];
    const float* conv1_b  = (const float*)d_in[2];
    const float* bn1_g    = (const float*)d_in[3];
    const float* bn1_b    = (const float*)d_in[4];
    const float* bn1_rm   = (const float*)d_in[5];
    const float* bn1_rv   = (const float*)d_in[6];
    const float* comp_w   = (const float*)d_in[7];
    const float* comp_b   = (const float*)d_in[8];
    const float* proj_w   = (const float*)d_in[9];
    const float* proj_b   = (const float*)d_in[10];
    const float* gates_w  = (const float*)d_in[11];
    const float* gates_b  = (const float*)d_in[12];
    const float* retention= (const float*)d_in[13];
    const float* expln_g  = (const float*)d_in[14];
    const float* expln_b  = (const float*)d_in[15];
    const float* ln_g     = (const float*)d_in[16];
    const float* ln_b     = (const float*)d_in[17];
    const float* attn_in_w= (const float*)d_in[18];
    const float* attn_in_b= (const float*)d_in[19];
    const float* attn_out_w=(const float*)d_in[20];
    const float* attn_out_b=(const float*)d_in[21];
    const float* bneck_w  = (const float*)d_in[22];
    const float* bneck_b  = (const float*)d_in[23];
    const float* bn2_g    = (const float*)d_in[24];
    const float* bn2_b    = (const float*)d_in[25];
    const float* bn2_rm   = (const float*)d_in[26];
    const float* bn2_rv   = (const float*)d_in[27];
    const float* out_w    = (const float*)d_in[28];
    const float* out_b    = (const float*)d_in[29];
    float* out = (float*)d_out;

    cudaFuncSetAttribute(gemm_bf16, cudaFuncAttributeMaxDynamicSharedMemorySize,
                         GEMM_SMEM_BYTES);

    float *combined, *seq, *G, *c, *kv, *q, *lat;
    uint32_t *combH, *combL, *seqH, *seqL, *hH, *hL, *attH, *attL, *finH, *finL, *Wh, *Wl;
    cudaGetSymbolAddress((void**)&combined, d_combined);
    cudaGetSymbolAddress((void**)&seq,      d_seq);
    cudaGetSymbolAddress((void**)&G,        d_G);
    cudaGetSymbolAddress((void**)&c,        d_c);
    cudaGetSymbolAddress((void**)&kv,       d_kv);
    cudaGetSymbolAddress((void**)&q,        d_q);
    cudaGetSymbolAddress((void**)&lat,      d_lat);
    cudaGetSymbolAddress((void**)&combH,    d_combH);
    cudaGetSymbolAddress((void**)&combL,    d_combL);
    cudaGetSymbolAddress((void**)&seqH,     d_seqH);
    cudaGetSymbolAddress((void**)&seqL,     d_seqL);
    cudaGetSymbolAddress((void**)&hH,       d_hH);
    cudaGetSymbolAddress((void**)&hL,       d_hL);
    cudaGetSymbolAddress((void**)&attH,     d_attH);
    cudaGetSymbolAddress((void**)&attL,     d_attL);
    cudaGetSymbolAddress((void**)&finH,     d_finH);
    cudaGetSymbolAddress((void**)&finL,     d_finL);
    cudaGetSymbolAddress((void**)&Wh,       d_Wh);
    cudaGetSymbolAddress((void**)&Wl,       d_Wl);

    uint32_t* h0H = hH;              uint32_t* h0L = hL;
    uint32_t* h1H = hH + (size_t)B * HW;
    uint32_t* h1L = hL + (size_t)B * HW;
    float* c0 = c;
    float* c1 = c + (size_t)B * H;

    // zero recurrent state (c fp32 + packed h; bf16 zero == 0 bits)
    zero_kernel<<<2048, 512>>>(c, 2 * B * H);
    zero_kernel<<<2048, 512>>>((float*)hH, 2 * B * HW);
    zero_kernel<<<2048, 512>>>((float*)hL, 2 * B * HW);

    // pre-split all GEMM weights into packed bf16 hi/lo
    split_kernel<<<2048, 256>>>(gates_w,    Wh + OFF_W0,   Wl + OFF_W0,   NG * K2H);
    split_kernel<<<1024, 256>>>(attn_in_w,  Wh + OFF_AIN,  Wl + OFF_AIN,  3 * H * H / 2);
    split_kernel<<<512, 256>>>(attn_out_w,  Wh + OFF_AOUT, Wl + OFF_AOUT, H * H / 2);
    split_kernel<<<128, 256>>>(bneck_w,     Wh + OFF_BNK,  Wl + OFF_BNK,  LAT * H / 2);

    frontend_kernel<<<B, 256>>>(x, conv1_w, conv1_b, bn1_g, bn1_b, bn1_rm, bn1_rv,
                                comp_w, comp_b, proj_w, proj_b, combined);
    split_kernel<<<8192, 256>>>(combined, combH, combL, B * TS * H / 2);

    const float* gb0 = gates_b;
    const float* gb1 = gates_b + NG;

    dim3 gemm_grid(B / 128, NG / 128);  // 32 x 20
    for (int t = 0; t < TS; t++) {
        gemm_bf16<<<gemm_grid, 256, GEMM_SMEM_BYTES>>>(
            combH + (size_t)t * HW, combL + (size_t)t * HW, TS * HW, HW,
            h0H, h0L, HW,
            Wh + OFF_W0, Wl + OFF_W0, 2 * HW, gb0, G, nullptr, nullptr, NG);
        gate_kernel<<<B / 8, 256>>>(G, h0H, h0L, c0, retention, expln_g, expln_b,
                                    ln_g, ln_b, nullptr);
        gemm_bf16<<<gemm_grid, 256, GEMM_SMEM_BYTES>>>(
            h0H, h0L, HW, HW, h1H, h1L, HW,
            Wh + OFF_W1, Wl + OFF_W1, 2 * HW, gb1, G, nullptr, nullptr, NG);
        gate_kernel<<<B / 8, 256>>>(G, h1H, h1L, c1, retention + H, expln_g + H,
                                    expln_b + H, ln_g + H, ln_b + H,
                                    seq + (size_t)t * H);
    }

    split_kernel<<<8192, 256>>>(seq, seqH, seqL, B * TS * H / 2);

    // k,v for all timesteps: (B*30, 512) @ (512, 1024); attn_in rows 512..1535
    gemm_bf16<<<dim3(B * TS / 128, K2H / 128), 256, GEMM_SMEM_BYTES>>>(
        seqH, seqL, HW, HW, seqH, seqL, HW,
        Wh + OFF_AIN + (size_t)H * HW / 2 * 2, Wl + OFF_AIN + (size_t)H * H / 2, HW,
        attn_in_b + H, kv, nullptr, nullptr, K2H);
    // q at last timestep: (B, 512) @ (512, 512); attn_in rows 0..511
    gemm_bf16<<<dim3(B / 128, H / 128), 256, GEMM_SMEM_BYTES>>>(
        seqH + (size_t)(TS - 1) * HW, seqL + (size_t)(TS - 1) * HW, TS * HW, HW,
        seqH, seqL, HW,
        Wh + OFF_AIN, Wl + OFF_AIN, HW, attn_in_b, q, nullptr, nullptr, H);
    attn_kernel<<<dim3(B, NH), 128>>>(q, kv, attH, attL);
    gemm_bf16<<<dim3(B / 128, H / 128), 256, GEMM_SMEM_BYTES>>>(
        attH, attL, HW, HW, attH, attL, HW,
        Wh + OFF_AOUT, Wl + OFF_AOUT, HW, attn_out_b, nullptr, finH, finL, H);
    gemm_bf16<<<dim3(B / 128, LAT / 128), 256, GEMM_SMEM_BYTES>>>(
        finH, finL, HW, HW, finH, finL, HW,
        Wh + OFF_BNK, Wl + OFF_BNK, HW, bneck_b, lat, nullptr, nullptr, LAT);
    head_kernel<<<B / 16, 256>>>(lat, bn2_g, bn2_b, bn2_rm, bn2_rv, out_w, out_b, out);
}

// round 8
// speedup vs baseline: 5.4566x; 1.2934x over previous
#include <cuda_runtime.h>
#include <cuda_bf16.h>
#include <cstdint>
#include <cstddef>

#define EPS 1e-5f

// ---------------- problem constants ----------------
#define B   4096
#define TT  60
#define TS  30
#define H   512
#define LAT 128
#define OUT 14
#define NH  4
#define DH  128
#define NG  2560
#define K2H 1024

// ---------------- device scratch ----------------
__device__ float d_combined[(size_t)B * TS * H];
__device__ float d_seq     [(size_t)B * TS * H];
__device__ float d_G0      [(size_t)B * NG];
__device__ float d_G1      [(size_t)B * NG];
__device__ float d_c       [(size_t)2 * B * H];
__device__ float d_kv      [(size_t)B * TS * K2H];
__device__ float d_q       [(size_t)B * H];
__device__ float d_lat     [(size_t)B * LAT];

#define HW  256
__device__ uint32_t d_combH[(size_t)B * TS * HW];
__device__ uint32_t d_combL[(size_t)B * TS * HW];
__device__ uint32_t d_seqH [(size_t)B * TS * HW];
__device__ uint32_t d_seqL [(size_t)B * TS * HW];
__device__ uint32_t d_hH   [(size_t)2 * B * HW];
__device__ uint32_t d_hL   [(size_t)2 * B * HW];
__device__ uint32_t d_attH [(size_t)B * HW];
__device__ uint32_t d_attL [(size_t)B * HW];
__device__ uint32_t d_finH [(size_t)B * HW];
__device__ uint32_t d_finL [(size_t)B * HW];

#define OFF_W0   0
#define OFF_W1   1310720
#define OFF_AIN  2621440
#define OFF_AOUT 3014656
#define OFF_BNK  3145728
#define W_WORDS  3178496
__device__ uint32_t d_Wh[(size_t)W_WORDS];
__device__ uint32_t d_Wl[(size_t)W_WORDS];

// ---------------- helpers ----------------
__device__ __forceinline__ uint32_t pack_bf(float a, float b) {
    __nv_bfloat162 t = __floats2bfloat162_rn(a, b);
    return *reinterpret_cast<uint32_t*>(&t);
}
__device__ __forceinline__ float bf_hi(float x) {
    return __bfloat162float(__float2bfloat16_rn(x));
}
__device__ __forceinline__ uint32_t smem_u32(const void* p) {
    uint32_t a;
    asm("{ .reg .u64 t; cvta.to.shared.u64 t, %1; cvt.u32.u64 %0, t; }" : "=r"(a) : "l"(p));
    return a;
}

#define MMA16(d, a, b) \
    asm volatile( \
        "mma.sync.aligned.m16n8k16.row.col.f32.bf16.bf16.f32 " \
        "{%0,%1,%2,%3}, {%4,%5,%6,%7}, {%8,%9}, {%0,%1,%2,%3};" \
        : "+f"((d)[0]), "+f"((d)[1]), "+f"((d)[2]), "+f"((d)[3]) \
        : "r"((a)[0]), "r"((a)[1]), "r"((a)[2]), "r"((a)[3]), \
          "r"((b)[0]), "r"((b)[1]))

#define LDSM4(v, addr) \
    asm volatile("ldmatrix.sync.aligned.m8n8.x4.shared.b16 {%0,%1,%2,%3}, [%4];" \
        : "=r"((v)[0]), "=r"((v)[1]), "=r"((v)[2]), "=r"((v)[3]) : "r"(addr))

#define CP16(dst, src) \
    asm volatile("cp.async.cg.shared.global [%0], [%1], 16;" :: "r"(dst), "l"(src))
#define CPCOMMIT() asm volatile("cp.async.commit_group;" ::: "memory")
#define CPWAIT1()  asm volatile("cp.async.wait_group 1;" ::: "memory")

#define STG_WORDS 8192
#define GEMM_SMEM_BYTES (3 * STG_WORDS * 4)

// ---------------- fused zero init (state) ----------------
__global__ void zero3_kernel(float* __restrict__ p0, int n0,
                             float* __restrict__ p1, int n1,
                             float* __restrict__ p2, int n2) {
    int i = blockIdx.x * blockDim.x + threadIdx.x;
    int stride = gridDim.x * blockDim.x;
    for (int j = i; j < n0; j += stride) p0[j] = 0.0f;
    for (int j = i; j < n1; j += stride) p1[j] = 0.0f;
    for (int j = i; j < n2; j += stride) p2[j] = 0.0f;
}

// ---------------- bf16 hi/lo packed split ----------------
__device__ __forceinline__ void split_range(const float* __restrict__ src,
                                            uint32_t* __restrict__ hi,
                                            uint32_t* __restrict__ lo,
                                            int nwords, int i, int stride) {
    for (; i < nwords; i += stride) {
        float2 v = *(const float2*)(src + 2 * (size_t)i);
        float h0 = bf_hi(v.x), h1 = bf_hi(v.y);
        hi[i] = pack_bf(h0, h1);
        lo[i] = pack_bf(v.x - h0, v.y - h1);
    }
}
__global__ void split_kernel(const float* __restrict__ src,
                             uint32_t* __restrict__ hi, uint32_t* __restrict__ lo,
                             int nwords) {
    split_range(src, hi, lo, nwords,
                blockIdx.x * blockDim.x + threadIdx.x, gridDim.x * blockDim.x);
}
__global__ void split3_kernel(
    const float* __restrict__ s0, uint32_t* __restrict__ h0, uint32_t* __restrict__ l0, int n0,
    const float* __restrict__ s1, uint32_t* __restrict__ h1, uint32_t* __restrict__ l1, int n1,
    const float* __restrict__ s2, uint32_t* __restrict__ h2, uint32_t* __restrict__ l2, int n2) {
    int i = blockIdx.x * blockDim.x + threadIdx.x;
    int stride = gridDim.x * blockDim.x;
    split_range(s0, h0, l0, n0, i, stride);
    split_range(s1, h1, l1, n1, i, stride);
    split_range(s2, h2, l2, n2, i, stride);
}

// ================= bf16x3 GEMM core (cp.async + ldmatrix) =================
__device__ __forceinline__ void gemm_core(
    const uint32_t* __restrict__ A1h, const uint32_t* __restrict__ A1l,
    int lda1, int K1w,
    const uint32_t* __restrict__ A2h, const uint32_t* __restrict__ A2l,
    int lda2,
    const uint32_t* __restrict__ Wh, const uint32_t* __restrict__ Wl, int Kw,
    const float* __restrict__ bias,
    float* __restrict__ C, uint32_t* __restrict__ Ch, uint32_t* __restrict__ Cl,
    int N, int m0, int n0, uint32_t smb)
{
    const int tid = threadIdx.x;
    const int wid = tid >> 5, lane = tid & 31;
    const int g = lane >> 2, t4 = lane & 3;
    const int warp_m = wid >> 2, warp_n = wid & 3;

    const int r = tid >> 1, half = tid & 1;
    const int wb = half * 8;
    const int swz = ((r >> 1) & 3) << 2;
    const int so0 = r * 16 + ((wb) ^ swz);
    const int so1 = r * 16 + ((wb + 4) ^ swz);

    const int a_r = lane & 15;
    const int a_k = (lane >> 4) << 2;
    int aoff[4], aswz[4];
    #pragma unroll
    for (int tm = 0; tm < 4; tm++) {
        const int row = warp_m * 64 + tm * 16 + a_r;
        aoff[tm] = row * 16;
        aswz[tm] = ((row >> 1) & 3) << 2;
    }
    const int b_r = (lane & 7) + ((lane >> 4) << 3);
    const int b_k = ((lane >> 3) & 1) << 2;
    int boff[2], bswz[2];
    #pragma unroll
    for (int tp = 0; tp < 2; tp++) {
        const int row = warp_n * 32 + tp * 16 + b_r;
        boff[tp] = row * 16;
        bswz[tp] = ((row >> 1) & 3) << 2;
    }

    float acc[4][4][4];
    #pragma unroll
    for (int i = 0; i < 4; i++)
        #pragma unroll
        for (int j = 0; j < 4; j++)
            #pragma unroll
            for (int e = 0; e < 4; e++) acc[i][j][e] = 0.0f;

    const int NKB = Kw / 16;

    auto issue = [&](int kb, int stage) {
        const int kbw = kb * 16 + wb;
        const uint32_t *ah, *al;
        if (kbw < K1w) {
            ah = A1h + (size_t)(m0 + r) * lda1 + kbw;
            al = A1l + (size_t)(m0 + r) * lda1 + kbw;
        } else {
            ah = A2h + (size_t)(m0 + r) * lda2 + (kbw - K1w);
            al = A2l + (size_t)(m0 + r) * lda2 + (kbw - K1w);
        }
        const uint32_t* bh = Wh + (size_t)(n0 + r) * Kw + kbw;
        const uint32_t* bl = Wl + (size_t)(n0 + r) * Kw + kbw;
        const uint32_t sb = smb + (uint32_t)(stage * STG_WORDS) * 4;
        CP16(sb + so0 * 4, ah);                 CP16(sb + so1 * 4, ah + 4);
        CP16(sb + (2048 + so0) * 4, al);        CP16(sb + (2048 + so1) * 4, al + 4);
        CP16(sb + (4096 + so0) * 4, bh);        CP16(sb + (4096 + so1) * 4, bh + 4);
        CP16(sb + (6144 + so0) * 4, bl);        CP16(sb + (6144 + so1) * 4, bl + 4);
    };

    issue(0, 0); CPCOMMIT();
    issue(1, 1); CPCOMMIT();

    for (int kb = 0; kb < NKB; kb++) {
        CPWAIT1();
        __syncthreads();
        const uint32_t sbase = smb + (uint32_t)((kb % 3) * STG_WORDS) * 4;

        #pragma unroll
        for (int kc = 0; kc < 2; kc++) {
            const int akw = kc * 8 + a_k;
            const int bkw = kc * 8 + b_k;
            uint32_t Ah[4][4], Al[4][4];
            #pragma unroll
            for (int tm = 0; tm < 4; tm++) {
                const uint32_t ad = sbase + (uint32_t)(aoff[tm] + (akw ^ aswz[tm])) * 4;
                LDSM4(Ah[tm], ad);
                LDSM4(Al[tm], ad + 2048 * 4);
            }
            uint32_t Bh[2][4], Bl[2][4];
            #pragma unroll
            for (int tp = 0; tp < 2; tp++) {
                const uint32_t bd = sbase + (uint32_t)(4096 + boff[tp] + (bkw ^ bswz[tp])) * 4;
                LDSM4(Bh[tp], bd);
                LDSM4(Bl[tp], bd + 2048 * 4);
            }
            #pragma unroll
            for (int tm = 0; tm < 4; tm++)
                #pragma unroll
                for (int tn = 0; tn < 4; tn++) {
                    uint32_t* bh = &Bh[tn >> 1][(tn & 1) * 2];
                    uint32_t* bl = &Bl[tn >> 1][(tn & 1) * 2];
                    MMA16(acc[tm][tn], Ah[tm], bh);
                    MMA16(acc[tm][tn], Ah[tm], bl);
                    MMA16(acc[tm][tn], Al[tm], bh);
                }
        }
        if (kb + 2 < NKB) issue(kb + 2, (kb + 2) % 3);
        CPCOMMIT();
    }

    const int Nw = N >> 1;
    #pragma unroll
    for (int tm = 0; tm < 4; tm++) {
        const int row0 = m0 + warp_m * 64 + tm * 16 + g;
        #pragma unroll
        for (int tn = 0; tn < 4; tn++) {
            const int col = n0 + warp_n * 32 + tn * 8 + t4 * 2;
            const float b0 = bias[col], b1 = bias[col + 1];
            const float v00 = acc[tm][tn][0] + b0, v01 = acc[tm][tn][1] + b1;
            const float v10 = acc[tm][tn][2] + b0, v11 = acc[tm][tn][3] + b1;
            if (C) {
                *(float2*)(C + (size_t)row0 * N + col)       = make_float2(v00, v01);
                *(float2*)(C + (size_t)(row0 + 8) * N + col) = make_float2(v10, v11);
            }
            if (Ch) {
                const int w = (col >> 1);
                float h00 = bf_hi(v00), h01 = bf_hi(v01);
                float h10 = bf_hi(v10), h11 = bf_hi(v11);
                Ch[(size_t)row0 * Nw + w]       = pack_bf(h00, h01);
                Cl[(size_t)row0 * Nw + w]       = pack_bf(v00 - h00, v01 - h01);
                Ch[(size_t)(row0 + 8) * Nw + w] = pack_bf(h10, h11);
                Cl[(size_t)(row0 + 8) * Nw + w] = pack_bf(v10 - h10, v11 - h11);
            }
        }
    }
}

__global__ __launch_bounds__(256) void gemm_bf16(
    const uint32_t* __restrict__ A1h, const uint32_t* __restrict__ A1l,
    int lda1, int K1w,
    const uint32_t* __restrict__ A2h, const uint32_t* __restrict__ A2l,
    int lda2,
    const uint32_t* __restrict__ Wh, const uint32_t* __restrict__ Wl, int Kw,
    const float* __restrict__ bias,
    float* __restrict__ C, uint32_t* __restrict__ Ch, uint32_t* __restrict__ Cl,
    int N)
{
    extern __shared__ uint32_t sm[];
    gemm_core(A1h, A1l, lda1, K1w, A2h, A2l, lda2, Wh, Wl, Kw, bias,
              C, Ch, Cl, N, blockIdx.x * 128, blockIdx.y * 128, smem_u32(sm));
}

// Dual GEMM: z=0 -> G1(t) = [h0|h1] @ W1 ; z=1 -> G0(t+1) = [comb(t+1)|h0] @ W0
__global__ __launch_bounds__(256) void gemm_dual(
    const uint32_t* __restrict__ h0H, const uint32_t* __restrict__ h0L,
    const uint32_t* __restrict__ h1H, const uint32_t* __restrict__ h1L,
    const uint32_t* __restrict__ combH, const uint32_t* __restrict__ combL,
    const uint32_t* __restrict__ Wall_h, const uint32_t* __restrict__ Wall_l,
    const float* __restrict__ gb0, const float* __restrict__ gb1,
    float* __restrict__ G0, float* __restrict__ G1,
    int has2)
{
    extern __shared__ uint32_t sm[];
    const uint32_t* A1h; const uint32_t* A1l; int lda1;
    const uint32_t* A2h; const uint32_t* A2l;
    const uint32_t* Wh;  const uint32_t* Wl;
    const float* bias;   float* C;
    if (blockIdx.z == 0) {
        A1h = h0H; A1l = h0L; lda1 = HW;
        A2h = h1H; A2l = h1L;
        Wh = Wall_h + OFF_W1; Wl = Wall_l + OFF_W1;
        bias = gb1; C = G1;
    } else {
        if (!has2) return;
        A1h = combH; A1l = combL; lda1 = TS * HW;
        A2h = h0H;   A2l = h0L;
        Wh = Wall_h + OFF_W0; Wl = Wall_l + OFF_W0;
        bias = gb0; C = G0;
    }
    gemm_core(A1h, A1l, lda1, HW, A2h, A2l, HW, Wh, Wl, 2 * HW, bias,
              C, nullptr, nullptr, NG, blockIdx.x * 128, blockIdx.y * 128, smem_u32(sm));
}

// ---------------- frontend ----------------
__global__ __launch_bounds__(256) void frontend_kernel(
    const float* __restrict__ x,
    const float* __restrict__ conv_w, const float* __restrict__ conv_b,
    const float* __restrict__ bn1_g, const float* __restrict__ bn1_b,
    const float* __restrict__ bn1_rm, const float* __restrict__ bn1_rv,
    const float* __restrict__ comp_w, const float* __restrict__ comp_b,
    const float* __restrict__ proj_w, const float* __restrict__ proj_b,
    float* __restrict__ combined)
{
    __shared__ float xs[TT][17];
    __shared__ float cw[24 * 9 * 3];
    __shared__ float cbias[24], cscale[24], cshift[24];
    __shared__ float cpw[20 * 8], cpb[20];
    __shared__ float feat[TS][44];

    const int b = blockIdx.x;
    const int tid = threadIdx.x;
    const float* xb = x + (size_t)b * TT * 17;

    for (int i = tid; i < TT * 17; i += 256) xs[i / 17][i % 17] = xb[i];
    for (int i = tid; i < 648; i += 256) cw[i] = conv_w[i];
    if (tid < 24) {
        cbias[tid] = conv_b[tid];
        float s = bn1_g[tid] * rsqrtf(bn1_rv[tid] + EPS);
        cscale[tid] = s;
        cshift[tid] = bn1_b[tid] - bn1_rm[tid] * s;
    }
    for (int i = tid; i < 160; i += 256) cpw[i] = comp_w[i];
    if (tid < 20) cpb[tid] = comp_b[tid];
    __syncthreads();

    for (int idx = tid; idx < 24 * TS; idx += 256) {
        int o = idx % 24, th = idx / 24;
        float mx = -1e30f;
        #pragma unroll
        for (int s = 0; s < 2; s++) {
            int t = th * 2 + s;
            float acc = cbias[o];
            #pragma unroll
            for (int k = 0; k < 3; k++) {
                int tt = t + k - 1;
                if (tt >= 0 && tt < TT) {
                    #pragma unroll
                    for (int i2 = 0; i2 < 9; i2++)
                        acc += xs[tt][i2] * cw[o * 27 + i2 * 3 + k];
                }
            }
            acc = fmaxf(acc, 0.0f);
            acc = acc * cscale[o] + cshift[o];
            mx = fmaxf(mx, acc);
        }
        feat[th][o] = mx;
    }
    for (int idx = tid; idx < TS * 20; idx += 256) {
        int j = idx % 20, t = idx / 20;
        float acc = cpb[j];
        #pragma unroll
        for (int i2 = 0; i2 < 8; i2++) acc += xs[t][9 + i2] * cpw[j * 8 + i2];
        feat[t][24 + j] = fmaxf(acc, 0.0f);
    }
    __syncthreads();

    for (int hh = tid; hh < H; hh += 256) {
        float w[44];
        #pragma unroll
        for (int f = 0; f < 44; f++) w[f] = proj_w[hh * 44 + f];
        float pb = proj_b[hh];
        for (int t = 0; t < TS; t++) {
            float acc = pb;
            #pragma unroll
            for (int f = 0; f < 44; f++) acc += feat[t][f] * w[f];
            combined[((size_t)b * TS + t) * H + hh] = acc;
        }
    }
}

// ---------------- gate core: warp per batch row ----------------
__device__ __forceinline__ float sigm(float v) { return 1.0f / (1.0f + expf(-v)); }

__device__ __forceinline__ void warp_ln(const float* v, float& mu, float& rs) {
    float s = 0.0f, q = 0.0f;
    #pragma unroll
    for (int i = 0; i < 16; i++) { s += v[i]; q += v[i] * v[i]; }
    #pragma unroll
    for (int o = 16; o > 0; o >>= 1) {
        s += __shfl_xor_sync(0xffffffffu, s, o);
        q += __shfl_xor_sync(0xffffffffu, q, o);
    }
    mu = s * (1.0f / 512.0f);
    rs = rsqrtf(q * (1.0f / 512.0f) - mu * mu + EPS);
}

__device__ __forceinline__ void gate_core(
    const float* __restrict__ G,
    uint32_t* __restrict__ hH, uint32_t* __restrict__ hL,
    float* __restrict__ c,
    const float* __restrict__ ret,
    const float* __restrict__ eg, const float* __restrict__ ebb,
    const float* __restrict__ lg, const float* __restrict__ lbb,
    float* __restrict__ seq_out)
{
    const int wid = threadIdx.x >> 5, lid = threadIdx.x & 31;
    const size_t b = (size_t)blockIdx.x * 8 + wid;
    const float* g = G + b * NG;
    float* crow = c + b * H;

    float o_[16], cn_[16];
    #pragma unroll
    for (int j = 0; j < 4; j++) {
        const int col = lid * 4 + j * 128;
        float4 vf = *(const float4*)(g + 0 * H + col);
        float4 vi = *(const float4*)(g + 1 * H + col);
        float4 vo = *(const float4*)(g + 2 * H + col);
        float4 vc = *(const float4*)(g + 3 * H + col);
        float4 vm = *(const float4*)(g + 4 * H + col);
        float4 cp = *(const float4*)(crow + col);
        float4 rr = *(const float4*)(ret + col);
        float bf[4], bi[4], bo[4], bc[4], bm[4], bp[4], br[4];
        *(float4*)bf = vf; *(float4*)bi = vi; *(float4*)bo = vo;
        *(float4*)bc = vc; *(float4*)bm = vm; *(float4*)bp = cp; *(float4*)br = rr;
        #pragma unroll
        for (int e = 0; e < 4; e++) {
            float f = sigm(bf[e]), iv = sigm(bi[e]), m = sigm(bm[e]);
            float ccv = tanhf(bc[e]);
            float cpv = bp[e], rv = br[e];
            float cn = f * cpv + iv * ccv;
            cn = cn * rv + (1.0f - rv) * cpv;
            cn = m * cn + (1.0f - m) * cpv;
            cn_[j * 4 + e] = cn;
            o_[j * 4 + e] = sigm(bo[e]);
        }
    }

    float mu1, rs1;
    warp_ln(o_, mu1, rs1);
    float u_[16];
    #pragma unroll
    for (int j = 0; j < 4; j++) {
        const int col = lid * 4 + j * 128;
        float4 ge = *(const float4*)(eg + col);
        float4 be = *(const float4*)(ebb + col);
        float g_[4], b_[4];
        *(float4*)g_ = ge; *(float4*)b_ = be;
        #pragma unroll
        for (int e = 0; e < 4; e++) {
            float on = (o_[j * 4 + e] - mu1) * rs1 * g_[e] + b_[e];
            u_[j * 4 + e] = sigm(on) * tanhf(cn_[j * 4 + e]);
        }
    }

    float mu2, rs2;
    warp_ln(u_, mu2, rs2);
    #pragma unroll
    for (int j = 0; j < 4; j++) {
        const int col = lid * 4 + j * 128;
        float4 gl = *(const float4*)(lg + col);
        float4 bl = *(const float4*)(lbb + col);
        float g_[4], b_[4], hn[4], cv[4];
        *(float4*)g_ = gl; *(float4*)b_ = bl;
        #pragma unroll
        for (int e = 0; e < 4; e++) {
            hn[e] = (u_[j * 4 + e] - mu2) * rs2 * g_[e] + b_[e];
            cv[e] = cn_[j * 4 + e];
        }
        *(float4*)(crow + col) = *(float4*)cv;
        float h0 = bf_hi(hn[0]), h1 = bf_hi(hn[1]), h2 = bf_hi(hn[2]), h3 = bf_hi(hn[3]);
        uint2 wh, wl;
        wh.x = pack_bf(h0, h1);              wh.y = pack_bf(h2, h3);
        wl.x = pack_bf(hn[0] - h0, hn[1] - h1);
        wl.y = pack_bf(hn[2] - h2, hn[3] - h3);
        *(uint2*)(hH + b * HW + (col >> 1)) = wh;
        *(uint2*)(hL + b * HW + (col >> 1)) = wl;
        if (seq_out) *(float4*)(seq_out + b * TS * H + col) = *(float4*)hn;
    }
}

__global__ __launch_bounds__(256) void gate_kernel(
    const float* __restrict__ G,
    uint32_t* __restrict__ hH, uint32_t* __restrict__ hL,
    float* __restrict__ c,
    const float* __restrict__ ret,
    const float* __restrict__ eg, const float* __restrict__ ebb,
    const float* __restrict__ lg, const float* __restrict__ lbb,
    float* __restrict__ seq_out)
{
    gate_core(G, hH, hL, c, ret, eg, ebb, lg, lbb, seq_out);
}

// Dual gate: y=0 -> gate1(t) (seq out) ; y=1 -> gate0(t+1)
__global__ __launch_bounds__(256) void gate_dual(
    const float* __restrict__ G1, uint32_t* __restrict__ h1H, uint32_t* __restrict__ h1L,
    float* __restrict__ c1,
    const float* __restrict__ G0, uint32_t* __restrict__ h0H, uint32_t* __restrict__ h0L,
    float* __restrict__ c0,
    const float* __restrict__ ret,
    const float* __restrict__ eg, const float* __restrict__ ebb,
    const float* __restrict__ lg, const float* __restrict__ lbb,
    float* __restrict__ seq_out, int has2)
{
    if (blockIdx.y == 0) {
        gate_core(G1, h1H, h1L, c1, ret + H, eg + H, ebb + H, lg + H, lbb + H, seq_out);
    } else {
        if (!has2) return;
        gate_core(G0, h0H, h0L, c0, ret, eg, ebb, lg, lbb, nullptr);
    }
}

// ---------------- last-query attention ----------------
__global__ __launch_bounds__(128) void attn_kernel(
    const float* __restrict__ q,
    const float* __restrict__ kv,
    uint32_t* __restrict__ attH, uint32_t* __restrict__ attL)
{
    __shared__ float qs[DH];
    __shared__ float sc[TS];
    const int b = blockIdx.x, hd = blockIdx.y;
    const int tid = threadIdx.x;

    qs[tid] = q[(size_t)b * H + hd * DH + tid];
    __syncthreads();

    if (tid < TS) {
        const float* kr = kv + ((size_t)b * TS + tid) * K2H + hd * DH;
        float s = 0.0f;
        #pragma unroll 16
        for (int d = 0; d < DH; d++) s += qs[d] * kr[d];
        sc[tid] = s * 0.08838834764831845f;
    }
    __syncthreads();

    float mx = -1e30f;
    #pragma unroll
    for (int t = 0; t < TS; t++) mx = fmaxf(mx, sc[t]);
    float p[TS], ssum = 0.0f;
    #pragma unroll
    for (int t = 0; t < TS; t++) { p[t] = expf(sc[t] - mx); ssum += p[t]; }
    float inv = 1.0f / ssum;

    float acc = 0.0f;
    #pragma unroll
    for (int t = 0; t < TS; t++)
        acc += p[t] * kv[((size_t)b * TS + t) * K2H + H + hd * DH + tid];
    float v = acc * inv;

    float pv = __shfl_down_sync(0xffffffffu, v, 1);
    if (!(tid & 1)) {
        float h0 = bf_hi(v), h1 = bf_hi(pv);
        const size_t w = (size_t)b * HW + hd * (DH / 2) + (tid >> 1);
        attH[w] = pack_bf(h0, h1);
        attL[w] = pack_bf(v - h0, pv - h1);
    }
}

// ---------------- bn2 + output head ----------------
__global__ __launch_bounds__(256) void head_kernel(
    const float* __restrict__ latent,
    const float* __restrict__ bn2_g, const float* __restrict__ bn2_b,
    const float* __restrict__ bn2_rm, const float* __restrict__ bn2_rv,
    const float* __restrict__ out_w, const float* __restrict__ out_b,
    float* __restrict__ out)
{
    __shared__ float lw[OUT * LAT];
    __shared__ float ls[16][LAT];
    __shared__ float scale[LAT], shift[LAT];
    const int b0 = blockIdx.x * 16;
    const int tid = threadIdx.x;

    if (tid < LAT) {
        float s = bn2_g[tid] * rsqrtf(bn2_rv[tid] + EPS);
        scale[tid] = s;
        shift[tid] = bn2_b[tid] - bn2_rm[tid] * s;
    }
    for (int i = tid; i < OUT * LAT; i += 256) lw[i] = out_w[i];
    __syncthreads();

    for (int i = tid; i < 16 * LAT; i += 256) {
        int r = i / LAT, j = i % LAT;
        ls[r][j] = latent[(size_t)(b0 + r) * LAT + j] * scale[j] + shift[j];
    }
    __syncthreads();

    for (int idx = tid; idx < 16 * OUT; idx += 256) {
        int r = idx / OUT, o = idx % OUT;
        float acc = out_b[o];
        #pragma unroll 16
        for (int j = 0; j < LAT; j++) acc += ls[r][j] * lw[o * LAT + j];
        out[(size_t)(b0 + r) * OUT + o] = acc;
    }
}

// ---------------- host launch ----------------
extern "C" void kernel_launch(void* const* d_in, const int* in_sizes, int n_in,
                              void* d_out, int out_size)
{
    const float* x        = (const float*)d_in[0];
    const float* conv1_w  = (const float*)d_in[1];
    const float* conv1_b  = (const float*)d_in[2];
    const float* bn1_g    = (const float*)d_in[3];
    const float* bn1_b    = (const float*)d_in[4];
    const float* bn1_rm   = (const float*)d_in[5];
    const float* bn1_rv   = (const float*)d_in[6];
    const float* comp_w   = (const float*)d_in[7];
    const float* comp_b   = (const float*)d_in[8];
    const float* proj_w   = (const float*)d_in[9];
    const float* proj_b   = (const float*)d_in[10];
    const float* gates_w  = (const float*)d_in[11];
    const float* gates_b  = (const float*)d_in[12];
    const float* retention= (const float*)d_in[13];
    const float* expln_g  = (const float*)d_in[14];
    const float* expln_b  = (const float*)d_in[15];
    const float* ln_g     = (const float*)d_in[16];
    const float* ln_b     = (const float*)d_in[17];
    const float* attn_in_w= (const float*)d_in[18];
    const float* attn_in_b= (const float*)d_in[19];
    const float* attn_out_w=(const float*)d_in[20];
    const float* attn_out_b=(const float*)d_in[21];
    const float* bneck_w  = (const float*)d_in[22];
    const float* bneck_b  = (const float*)d_in[23];
    const float* bn2_g    = (const float*)d_in[24];
    const float* bn2_b    = (const float*)d_in[25];
    const float* bn2_rm   = (const float*)d_in[26];
    const float* bn2_rv   = (const float*)d_in[27];
    const float* out_w    = (const float*)d_in[28];
    const float* out_b    = (const float*)d_in[29];
    float* out = (float*)d_out;

    cudaFuncSetAttribute(gemm_bf16, cudaFuncAttributeMaxDynamicSharedMemorySize,
                         GEMM_SMEM_BYTES);
    cudaFuncSetAttribute(gemm_dual, cudaFuncAttributeMaxDynamicSharedMemorySize,
                         GEMM_SMEM_BYTES);

    float *combined, *seq, *G0, *G1, *c, *kv, *q, *lat;
    uint32_t *combH, *combL, *seqH, *seqL, *hH, *hL, *attH, *attL, *finH, *finL, *Wh, *Wl;
    cudaGetSymbolAddress((void**)&combined, d_combined);
    cudaGetSymbolAddress((void**)&seq,      d_seq);
    cudaGetSymbolAddress((void**)&G0,       d_G0);
    cudaGetSymbolAddress((void**)&G1,       d_G1);
    cudaGetSymbolAddress((void**)&c,        d_c);
    cudaGetSymbolAddress((void**)&kv,       d_kv);
    cudaGetSymbolAddress((void**)&q,        d_q);
    cudaGetSymbolAddress((void**)&lat,      d_lat);
    cudaGetSymbolAddress((void**)&combH,    d_combH);
    cudaGetSymbolAddress((void**)&combL,    d_combL);
    cudaGetSymbolAddress((void**)&seqH,     d_seqH);
    cudaGetSymbolAddress((void**)&seqL,     d_seqL);
    cudaGetSymbolAddress((void**)&hH,       d_hH);
    cudaGetSymbolAddress((void**)&hL,       d_hL);
    cudaGetSymbolAddress((void**)&attH,     d_attH);
    cudaGetSymbolAddress((void**)&attL,     d_attL);
    cudaGetSymbolAddress((void**)&finH,     d_finH);
    cudaGetSymbolAddress((void**)&finL,     d_finL);
    cudaGetSymbolAddress((void**)&Wh,       d_Wh);
    cudaGetSymbolAddress((void**)&Wl,       d_Wl);

    uint32_t* h0H = hH;              uint32_t* h0L = hL;
    uint32_t* h1H = hH + (size_t)B * HW;
    uint32_t* h1L = hL + (size_t)B * HW;
    float* c0 = c;
    float* c1 = c + (size_t)B * H;

    // launch 1: zero state
    zero3_kernel<<<2048, 512>>>(c, 2 * B * H,
                                (float*)hH, 2 * B * HW,
                                (float*)hL, 2 * B * HW);
    // launch 2: frontend
    frontend_kernel<<<B, 256>>>(x, conv1_w, conv1_b, bn1_g, bn1_b, bn1_rm, bn1_rv,
                                comp_w, comp_b, proj_w, proj_b, combined);
    // launch 3: fused split (gates_w + combined + attn_in)
    split3_kernel<<<8192, 256>>>(
        gates_w,   Wh + OFF_W0,  Wl + OFF_W0,  NG * K2H,
        combined,  combH,        combL,        B * TS * H / 2,
        attn_in_w, Wh + OFF_AIN, Wl + OFF_AIN, 3 * H * H / 2);

    const float* gb0 = gates_b;
    const float* gb1 = gates_b + NG;

    // launch 4: prologue GEMM G0(0)  <-- ncu capture target
    dim3 gemm_grid(B / 128, NG / 128);
    gemm_bf16<<<gemm_grid, 256, GEMM_SMEM_BYTES>>>(
        combH, combL, TS * HW, HW, h0H, h0L, HW,
        Wh + OFF_W0, Wl + OFF_W0, 2 * HW, gb0, G0, nullptr, nullptr, NG);
    gate_kernel<<<B / 8, 256>>>(G0, h0H, h0L, c0, retention, expln_g, expln_b,
                                ln_g, ln_b, nullptr);

    // scan: per t, dual GEMM (G1(t) || G0(t+1)) then dual gate
    dim3 dual_grid(B / 128, NG / 128, 2);
    for (int t = 0; t < TS; t++) {
        const int has2 = (t + 1 < TS) ? 1 : 0;
        gemm_dual<<<dual_grid, 256, GEMM_SMEM_BYTES>>>(
            h0H, h0L, h1H, h1L,
            combH + (size_t)(t + 1) * HW, combL + (size_t)(t + 1) * HW,
            Wh, Wl, gb0, gb1, G0, G1, has2);
        gate_dual<<<dim3(B / 8, 2), 256>>>(
            G1, h1H, h1L, c1, G0, h0H, h0L, c0,
            retention, expln_g, expln_b, ln_g, ln_b,
            seq + (size_t)t * H, has2);
    }

    split_kernel<<<8192, 256>>>(seq, seqH, seqL, B * TS * H / 2);
    split_kernel<<<512, 256>>>(attn_out_w, Wh + OFF_AOUT, Wl + OFF_AOUT, H * H / 2);
    split_kernel<<<128, 256>>>(bneck_w,    Wh + OFF_BNK,  Wl + OFF_BNK,  LAT * H / 2);

    // k,v: (B*30, 512) @ (512, 1024)
    gemm_bf16<<<dim3(B * TS / 128, K2H / 128), 256, GEMM_SMEM_BYTES>>>(
        seqH, seqL, HW, HW, seqH, seqL, HW,
        Wh + OFF_AIN + (size_t)H * H / 2, Wl + OFF_AIN + (size_t)H * H / 2, HW,
        attn_in_b + H, kv, nullptr, nullptr, K2H);
    // q at last timestep
    gemm_bf16<<<dim3(B / 128, H / 128), 256, GEMM_SMEM_BYTES>>>(
        seqH + (size_t)(TS - 1) * HW, seqL + (size_t)(TS - 1) * HW, TS * HW, HW,
        seqH, seqL, HW,
        Wh + OFF_AIN, Wl + OFF_AIN, HW, attn_in_b, q, nullptr, nullptr, H);
    attn_kernel<<<dim3(B, NH), 128>>>(q, kv, attH, attL);
    gemm_bf16<<<dim3(B / 128, H / 128), 256, GEMM_SMEM_BYTES>>>(
        attH, attL, HW, HW, attH, attL, HW,
        Wh + OFF_AOUT, Wl + OFF_AOUT, HW, attn_out_b, nullptr, finH, finL, H);
    gemm_bf16<<<dim3(B / 128, LAT / 128), 256, GEMM_SMEM_BYTES>>>(
        finH, finL, HW, HW, finH, finL, HW,
        Wh + OFF_BNK, Wl + OFF_BNK, HW, bneck_b, lat, nullptr, nullptr, LAT);
    head_kernel<<<B / 16, 256>>>(lat, bn2_g, bn2_b, bn2_rm, bn2_rv, out_w, out_b, out);
}

// round 9
// speedup vs baseline: 5.5520x; 1.0175x over previous
#include <cuda_runtime.h>
#include <cuda_bf16.h>
#include <cstdint>
#include <cstddef>

#define EPS 1e-5f

// ---------------- problem constants ----------------
#define B   4096
#define TT  60
#define TS  30
#define H   512
#define LAT 128
#define OUT 14
#define NH  4
#define DH  128
#define NG  2560
#define K2H 1024

// ---------------- device scratch ----------------
__device__ float d_combined[(size_t)B * TS * H];
__device__ float d_seq     [(size_t)B * TS * H];
__device__ float d_G0      [(size_t)B * NG];
__device__ float d_G1      [(size_t)B * NG];
__device__ float d_c       [(size_t)2 * B * H];
__device__ float d_kv      [(size_t)B * TS * K2H];
__device__ float d_q       [(size_t)B * H];
__device__ float d_lat     [(size_t)B * LAT];

#define HW  256
__device__ uint32_t d_combH[(size_t)B * TS * HW];
__device__ uint32_t d_combL[(size_t)B * TS * HW];
__device__ uint32_t d_seqH [(size_t)B * TS * HW];
__device__ uint32_t d_seqL [(size_t)B * TS * HW];
__device__ uint32_t d_hH   [(size_t)2 * B * HW];
__device__ uint32_t d_hL   [(size_t)2 * B * HW];
__device__ uint32_t d_attH [(size_t)B * HW];
__device__ uint32_t d_attL [(size_t)B * HW];
__device__ uint32_t d_finH [(size_t)B * HW];
__device__ uint32_t d_finL [(size_t)B * HW];

#define OFF_W0   0
#define OFF_W1   1310720
#define OFF_AIN  2621440
#define OFF_AOUT 3014656
#define OFF_BNK  3145728
#define W_WORDS  3178496
__device__ uint32_t d_Wh[(size_t)W_WORDS];
__device__ uint32_t d_Wl[(size_t)W_WORDS];

// ---------------- helpers ----------------
__device__ __forceinline__ uint32_t pack_bf(float a, float b) {
    __nv_bfloat162 t = __floats2bfloat162_rn(a, b);
    return *reinterpret_cast<uint32_t*>(&t);
}
__device__ __forceinline__ float bf_hi(float x) {
    return __bfloat162float(__float2bfloat16_rn(x));
}
__device__ __forceinline__ uint32_t smem_u32(const void* p) {
    uint32_t a;
    asm("{ .reg .u64 t; cvta.to.shared.u64 t, %1; cvt.u32.u64 %0, t; }" : "=r"(a) : "l"(p));
    return a;
}

#define MMA16(d, a, b) \
    asm volatile( \
        "mma.sync.aligned.m16n8k16.row.col.f32.bf16.bf16.f32 " \
        "{%0,%1,%2,%3}, {%4,%5,%6,%7}, {%8,%9}, {%0,%1,%2,%3};" \
        : "+f"((d)[0]), "+f"((d)[1]), "+f"((d)[2]), "+f"((d)[3]) \
        : "r"((a)[0]), "r"((a)[1]), "r"((a)[2]), "r"((a)[3]), \
          "r"((b)[0]), "r"((b)[1]))

#define LDSM4(v, addr) \
    asm volatile("ldmatrix.sync.aligned.m8n8.x4.shared.b16 {%0,%1,%2,%3}, [%4];" \
        : "=r"((v)[0]), "=r"((v)[1]), "=r"((v)[2]), "=r"((v)[3]) : "r"(addr))

#define CP16(dst, src) \
    asm volatile("cp.async.cg.shared.global [%0], [%1], 16;" :: "r"(dst), "l"(src))
#define CPCOMMIT() asm volatile("cp.async.commit_group;" ::: "memory")
#define CPWAIT1()  asm volatile("cp.async.wait_group 1;" ::: "memory")

#define STG_WORDS 8192
#define GEMM_SMEM_BYTES (3 * STG_WORDS * 4)

// ---------------- fused zero init ----------------
__global__ void zero3_kernel(float* __restrict__ p0, int n0,
                             float* __restrict__ p1, int n1,
                             float* __restrict__ p2, int n2) {
    int i = blockIdx.x * blockDim.x + threadIdx.x;
    int stride = gridDim.x * blockDim.x;
    for (int j = i; j < n0; j += stride) p0[j] = 0.0f;
    for (int j = i; j < n1; j += stride) p1[j] = 0.0f;
    for (int j = i; j < n2; j += stride) p2[j] = 0.0f;
}

// ---------------- bf16 hi/lo packed split ----------------
__device__ __forceinline__ void split_range(const float* __restrict__ src,
                                            uint32_t* __restrict__ hi,
                                            uint32_t* __restrict__ lo,
                                            int nwords, int i, int stride) {
    for (; i < nwords; i += stride) {
        float2 v = *(const float2*)(src + 2 * (size_t)i);
        float h0 = bf_hi(v.x), h1 = bf_hi(v.y);
        hi[i] = pack_bf(h0, h1);
        lo[i] = pack_bf(v.x - h0, v.y - h1);
    }
}
__global__ void split_kernel(const float* __restrict__ src,
                             uint32_t* __restrict__ hi, uint32_t* __restrict__ lo,
                             int nwords) {
    split_range(src, hi, lo, nwords,
                blockIdx.x * blockDim.x + threadIdx.x, gridDim.x * blockDim.x);
}
__global__ void split3_kernel(
    const float* __restrict__ s0, uint32_t* __restrict__ h0, uint32_t* __restrict__ l0, int n0,
    const float* __restrict__ s1, uint32_t* __restrict__ h1, uint32_t* __restrict__ l1, int n1,
    const float* __restrict__ s2, uint32_t* __restrict__ h2, uint32_t* __restrict__ l2, int n2) {
    int i = blockIdx.x * blockDim.x + threadIdx.x;
    int stride = gridDim.x * blockDim.x;
    split_range(s0, h0, l0, n0, i, stride);
    split_range(s1, h1, l1, n1, i, stride);
    split_range(s2, h2, l2, n2, i, stride);
}

// ================= bf16x3 GEMM core (cp.async + ldmatrix, 2 CTA/SM) =================
__device__ __forceinline__ void gemm_core(
    const uint32_t* __restrict__ A1h, const uint32_t* __restrict__ A1l,
    int lda1, int K1w,
    const uint32_t* __restrict__ A2h, const uint32_t* __restrict__ A2l,
    int lda2,
    const uint32_t* __restrict__ Wh, const uint32_t* __restrict__ Wl, int Kw,
    const float* __restrict__ bias,
    float* __restrict__ C, uint32_t* __restrict__ Ch, uint32_t* __restrict__ Cl,
    int N, int m0, int n0, uint32_t smb)
{
    const int tid = threadIdx.x;
    const int wid = tid >> 5, lane = tid & 31;
    const int g = lane >> 2, t4 = lane & 3;
    const int warp_m = wid >> 2, warp_n = wid & 3;

    const int r = tid >> 1, half = tid & 1;
    const int wb = half * 8;
    const int swz = ((r >> 1) & 3) << 2;
    const int so0 = r * 16 + ((wb) ^ swz);
    const int so1 = r * 16 + ((wb + 4) ^ swz);

    const int a_r = lane & 15;
    const int a_k = (lane >> 4) << 2;
    int aoff[4], aswz[4];
    #pragma unroll
    for (int tm = 0; tm < 4; tm++) {
        const int row = warp_m * 64 + tm * 16 + a_r;
        aoff[tm] = row * 16;
        aswz[tm] = ((row >> 1) & 3) << 2;
    }
    const int b_r = (lane & 7) + ((lane >> 4) << 3);
    const int b_k = ((lane >> 3) & 1) << 2;
    int boff[2], bswz[2];
    #pragma unroll
    for (int tp = 0; tp < 2; tp++) {
        const int row = warp_n * 32 + tp * 16 + b_r;
        boff[tp] = row * 16;
        bswz[tp] = ((row >> 1) & 3) << 2;
    }

    float acc[4][4][4];
    #pragma unroll
    for (int i = 0; i < 4; i++)
        #pragma unroll
        for (int j = 0; j < 4; j++)
            #pragma unroll
            for (int e = 0; e < 4; e++) acc[i][j][e] = 0.0f;

    const int NKB = Kw / 16;

    auto issue = [&](int kb, int stage) {
        const int kbw = kb * 16 + wb;
        const uint32_t *ah, *al;
        if (kbw < K1w) {
            ah = A1h + (size_t)(m0 + r) * lda1 + kbw;
            al = A1l + (size_t)(m0 + r) * lda1 + kbw;
        } else {
            ah = A2h + (size_t)(m0 + r) * lda2 + (kbw - K1w);
            al = A2l + (size_t)(m0 + r) * lda2 + (kbw - K1w);
        }
        const uint32_t* bh = Wh + (size_t)(n0 + r) * Kw + kbw;
        const uint32_t* bl = Wl + (size_t)(n0 + r) * Kw + kbw;
        const uint32_t sb = smb + (uint32_t)(stage * STG_WORDS) * 4;
        CP16(sb + so0 * 4, ah);                 CP16(sb + so1 * 4, ah + 4);
        CP16(sb + (2048 + so0) * 4, al);        CP16(sb + (2048 + so1) * 4, al + 4);
        CP16(sb + (4096 + so0) * 4, bh);        CP16(sb + (4096 + so1) * 4, bh + 4);
        CP16(sb + (6144 + so0) * 4, bl);        CP16(sb + (6144 + so1) * 4, bl + 4);
    };

    issue(0, 0); CPCOMMIT();
    issue(1, 1); CPCOMMIT();

    for (int kb = 0; kb < NKB; kb++) {
        CPWAIT1();
        __syncthreads();
        const uint32_t sbase = smb + (uint32_t)((kb % 3) * STG_WORDS) * 4;

        #pragma unroll
        for (int kc = 0; kc < 2; kc++) {
            const int akw = kc * 8 + a_k;
            const int bkw = kc * 8 + b_k;
            // B fragments first (16 regs live)
            uint32_t Bh[2][4], Bl[2][4];
            #pragma unroll
            for (int tp = 0; tp < 2; tp++) {
                const uint32_t bd = sbase + (uint32_t)(4096 + boff[tp] + (bkw ^ bswz[tp])) * 4;
                LDSM4(Bh[tp], bd);
                LDSM4(Bl[tp], bd + 2048 * 4);
            }
            // per-tm A fragments (8 regs live at a time)
            #pragma unroll
            for (int tm = 0; tm < 4; tm++) {
                uint32_t Ah[4], Al[4];
                const uint32_t ad = sbase + (uint32_t)(aoff[tm] + (akw ^ aswz[tm])) * 4;
                LDSM4(Ah, ad);
                LDSM4(Al, ad + 2048 * 4);
                #pragma unroll
                for (int tn = 0; tn < 4; tn++) {
                    uint32_t* bh = &Bh[tn >> 1][(tn & 1) * 2];
                    uint32_t* bl = &Bl[tn >> 1][(tn & 1) * 2];
                    MMA16(acc[tm][tn], Ah, bh);
                    MMA16(acc[tm][tn], Ah, bl);
                    MMA16(acc[tm][tn], Al, bh);
                }
            }
        }
        if (kb + 2 < NKB) issue(kb + 2, (kb + 2) % 3);
        CPCOMMIT();
    }

    const int Nw = N >> 1;
    #pragma unroll
    for (int tm = 0; tm < 4; tm++) {
        const int row0 = m0 + warp_m * 64 + tm * 16 + g;
        #pragma unroll
        for (int tn = 0; tn < 4; tn++) {
            const int col = n0 + warp_n * 32 + tn * 8 + t4 * 2;
            const float b0 = bias[col], b1 = bias[col + 1];
            const float v00 = acc[tm][tn][0] + b0, v01 = acc[tm][tn][1] + b1;
            const float v10 = acc[tm][tn][2] + b0, v11 = acc[tm][tn][3] + b1;
            if (C) {
                *(float2*)(C + (size_t)row0 * N + col)       = make_float2(v00, v01);
                *(float2*)(C + (size_t)(row0 + 8) * N + col) = make_float2(v10, v11);
            }
            if (Ch) {
                const int w = (col >> 1);
                float h00 = bf_hi(v00), h01 = bf_hi(v01);
                float h10 = bf_hi(v10), h11 = bf_hi(v11);
                Ch[(size_t)row0 * Nw + w]       = pack_bf(h00, h01);
                Cl[(size_t)row0 * Nw + w]       = pack_bf(v00 - h00, v01 - h01);
                Ch[(size_t)(row0 + 8) * Nw + w] = pack_bf(h10, h11);
                Cl[(size_t)(row0 + 8) * Nw + w] = pack_bf(v10 - h10, v11 - h11);
            }
        }
    }
}

__global__ __launch_bounds__(256, 2) void gemm_bf16(
    const uint32_t* __restrict__ A1h, const uint32_t* __restrict__ A1l,
    int lda1, int K1w,
    const uint32_t* __restrict__ A2h, const uint32_t* __restrict__ A2l,
    int lda2,
    const uint32_t* __restrict__ Wh, const uint32_t* __restrict__ Wl, int Kw,
    const float* __restrict__ bias,
    float* __restrict__ C, uint32_t* __restrict__ Ch, uint32_t* __restrict__ Cl,
    int N)
{
    extern __shared__ uint32_t sm[];
    gemm_core(A1h, A1l, lda1, K1w, A2h, A2l, lda2, Wh, Wl, Kw, bias,
              C, Ch, Cl, N, blockIdx.x * 128, blockIdx.y * 128, smem_u32(sm));
}

// Dual GEMM: z=0 -> G1(t) = [h0|h1] @ W1 ; z=1 -> G0(t+1) = [comb(t+1)|h0] @ W0
__global__ __launch_bounds__(256, 2) void gemm_dual(
    const uint32_t* __restrict__ h0H, const uint32_t* __restrict__ h0L,
    const uint32_t* __restrict__ h1H, const uint32_t* __restrict__ h1L,
    const uint32_t* __restrict__ combH, const uint32_t* __restrict__ combL,
    const uint32_t* __restrict__ Wall_h, const uint32_t* __restrict__ Wall_l,
    const float* __restrict__ gb0, const float* __restrict__ gb1,
    float* __restrict__ G0, float* __restrict__ G1,
    int has2)
{
    extern __shared__ uint32_t sm[];
    const uint32_t* A1h; const uint32_t* A1l; int lda1;
    const uint32_t* A2h; const uint32_t* A2l;
    const uint32_t* Wh;  const uint32_t* Wl;
    const float* bias;   float* C;
    if (blockIdx.z == 0) {
        A1h = h0H; A1l = h0L; lda1 = HW;
        A2h = h1H; A2l = h1L;
        Wh = Wall_h + OFF_W1; Wl = Wall_l + OFF_W1;
        bias = gb1; C = G1;
    } else {
        if (!has2) return;
        A1h = combH; A1l = combL; lda1 = TS * HW;
        A2h = h0H;   A2l = h0L;
        Wh = Wall_h + OFF_W0; Wl = Wall_l + OFF_W0;
        bias = gb0; C = G0;
    }
    gemm_core(A1h, A1l, lda1, HW, A2h, A2l, HW, Wh, Wl, 2 * HW, bias,
              C, nullptr, nullptr, NG, blockIdx.x * 128, blockIdx.y * 128, smem_u32(sm));
}

// ---------------- frontend ----------------
__global__ __launch_bounds__(256) void frontend_kernel(
    const float* __restrict__ x,
    const float* __restrict__ conv_w, const float* __restrict__ conv_b,
    const float* __restrict__ bn1_g, const float* __restrict__ bn1_b,
    const float* __restrict__ bn1_rm, const float* __restrict__ bn1_rv,
    const float* __restrict__ comp_w, const float* __restrict__ comp_b,
    const float* __restrict__ proj_w, const float* __restrict__ proj_b,
    float* __restrict__ combined)
{
    __shared__ float xs[TT][17];
    __shared__ float cw[24 * 9 * 3];
    __shared__ float cbias[24], cscale[24], cshift[24];
    __shared__ float cpw[20 * 8], cpb[20];
    __shared__ float feat[TS][44];

    const int b = blockIdx.x;
    const int tid = threadIdx.x;
    const float* xb = x + (size_t)b * TT * 17;

    for (int i = tid; i < TT * 17; i += 256) xs[i / 17][i % 17] = xb[i];
    for (int i = tid; i < 648; i += 256) cw[i] = conv_w[i];
    if (tid < 24) {
        cbias[tid] = conv_b[tid];
        float s = bn1_g[tid] * rsqrtf(bn1_rv[tid] + EPS);
        cscale[tid] = s;
        cshift[tid] = bn1_b[tid] - bn1_rm[tid] * s;
    }
    for (int i = tid; i < 160; i += 256) cpw[i] = comp_w[i];
    if (tid < 20) cpb[tid] = comp_b[tid];
    __syncthreads();

    for (int idx = tid; idx < 24 * TS; idx += 256) {
        int o = idx % 24, th = idx / 24;
        float mx = -1e30f;
        #pragma unroll
        for (int s = 0; s < 2; s++) {
            int t = th * 2 + s;
            float acc = cbias[o];
            #pragma unroll
            for (int k = 0; k < 3; k++) {
                int tt = t + k - 1;
                if (tt >= 0 && tt < TT) {
                    #pragma unroll
                    for (int i2 = 0; i2 < 9; i2++)
                        acc += xs[tt][i2] * cw[o * 27 + i2 * 3 + k];
                }
            }
            acc = fmaxf(acc, 0.0f);
            acc = acc * cscale[o] + cshift[o];
            mx = fmaxf(mx, acc);
        }
        feat[th][o] = mx;
    }
    for (int idx = tid; idx < TS * 20; idx += 256) {
        int j = idx % 20, t = idx / 20;
        float acc = cpb[j];
        #pragma unroll
        for (int i2 = 0; i2 < 8; i2++) acc += xs[t][9 + i2] * cpw[j * 8 + i2];
        feat[t][24 + j] = fmaxf(acc, 0.0f);
    }
    __syncthreads();

    for (int hh = tid; hh < H; hh += 256) {
        float w[44];
        #pragma unroll
        for (int f = 0; f < 44; f++) w[f] = proj_w[hh * 44 + f];
        float pb = proj_b[hh];
        for (int t = 0; t < TS; t++) {
            float acc = pb;
            #pragma unroll
            for (int f = 0; f < 44; f++) acc += feat[t][f] * w[f];
            combined[((size_t)b * TS + t) * H + hh] = acc;
        }
    }
}

// ---------------- gate core: warp per batch row ----------------
__device__ __forceinline__ float sigm(float v) { return 1.0f / (1.0f + expf(-v)); }

__device__ __forceinline__ void warp_ln(const float* v, float& mu, float& rs) {
    float s = 0.0f, q = 0.0f;
    #pragma unroll
    for (int i = 0; i < 16; i++) { s += v[i]; q += v[i] * v[i]; }
    #pragma unroll
    for (int o = 16; o > 0; o >>= 1) {
        s += __shfl_xor_sync(0xffffffffu, s, o);
        q += __shfl_xor_sync(0xffffffffu, q, o);
    }
    mu = s * (1.0f / 512.0f);
    rs = rsqrtf(q * (1.0f / 512.0f) - mu * mu + EPS);
}

__device__ __forceinline__ void gate_core(
    const float* __restrict__ G,
    uint32_t* __restrict__ hH, uint32_t* __restrict__ hL,
    float* __restrict__ c,
    const float* __restrict__ ret,
    const float* __restrict__ eg, const float* __restrict__ ebb,
    const float* __restrict__ lg, const float* __restrict__ lbb,
    float* __restrict__ seq_out)
{
    const int wid = threadIdx.x >> 5, lid = threadIdx.x & 31;
    const size_t b = (size_t)blockIdx.x * 8 + wid;
    const float* g = G + b * NG;
    float* crow = c + b * H;

    float o_[16], cn_[16];
    #pragma unroll
    for (int j = 0; j < 4; j++) {
        const int col = lid * 4 + j * 128;
        float4 vf = *(const float4*)(g + 0 * H + col);
        float4 vi = *(const float4*)(g + 1 * H + col);
        float4 vo = *(const float4*)(g + 2 * H + col);
        float4 vc = *(const float4*)(g + 3 * H + col);
        float4 vm = *(const float4*)(g + 4 * H + col);
        float4 cp = *(const float4*)(crow + col);
        float4 rr = *(const float4*)(ret + col);
        float bf[4], bi[4], bo[4], bc[4], bm[4], bp[4], br[4];
        *(float4*)bf = vf; *(float4*)bi = vi; *(float4*)bo = vo;
        *(float4*)bc = vc; *(float4*)bm = vm; *(float4*)bp = cp; *(float4*)br = rr;
        #pragma unroll
        for (int e = 0; e < 4; e++) {
            float f = sigm(bf[e]), iv = sigm(bi[e]), m = sigm(bm[e]);
            float ccv = tanhf(bc[e]);
            float cpv = bp[e], rv = br[e];
            float cn = f * cpv + iv * ccv;
            cn = cn * rv + (1.0f - rv) * cpv;
            cn = m * cn + (1.0f - m) * cpv;
            cn_[j * 4 + e] = cn;
            o_[j * 4 + e] = sigm(bo[e]);
        }
    }

    float mu1, rs1;
    warp_ln(o_, mu1, rs1);
    float u_[16];
    #pragma unroll
    for (int j = 0; j < 4; j++) {
        const int col = lid * 4 + j * 128;
        float4 ge = *(const float4*)(eg + col);
        float4 be = *(const float4*)(ebb + col);
        float g_[4], b_[4];
        *(float4*)g_ = ge; *(float4*)b_ = be;
        #pragma unroll
        for (int e = 0; e < 4; e++) {
            float on = (o_[j * 4 + e] - mu1) * rs1 * g_[e] + b_[e];
            u_[j * 4 + e] = sigm(on) * tanhf(cn_[j * 4 + e]);
        }
    }

    float mu2, rs2;
    warp_ln(u_, mu2, rs2);
    #pragma unroll
    for (int j = 0; j < 4; j++) {
        const int col = lid * 4 + j * 128;
        float4 gl = *(const float4*)(lg + col);
        float4 bl = *(const float4*)(lbb + col);
        float g_[4], b_[4], hn[4], cv[4];
        *(float4*)g_ = gl; *(float4*)b_ = bl;
        #pragma unroll
        for (int e = 0; e < 4; e++) {
            hn[e] = (u_[j * 4 + e] - mu2) * rs2 * g_[e] + b_[e];
            cv[e] = cn_[j * 4 + e];
        }
        *(float4*)(crow + col) = *(float4*)cv;
        float h0 = bf_hi(hn[0]), h1 = bf_hi(hn[1]), h2 = bf_hi(hn[2]), h3 = bf_hi(hn[3]);
        uint2 wh, wl;
        wh.x = pack_bf(h0, h1);              wh.y = pack_bf(h2, h3);
        wl.x = pack_bf(hn[0] - h0, hn[1] - h1);
        wl.y = pack_bf(hn[2] - h2, hn[3] - h3);
        *(uint2*)(hH + b * HW + (col >> 1)) = wh;
        *(uint2*)(hL + b * HW + (col >> 1)) = wl;
        if (seq_out) *(float4*)(seq_out + b * TS * H + col) = *(float4*)hn;
    }
}

__global__ __launch_bounds__(256) void gate_kernel(
    const float* __restrict__ G,
    uint32_t* __restrict__ hH, uint32_t* __restrict__ hL,
    float* __restrict__ c,
    const float* __restrict__ ret,
    const float* __restrict__ eg, const float* __restrict__ ebb,
    const float* __restrict__ lg, const float* __restrict__ lbb,
    float* __restrict__ seq_out)
{
    gate_core(G, hH, hL, c, ret, eg, ebb, lg, lbb, seq_out);
}

// Dual gate: y=0 -> gate1(t) (seq out) ; y=1 -> gate0(t+1)
__global__ __launch_bounds__(256) void gate_dual(
    const float* __restrict__ G1, uint32_t* __restrict__ h1H, uint32_t* __restrict__ h1L,
    float* __restrict__ c1,
    const float* __restrict__ G0, uint32_t* __restrict__ h0H, uint32_t* __restrict__ h0L,
    float* __restrict__ c0,
    const float* __restrict__ ret,
    const float* __restrict__ eg, const float* __restrict__ ebb,
    const float* __restrict__ lg, const float* __restrict__ lbb,
    float* __restrict__ seq_out, int has2)
{
    if (blockIdx.y == 0) {
        gate_core(G1, h1H, h1L, c1, ret + H, eg + H, ebb + H, lg + H, lbb + H, seq_out);
    } else {
        if (!has2) return;
        gate_core(G0, h0H, h0L, c0, ret, eg, ebb, lg, lbb, nullptr);
    }
}

// ---------------- last-query attention ----------------
__global__ __launch_bounds__(128) void attn_kernel(
    const float* __restrict__ q,
    const float* __restrict__ kv,
    uint32_t* __restrict__ attH, uint32_t* __restrict__ attL)
{
    __shared__ float qs[DH];
    __shared__ float sc[TS];
    const int b = blockIdx.x, hd = blockIdx.y;
    const int tid = threadIdx.x;

    qs[tid] = q[(size_t)b * H + hd * DH + tid];
    __syncthreads();

    if (tid < TS) {
        const float* kr = kv + ((size_t)b * TS + tid) * K2H + hd * DH;
        float s = 0.0f;
        #pragma unroll 16
        for (int d = 0; d < DH; d++) s += qs[d] * kr[d];
        sc[tid] = s * 0.08838834764831845f;
    }
    __syncthreads();

    float mx = -1e30f;
    #pragma unroll
    for (int t = 0; t < TS; t++) mx = fmaxf(mx, sc[t]);
    float p[TS], ssum = 0.0f;
    #pragma unroll
    for (int t = 0; t < TS; t++) { p[t] = expf(sc[t] - mx); ssum += p[t]; }
    float inv = 1.0f / ssum;

    float acc = 0.0f;
    #pragma unroll
    for (int t = 0; t < TS; t++)
        acc += p[t] * kv[((size_t)b * TS + t) * K2H + H + hd * DH + tid];
    float v = acc * inv;

    float pv = __shfl_down_sync(0xffffffffu, v, 1);
    if (!(tid & 1)) {
        float h0 = bf_hi(v), h1 = bf_hi(pv);
        const size_t w = (size_t)b * HW + hd * (DH / 2) + (tid >> 1);
        attH[w] = pack_bf(h0, h1);
        attL[w] = pack_bf(v - h0, pv - h1);
    }
}

// ---------------- bn2 + output head ----------------
__global__ __launch_bounds__(256) void head_kernel(
    const float* __restrict__ latent,
    const float* __restrict__ bn2_g, const float* __restrict__ bn2_b,
    const float* __restrict__ bn2_rm, const float* __restrict__ bn2_rv,
    const float* __restrict__ out_w, const float* __restrict__ out_b,
    float* __restrict__ out)
{
    __shared__ float lw[OUT * LAT];
    __shared__ float ls[16][LAT];
    __shared__ float scale[LAT], shift[LAT];
    const int b0 = blockIdx.x * 16;
    const int tid = threadIdx.x;

    if (tid < LAT) {
        float s = bn2_g[tid] * rsqrtf(bn2_rv[tid] + EPS);
        scale[tid] = s;
        shift[tid] = bn2_b[tid] - bn2_rm[tid] * s;
    }
    for (int i = tid; i < OUT * LAT; i += 256) lw[i] = out_w[i];
    __syncthreads();

    for (int i = tid; i < 16 * LAT; i += 256) {
        int r = i / LAT, j = i % LAT;
        ls[r][j] = latent[(size_t)(b0 + r) * LAT + j] * scale[j] + shift[j];
    }
    __syncthreads();

    for (int idx = tid; idx < 16 * OUT; idx += 256) {
        int r = idx / OUT, o = idx % OUT;
        float acc = out_b[o];
        #pragma unroll 16
        for (int j = 0; j < LAT; j++) acc += ls[r][j] * lw[o * LAT + j];
        out[(size_t)(b0 + r) * OUT + o] = acc;
    }
}

// ---------------- host launch ----------------
extern "C" void kernel_launch(void* const* d_in, const int* in_sizes, int n_in,
                              void* d_out, int out_size)
{
    const float* x        = (const float*)d_in[0];
    const float* conv1_w  = (const float*)d_in[1];
    const float* conv1_b  = (const float*)d_in[2];
    const float* bn1_g    = (const float*)d_in[3];
    const float* bn1_b    = (const float*)d_in[4];
    const float* bn1_rm   = (const float*)d_in[5];
    const float* bn1_rv   = (const float*)d_in[6];
    const float* comp_w   = (const float*)d_in[7];
    const float* comp_b   = (const float*)d_in[8];
    const float* proj_w   = (const float*)d_in[9];
    const float* proj_b   = (const float*)d_in[10];
    const float* gates_w  = (const float*)d_in[11];
    const float* gates_b  = (const float*)d_in[12];
    const float* retention= (const float*)d_in[13];
    const float* expln_g  = (const float*)d_in[14];
    const float* expln_b  = (const float*)d_in[15];
    const float* ln_g     = (const float*)d_in[16];
    const float* ln_b     = (const float*)d_in[17];
    const float* attn_in_w= (const float*)d_in[18];
    const float* attn_in_b= (const float*)d_in[19];
    const float* attn_out_w=(const float*)d_in[20];
    const float* attn_out_b=(const float*)d_in[21];
    const float* bneck_w  = (const float*)d_in[22];
    const float* bneck_b  = (const float*)d_in[23];
    const float* bn2_g    = (const float*)d_in[24];
    const float* bn2_b    = (const float*)d_in[25];
    const float* bn2_rm   = (const float*)d_in[26];
    const float* bn2_rv   = (const float*)d_in[27];
    const float* out_w    = (const float*)d_in[28];
    const float* out_b    = (const float*)d_in[29];
    float* out = (float*)d_out;

    cudaFuncSetAttribute(gemm_bf16, cudaFuncAttributeMaxDynamicSharedMemorySize,
                         GEMM_SMEM_BYTES);
    cudaFuncSetAttribute(gemm_dual, cudaFuncAttributeMaxDynamicSharedMemorySize,
                         GEMM_SMEM_BYTES);

    float *combined, *seq, *G0, *G1, *c, *kv, *q, *lat;
    uint32_t *combH, *combL, *seqH, *seqL, *hH, *hL, *attH, *attL, *finH, *finL, *Wh, *Wl;
    cudaGetSymbolAddress((void**)&combined, d_combined);
    cudaGetSymbolAddress((void**)&seq,      d_seq);
    cudaGetSymbolAddress((void**)&G0,       d_G0);
    cudaGetSymbolAddress((void**)&G1,       d_G1);
    cudaGetSymbolAddress((void**)&c,        d_c);
    cudaGetSymbolAddress((void**)&kv,       d_kv);
    cudaGetSymbolAddress((void**)&q,        d_q);
    cudaGetSymbolAddress((void**)&lat,      d_lat);
    cudaGetSymbolAddress((void**)&combH,    d_combH);
    cudaGetSymbolAddress((void**)&combL,    d_combL);
    cudaGetSymbolAddress((void**)&seqH,     d_seqH);
    cudaGetSymbolAddress((void**)&seqL,     d_seqL);
    cudaGetSymbolAddress((void**)&hH,       d_hH);
    cudaGetSymbolAddress((void**)&hL,       d_hL);
    cudaGetSymbolAddress((void**)&attH,     d_attH);
    cudaGetSymbolAddress((void**)&attL,     d_attL);
    cudaGetSymbolAddress((void**)&finH,     d_finH);
    cudaGetSymbolAddress((void**)&finL,     d_finL);
    cudaGetSymbolAddress((void**)&Wh,       d_Wh);
    cudaGetSymbolAddress((void**)&Wl,       d_Wl);

    uint32_t* h0H = hH;              uint32_t* h0L = hL;
    uint32_t* h1H = hH + (size_t)B * HW;
    uint32_t* h1L = hL + (size_t)B * HW;
    float* c0 = c;
    float* c1 = c + (size_t)B * H;

    zero3_kernel<<<2048, 512>>>(c, 2 * B * H,
                                (float*)hH, 2 * B * HW,
                                (float*)hL, 2 * B * HW);
    frontend_kernel<<<B, 256>>>(x, conv1_w, conv1_b, bn1_g, bn1_b, bn1_rm, bn1_rv,
                                comp_w, comp_b, proj_w, proj_b, combined);
    split3_kernel<<<8192, 256>>>(
        gates_w,   Wh + OFF_W0,  Wl + OFF_W0,  NG * K2H,
        combined,  combH,        combL,        B * TS * H / 2,
        attn_in_w, Wh + OFF_AIN, Wl + OFF_AIN, 3 * H * H / 2);

    const float* gb0 = gates_b;
    const float* gb1 = gates_b + NG;

    // launch 4: prologue GEMM G0(0)  <-- ncu capture target
    dim3 gemm_grid(B / 128, NG / 128);
    gemm_bf16<<<gemm_grid, 256, GEMM_SMEM_BYTES>>>(
        combH, combL, TS * HW, HW, h0H, h0L, HW,
        Wh + OFF_W0, Wl + OFF_W0, 2 * HW, gb0, G0, nullptr, nullptr, NG);
    gate_kernel<<<B / 8, 256>>>(G0, h0H, h0L, c0, retention, expln_g, expln_b,
                                ln_g, ln_b, nullptr);

    // scan: per t, dual GEMM (G1(t) || G0(t+1)) then dual gate
    dim3 dual_grid(B / 128, NG / 128, 2);
    for (int t = 0; t < TS; t++) {
        const int has2 = (t + 1 < TS) ? 1 : 0;
        gemm_dual<<<dual_grid, 256, GEMM_SMEM_BYTES>>>(
            h0H, h0L, h1H, h1L,
            combH + (size_t)(t + 1) * HW, combL + (size_t)(t + 1) * HW,
            Wh, Wl, gb0, gb1, G0, G1, has2);
        gate_dual<<<dim3(B / 8, 2), 256>>>(
            G1, h1H, h1L, c1, G0, h0H, h0L, c0,
            retention, expln_g, expln_b, ln_g, ln_b,
            seq + (size_t)t * H, has2);
    }

    split_kernel<<<8192, 256>>>(seq, seqH, seqL, B * TS * H / 2);
    split_kernel<<<512, 256>>>(attn_out_w, Wh + OFF_AOUT, Wl + OFF_AOUT, H * H / 2);
    split_kernel<<<128, 256>>>(bneck_w,    Wh + OFF_BNK,  Wl + OFF_BNK,  LAT * H / 2);

    // k,v: (B*30, 512) @ (512, 1024)
    gemm_bf16<<<dim3(B * TS / 128, K2H / 128), 256, GEMM_SMEM_BYTES>>>(
        seqH, seqL, HW, HW, seqH, seqL, HW,
        Wh + OFF_AIN + (size_t)H * H / 2, Wl + OFF_AIN + (size_t)H * H / 2, HW,
        attn_in_b + H, kv, nullptr, nullptr, K2H);
    // q at last timestep
    gemm_bf16<<<dim3(B / 128, H / 128), 256, GEMM_SMEM_BYTES>>>(
        seqH + (size_t)(TS - 1) * HW, seqL + (size_t)(TS - 1) * HW, TS * HW, HW,
        seqH, seqL, HW,
        Wh + OFF_AIN, Wl + OFF_AIN, HW, attn_in_b, q, nullptr, nullptr, H);
    attn_kernel<<<dim3(B, NH), 128>>>(q, kv, attH, attL);
    gemm_bf16<<<dim3(B / 128, H / 128), 256, GEMM_SMEM_BYTES>>>(
        attH, attL, HW, HW, attH, attL, HW,
        Wh + OFF_AOUT, Wl + OFF_AOUT, HW, attn_out_b, nullptr, finH, finL, H);
    gemm_bf16<<<dim3(B / 128, LAT / 128), 256, GEMM_SMEM_BYTES>>>(
        finH, finL, HW, HW, finH, finL, HW,
        Wh + OFF_BNK, Wl + OFF_BNK, HW, bneck_b, lat, nullptr, nullptr, LAT);
    head_kernel<<<B / 16, 256>>>(lat, bn2_g, bn2_b, bn2_rm, bn2_rv, out_w, out_b, out);
}

// round 10
// speedup vs baseline: 5.5847x; 1.0059x over previous
#include <cuda_runtime.h>
#include <cuda_bf16.h>
#include <cstdint>
#include <cstddef>

#define EPS 1e-5f

// ---------------- problem constants ----------------
#define B   4096
#define TT  60
#define TS  30
#define H   512
#define LAT 128
#define OUT 14
#define NH  4
#define DH  128
#define NG  2560
#define K2H 1024

// ---------------- device scratch ----------------
__device__ float d_combined[(size_t)B * TS * H];
__device__ float d_G0a     [(size_t)B * NG];
__device__ float d_G0b     [(size_t)B * NG];
__device__ float d_G1a     [(size_t)B * NG];
__device__ float d_G1b     [(size_t)B * NG];
__device__ float d_c       [(size_t)2 * B * H];
__device__ float d_kv      [(size_t)B * TS * K2H];
__device__ float d_q       [(size_t)B * H];
__device__ float d_lat     [(size_t)B * LAT];

#define HW  256
__device__ uint32_t d_combH[(size_t)B * TS * HW];
__device__ uint32_t d_combL[(size_t)B * TS * HW];
__device__ uint32_t d_seqH [(size_t)B * TS * HW];
__device__ uint32_t d_seqL [(size_t)B * TS * HW];
__device__ uint32_t d_hH   [(size_t)2 * B * HW];
__device__ uint32_t d_hL   [(size_t)2 * B * HW];
__device__ uint32_t d_attH [(size_t)B * HW];
__device__ uint32_t d_attL [(size_t)B * HW];
__device__ uint32_t d_finH [(size_t)B * HW];
__device__ uint32_t d_finL [(size_t)B * HW];

#define OFF_W0   0
#define OFF_W1   1310720
#define OFF_AIN  2621440
#define OFF_AOUT 3014656
#define OFF_BNK  3145728
#define W_WORDS  3178496
__device__ uint32_t d_Wh[(size_t)W_WORDS];
__device__ uint32_t d_Wl[(size_t)W_WORDS];

// ---------------- helpers ----------------
__device__ __forceinline__ uint32_t pack_bf(float a, float b) {
    __nv_bfloat162 t = __floats2bfloat162_rn(a, b);
    return *reinterpret_cast<uint32_t*>(&t);
}
__device__ __forceinline__ float bf_hi(float x) {
    return __bfloat162float(__float2bfloat16_rn(x));
}
__device__ __forceinline__ uint32_t smem_u32(const void* p) {
    uint32_t a;
    asm("{ .reg .u64 t; cvta.to.shared.u64 t, %1; cvt.u32.u64 %0, t; }" : "=r"(a) : "l"(p));
    return a;
}

#define MMA16(d, a, b) \
    asm volatile( \
        "mma.sync.aligned.m16n8k16.row.col.f32.bf16.bf16.f32 " \
        "{%0,%1,%2,%3}, {%4,%5,%6,%7}, {%8,%9}, {%0,%1,%2,%3};" \
        : "+f"((d)[0]), "+f"((d)[1]), "+f"((d)[2]), "+f"((d)[3]) \
        : "r"((a)[0]), "r"((a)[1]), "r"((a)[2]), "r"((a)[3]), \
          "r"((b)[0]), "r"((b)[1]))

#define LDSM4(v, addr) \
    asm volatile("ldmatrix.sync.aligned.m8n8.x4.shared.b16 {%0,%1,%2,%3}, [%4];" \
        : "=r"((v)[0]), "=r"((v)[1]), "=r"((v)[2]), "=r"((v)[3]) : "r"(addr))

#define CP16(dst, src) \
    asm volatile("cp.async.cg.shared.global [%0], [%1], 16;" :: "r"(dst), "l"(src))
#define CPCOMMIT() asm volatile("cp.async.commit_group;" ::: "memory")
#define CPWAIT1()  asm volatile("cp.async.wait_group 1;" ::: "memory")

#define STG_WORDS 8192
#define GEMM_SMEM_BYTES (3 * STG_WORDS * 4)

// ---------------- fused zero init ----------------
__global__ void zero4_kernel(float* __restrict__ p0, int n0,
                             float* __restrict__ p1, int n1,
                             float* __restrict__ p2, int n2,
                             float* __restrict__ p3, int n3) {
    int i = blockIdx.x * blockDim.x + threadIdx.x;
    int stride = gridDim.x * blockDim.x;
    for (int j = i; j < n0; j += stride) p0[j] = 0.0f;
    for (int j = i; j < n1; j += stride) p1[j] = 0.0f;
    for (int j = i; j < n2; j += stride) p2[j] = 0.0f;
    for (int j = i; j < n3; j += stride) p3[j] = 0.0f;
}

// ---------------- bf16 hi/lo packed split ----------------
__device__ __forceinline__ void split_range(const float* __restrict__ src,
                                            uint32_t* __restrict__ hi,
                                            uint32_t* __restrict__ lo,
                                            int nwords, int i, int stride) {
    for (; i < nwords; i += stride) {
        float2 v = *(const float2*)(src + 2 * (size_t)i);
        float h0 = bf_hi(v.x), h1 = bf_hi(v.y);
        hi[i] = pack_bf(h0, h1);
        lo[i] = pack_bf(v.x - h0, v.y - h1);
    }
}
__global__ void split5_kernel(
    const float* __restrict__ s0, uint32_t* __restrict__ h0, uint32_t* __restrict__ l0, int n0,
    const float* __restrict__ s1, uint32_t* __restrict__ h1, uint32_t* __restrict__ l1, int n1,
    const float* __restrict__ s2, uint32_t* __restrict__ h2, uint32_t* __restrict__ l2, int n2,
    const float* __restrict__ s3, uint32_t* __restrict__ h3, uint32_t* __restrict__ l3, int n3,
    const float* __restrict__ s4, uint32_t* __restrict__ h4, uint32_t* __restrict__ l4, int n4) {
    int i = blockIdx.x * blockDim.x + threadIdx.x;
    int stride = gridDim.x * blockDim.x;
    split_range(s0, h0, l0, n0, i, stride);
    split_range(s1, h1, l1, n1, i, stride);
    split_range(s2, h2, l2, n2, i, stride);
    split_range(s3, h3, l3, n3, i, stride);
    split_range(s4, h4, l4, n4, i, stride);
}

// ================= bf16x3 GEMM core, single A source (cp.async + ldmatrix) ==========
// C[M,N] = A @ W^T (+ bias). A packed hi/lo (lda words/row), W packed hi/lo
// (ldw words/row, using Kw words starting at the given base).
__device__ __forceinline__ void gemm_core(
    const uint32_t* __restrict__ Ah, const uint32_t* __restrict__ Al, int lda,
    const uint32_t* __restrict__ Wh, const uint32_t* __restrict__ Wl, int ldw, int Kw,
    const float* __restrict__ bias,
    float* __restrict__ C, uint32_t* __restrict__ Ch, uint32_t* __restrict__ Cl,
    int N, int m0, int n0, uint32_t smb)
{
    const int tid = threadIdx.x;
    const int wid = tid >> 5, lane = tid & 31;
    const int g = lane >> 2, t4 = lane & 3;
    const int warp_m = wid >> 2, warp_n = wid & 3;

    const int r = tid >> 1, half = tid & 1;
    const int wb = half * 8;
    const int swz = ((r >> 1) & 3) << 2;
    const int so0 = r * 16 + ((wb) ^ swz);
    const int so1 = r * 16 + ((wb + 4) ^ swz);

    const int a_r = lane & 15;
    const int a_k = (lane >> 4) << 2;
    int aoff[4], aswz[4];
    #pragma unroll
    for (int tm = 0; tm < 4; tm++) {
        const int row = warp_m * 64 + tm * 16 + a_r;
        aoff[tm] = row * 16;
        aswz[tm] = ((row >> 1) & 3) << 2;
    }
    const int b_r = (lane & 7) + ((lane >> 4) << 3);
    const int b_k = ((lane >> 3) & 1) << 2;
    int boff[2], bswz[2];
    #pragma unroll
    for (int tp = 0; tp < 2; tp++) {
        const int row = warp_n * 32 + tp * 16 + b_r;
        boff[tp] = row * 16;
        bswz[tp] = ((row >> 1) & 3) << 2;
    }

    float acc[4][4][4];
    #pragma unroll
    for (int i = 0; i < 4; i++)
        #pragma unroll
        for (int j = 0; j < 4; j++)
            #pragma unroll
            for (int e = 0; e < 4; e++) acc[i][j][e] = 0.0f;

    const int NKB = Kw / 16;
    const uint32_t* arow_h = Ah + (size_t)(m0 + r) * lda + wb;
    const uint32_t* arow_l = Al + (size_t)(m0 + r) * lda + wb;
    const uint32_t* brow_h = Wh + (size_t)(n0 + r) * ldw + wb;
    const uint32_t* brow_l = Wl + (size_t)(n0 + r) * ldw + wb;

    auto issue = [&](int kb, int stage) {
        const int kw = kb * 16;
        const uint32_t sb = smb + (uint32_t)(stage * STG_WORDS) * 4;
        CP16(sb + so0 * 4, arow_h + kw);          CP16(sb + so1 * 4, arow_h + kw + 4);
        CP16(sb + (2048 + so0) * 4, arow_l + kw); CP16(sb + (2048 + so1) * 4, arow_l + kw + 4);
        CP16(sb + (4096 + so0) * 4, brow_h + kw); CP16(sb + (4096 + so1) * 4, brow_h + kw + 4);
        CP16(sb + (6144 + so0) * 4, brow_l + kw); CP16(sb + (6144 + so1) * 4, brow_l + kw + 4);
    };

    issue(0, 0); CPCOMMIT();
    issue(1, 1); CPCOMMIT();

    for (int kb = 0; kb < NKB; kb++) {
        CPWAIT1();
        __syncthreads();
        const uint32_t sbase = smb + (uint32_t)((kb % 3) * STG_WORDS) * 4;

        #pragma unroll
        for (int kc = 0; kc < 2; kc++) {
            const int akw = kc * 8 + a_k;
            const int bkw = kc * 8 + b_k;
            uint32_t Bh[2][4], Bl[2][4];
            #pragma unroll
            for (int tp = 0; tp < 2; tp++) {
                const uint32_t bd = sbase + (uint32_t)(4096 + boff[tp] + (bkw ^ bswz[tp])) * 4;
                LDSM4(Bh[tp], bd);
                LDSM4(Bl[tp], bd + 2048 * 4);
            }
            #pragma unroll
            for (int tm = 0; tm < 4; tm++) {
                uint32_t Ahf[4], Alf[4];
                const uint32_t ad = sbase + (uint32_t)(aoff[tm] + (akw ^ aswz[tm])) * 4;
                LDSM4(Ahf, ad);
                LDSM4(Alf, ad + 2048 * 4);
                #pragma unroll
                for (int tn = 0; tn < 4; tn++) {
                    uint32_t* bh = &Bh[tn >> 1][(tn & 1) * 2];
                    uint32_t* bl = &Bl[tn >> 1][(tn & 1) * 2];
                    MMA16(acc[tm][tn], Ahf, bh);
                    MMA16(acc[tm][tn], Ahf, bl);
                    MMA16(acc[tm][tn], Alf, bh);
                }
            }
        }
        if (kb + 2 < NKB) issue(kb + 2, (kb + 2) % 3);
        CPCOMMIT();
    }

    const int Nw = N >> 1;
    #pragma unroll
    for (int tm = 0; tm < 4; tm++) {
        const int row0 = m0 + warp_m * 64 + tm * 16 + g;
        #pragma unroll
        for (int tn = 0; tn < 4; tn++) {
            const int col = n0 + warp_n * 32 + tn * 8 + t4 * 2;
            float b0 = 0.0f, b1 = 0.0f;
            if (bias) { b0 = bias[col]; b1 = bias[col + 1]; }
            const float v00 = acc[tm][tn][0] + b0, v01 = acc[tm][tn][1] + b1;
            const float v10 = acc[tm][tn][2] + b0, v11 = acc[tm][tn][3] + b1;
            if (C) {
                *(float2*)(C + (size_t)row0 * N + col)       = make_float2(v00, v01);
                *(float2*)(C + (size_t)(row0 + 8) * N + col) = make_float2(v10, v11);
            }
            if (Ch) {
                const int w = (col >> 1);
                float h00 = bf_hi(v00), h01 = bf_hi(v01);
                float h10 = bf_hi(v10), h11 = bf_hi(v11);
                Ch[(size_t)row0 * Nw + w]       = pack_bf(h00, h01);
                Cl[(size_t)row0 * Nw + w]       = pack_bf(v00 - h00, v01 - h01);
                Ch[(size_t)(row0 + 8) * Nw + w] = pack_bf(h10, h11);
                Cl[(size_t)(row0 + 8) * Nw + w] = pack_bf(v10 - h10, v11 - h11);
            }
        }
    }
}

__global__ __launch_bounds__(256, 2) void gemm_one(
    const uint32_t* __restrict__ Ah, const uint32_t* __restrict__ Al, int lda,
    const uint32_t* __restrict__ Wh, const uint32_t* __restrict__ Wl, int ldw, int Kw,
    const float* __restrict__ bias,
    float* __restrict__ C, uint32_t* __restrict__ Ch, uint32_t* __restrict__ Cl,
    int N)
{
    extern __shared__ uint32_t sm[];
    gemm_core(Ah, Al, lda, Wh, Wl, ldw, Kw, bias,
              C, Ch, Cl, N, blockIdx.x * 128, blockIdx.y * 128, smem_u32(sm));
}

// Quad GEMM (split-K=2 over both recurrent layers):
//  z=0: G1a = h0(t)   @ W1[:, :H] + gb1
//  z=1: G1b = h1(t-1) @ W1[:, H:]
//  z=2: G0a = comb(t+1) @ W0[:, :H] + gb0   (skipped when !has2)
//  z=3: G0b = h0(t)   @ W0[:, H:]           (skipped when !has2)
__global__ __launch_bounds__(256, 2) void gemm_quad(
    const uint32_t* __restrict__ h0H, const uint32_t* __restrict__ h0L,
    const uint32_t* __restrict__ h1H, const uint32_t* __restrict__ h1L,
    const uint32_t* __restrict__ combH, const uint32_t* __restrict__ combL,
    const uint32_t* __restrict__ Wall_h, const uint32_t* __restrict__ Wall_l,
    const float* __restrict__ gb0, const float* __restrict__ gb1,
    float* __restrict__ G0a, float* __restrict__ G0b,
    float* __restrict__ G1a, float* __restrict__ G1b,
    int has2)
{
    extern __shared__ uint32_t sm[];
    const uint32_t *Ah, *Al, *Wh, *Wl;
    const float* bias = nullptr;
    float* C;
    int lda;
    switch (blockIdx.z) {
        case 0: Ah = h0H; Al = h0L; lda = HW;
                Wh = Wall_h + OFF_W1; Wl = Wall_l + OFF_W1;
                bias = gb1; C = G1a; break;
        case 1: Ah = h1H; Al = h1L; lda = HW;
                Wh = Wall_h + OFF_W1 + HW; Wl = Wall_l + OFF_W1 + HW;
                C = G1b; break;
        case 2: if (!has2) return;
                Ah = combH; Al = combL; lda = TS * HW;
                Wh = Wall_h + OFF_W0; Wl = Wall_l + OFF_W0;
                bias = gb0; C = G0a; break;
        default: if (!has2) return;
                Ah = h0H; Al = h0L; lda = HW;
                Wh = Wall_h + OFF_W0 + HW; Wl = Wall_l + OFF_W0 + HW;
                C = G0b; break;
    }
    gemm_core(Ah, Al, lda, Wh, Wl, 2 * HW, HW, bias,
              C, nullptr, nullptr, NG, blockIdx.x * 128, blockIdx.y * 128, smem_u32(sm));
}

// ---------------- frontend ----------------
__global__ __launch_bounds__(256) void frontend_kernel(
    const float* __restrict__ x,
    const float* __restrict__ conv_w, const float* __restrict__ conv_b,
    const float* __restrict__ bn1_g, const float* __restrict__ bn1_b,
    const float* __restrict__ bn1_rm, const float* __restrict__ bn1_rv,
    const float* __restrict__ comp_w, const float* __restrict__ comp_b,
    const float* __restrict__ proj_w, const float* __restrict__ proj_b,
    float* __restrict__ combined)
{
    __shared__ float xs[TT][17];
    __shared__ float cw[24 * 9 * 3];
    __shared__ float cbias[24], cscale[24], cshift[24];
    __shared__ float cpw[20 * 8], cpb[20];
    __shared__ float feat[TS][44];

    const int b = blockIdx.x;
    const int tid = threadIdx.x;
    const float* xb = x + (size_t)b * TT * 17;

    for (int i = tid; i < TT * 17; i += 256) xs[i / 17][i % 17] = xb[i];
    for (int i = tid; i < 648; i += 256) cw[i] = conv_w[i];
    if (tid < 24) {
        cbias[tid] = conv_b[tid];
        float s = bn1_g[tid] * rsqrtf(bn1_rv[tid] + EPS);
        cscale[tid] = s;
        cshift[tid] = bn1_b[tid] - bn1_rm[tid] * s;
    }
    for (int i = tid; i < 160; i += 256) cpw[i] = comp_w[i];
    if (tid < 20) cpb[tid] = comp_b[tid];
    __syncthreads();

    for (int idx = tid; idx < 24 * TS; idx += 256) {
        int o = idx % 24, th = idx / 24;
        float mx = -1e30f;
        #pragma unroll
        for (int s = 0; s < 2; s++) {
            int t = th * 2 + s;
            float acc = cbias[o];
            #pragma unroll
            for (int k = 0; k < 3; k++) {
                int tt = t + k - 1;
                if (tt >= 0 && tt < TT) {
                    #pragma unroll
                    for (int i2 = 0; i2 < 9; i2++)
                        acc += xs[tt][i2] * cw[o * 27 + i2 * 3 + k];
                }
            }
            acc = fmaxf(acc, 0.0f);
            acc = acc * cscale[o] + cshift[o];
            mx = fmaxf(mx, acc);
        }
        feat[th][o] = mx;
    }
    for (int idx = tid; idx < TS * 20; idx += 256) {
        int j = idx % 20, t = idx / 20;
        float acc = cpb[j];
        #pragma unroll
        for (int i2 = 0; i2 < 8; i2++) acc += xs[t][9 + i2] * cpw[j * 8 + i2];
        feat[t][24 + j] = fmaxf(acc, 0.0f);
    }
    __syncthreads();

    for (int hh = tid; hh < H; hh += 256) {
        float w[44];
        #pragma unroll
        for (int f = 0; f < 44; f++) w[f] = proj_w[hh * 44 + f];
        float pb = proj_b[hh];
        for (int t = 0; t < TS; t++) {
            float acc = pb;
            #pragma unroll
            for (int f = 0; f < 44; f++) acc += feat[t][f] * w[f];
            combined[((size_t)b * TS + t) * H + hh] = acc;
        }
    }
}

// ---------------- gate core: warp per batch row, sums 2 G partials ----------------
__device__ __forceinline__ float sigm(float v) { return 1.0f / (1.0f + expf(-v)); }

__device__ __forceinline__ void warp_ln(const float* v, float& mu, float& rs) {
    float s = 0.0f, q = 0.0f;
    #pragma unroll
    for (int i = 0; i < 16; i++) { s += v[i]; q += v[i] * v[i]; }
    #pragma unroll
    for (int o = 16; o > 0; o >>= 1) {
        s += __shfl_xor_sync(0xffffffffu, s, o);
        q += __shfl_xor_sync(0xffffffffu, q, o);
    }
    mu = s * (1.0f / 512.0f);
    rs = rsqrtf(q * (1.0f / 512.0f) - mu * mu + EPS);
}

__device__ __forceinline__ float4 add4(float4 a, float4 b) {
    return make_float4(a.x + b.x, a.y + b.y, a.z + b.z, a.w + b.w);
}

__device__ __forceinline__ void gate_core(
    const float* __restrict__ Ga, const float* __restrict__ Gb,
    uint32_t* __restrict__ hH, uint32_t* __restrict__ hL,
    float* __restrict__ c,
    const float* __restrict__ ret,
    const float* __restrict__ eg, const float* __restrict__ ebb,
    const float* __restrict__ lg, const float* __restrict__ lbb,
    uint32_t* __restrict__ soH, uint32_t* __restrict__ soL)  // seq packed, may be null
{
    const int wid = threadIdx.x >> 5, lid = threadIdx.x & 31;
    const size_t b = (size_t)blockIdx.x * 8 + wid;
    const float* ga = Ga + b * NG;
    const float* gbp = Gb + b * NG;
    float* crow = c + b * H;

    float o_[16], cn_[16];
    #pragma unroll
    for (int j = 0; j < 4; j++) {
        const int col = lid * 4 + j * 128;
        float4 vf = add4(__ldcs((const float4*)(ga + 0 * H + col)), __ldcs((const float4*)(gbp + 0 * H + col)));
        float4 vi = add4(__ldcs((const float4*)(ga + 1 * H + col)), __ldcs((const float4*)(gbp + 1 * H + col)));
        float4 vo = add4(__ldcs((const float4*)(ga + 2 * H + col)), __ldcs((const float4*)(gbp + 2 * H + col)));
        float4 vc = add4(__ldcs((const float4*)(ga + 3 * H + col)), __ldcs((const float4*)(gbp + 3 * H + col)));
        float4 vm = add4(__ldcs((const float4*)(ga + 4 * H + col)), __ldcs((const float4*)(gbp + 4 * H + col)));
        float4 cp = *(const float4*)(crow + col);
        float4 rr = *(const float4*)(ret + col);
        float bf[4], bi[4], bo[4], bc[4], bm[4], bp[4], br[4];
        *(float4*)bf = vf; *(float4*)bi = vi; *(float4*)bo = vo;
        *(float4*)bc = vc; *(float4*)bm = vm; *(float4*)bp = cp; *(float4*)br = rr;
        #pragma unroll
        for (int e = 0; e < 4; e++) {
            float f = sigm(bf[e]), iv = sigm(bi[e]), m = sigm(bm[e]);
            float ccv = tanhf(bc[e]);
            float cpv = bp[e], rv = br[e];
            float cn = f * cpv + iv * ccv;
            cn = cn * rv + (1.0f - rv) * cpv;
            cn = m * cn + (1.0f - m) * cpv;
            cn_[j * 4 + e] = cn;
            o_[j * 4 + e] = sigm(bo[e]);
        }
    }

    float mu1, rs1;
    warp_ln(o_, mu1, rs1);
    float u_[16];
    #pragma unroll
    for (int j = 0; j < 4; j++) {
        const int col = lid * 4 + j * 128;
        float4 ge = *(const float4*)(eg + col);
        float4 be = *(const float4*)(ebb + col);
        float g_[4], b_[4];
        *(float4*)g_ = ge; *(float4*)b_ = be;
        #pragma unroll
        for (int e = 0; e < 4; e++) {
            float on = (o_[j * 4 + e] - mu1) * rs1 * g_[e] + b_[e];
            u_[j * 4 + e] = sigm(on) * tanhf(cn_[j * 4 + e]);
        }
    }

    float mu2, rs2;
    warp_ln(u_, mu2, rs2);
    #pragma unroll
    for (int j = 0; j < 4; j++) {
        const int col = lid * 4 + j * 128;
        float4 gl = *(const float4*)(lg + col);
        float4 bl = *(const float4*)(lbb + col);
        float g_[4], b_[4], hn[4], cv[4];
        *(float4*)g_ = gl; *(float4*)b_ = bl;
        #pragma unroll
        for (int e = 0; e < 4; e++) {
            hn[e] = (u_[j * 4 + e] - mu2) * rs2 * g_[e] + b_[e];
            cv[e] = cn_[j * 4 + e];
        }
        *(float4*)(crow + col) = *(float4*)cv;
        float h0 = bf_hi(hn[0]), h1 = bf_hi(hn[1]), h2 = bf_hi(hn[2]), h3 = bf_hi(hn[3]);
        uint2 wh, wl;
        wh.x = pack_bf(h0, h1);              wh.y = pack_bf(h2, h3);
        wl.x = pack_bf(hn[0] - h0, hn[1] - h1);
        wl.y = pack_bf(hn[2] - h2, hn[3] - h3);
        *(uint2*)(hH + b * HW + (col >> 1)) = wh;
        *(uint2*)(hL + b * HW + (col >> 1)) = wl;
        if (soH) {
            *(uint2*)(soH + b * TS * HW + (col >> 1)) = wh;
            *(uint2*)(soL + b * TS * HW + (col >> 1)) = wl;
        }
    }
}

__global__ __launch_bounds__(256) void gate_kernel(
    const float* __restrict__ Ga, const float* __restrict__ Gb,
    uint32_t* __restrict__ hH, uint32_t* __restrict__ hL,
    float* __restrict__ c,
    const float* __restrict__ ret,
    const float* __restrict__ eg, const float* __restrict__ ebb,
    const float* __restrict__ lg, const float* __restrict__ lbb)
{
    gate_core(Ga, Gb, hH, hL, c, ret, eg, ebb, lg, lbb, nullptr, nullptr);
}

// Dual gate: y=0 -> gate1(t) (writes seq packed) ; y=1 -> gate0(t+1)
__global__ __launch_bounds__(256) void gate_dual(
    const float* __restrict__ G1a, const float* __restrict__ G1b,
    uint32_t* __restrict__ h1H, uint32_t* __restrict__ h1L, float* __restrict__ c1,
    const float* __restrict__ G0a, const float* __restrict__ G0b,
    uint32_t* __restrict__ h0H, uint32_t* __restrict__ h0L, float* __restrict__ c0,
    const float* __restrict__ ret,
    const float* __restrict__ eg, const float* __restrict__ ebb,
    const float* __restrict__ lg, const float* __restrict__ lbb,
    uint32_t* __restrict__ soH, uint32_t* __restrict__ soL, int has2)
{
    if (blockIdx.y == 0) {
        gate_core(G1a, G1b, h1H, h1L, c1, ret + H, eg + H, ebb + H, lg + H, lbb + H,
                  soH, soL);
    } else {
        if (!has2) return;
        gate_core(G0a, G0b, h0H, h0L, c0, ret, eg, ebb, lg, lbb, nullptr, nullptr);
    }
}

// ---------------- last-query attention ----------------
__global__ __launch_bounds__(128) void attn_kernel(
    const float* __restrict__ q,
    const float* __restrict__ kv,
    uint32_t* __restrict__ attH, uint32_t* __restrict__ attL)
{
    __shared__ float qs[DH];
    __shared__ float sc[TS];
    const int b = blockIdx.x, hd = blockIdx.y;
    const int tid = threadIdx.x;

    qs[tid] = q[(size_t)b * H + hd * DH + tid];
    __syncthreads();

    if (tid < TS) {
        const float* kr = kv + ((size_t)b * TS + tid) * K2H + hd * DH;
        float s = 0.0f;
        #pragma unroll 16
        for (int d = 0; d < DH; d++) s += qs[d] * kr[d];
        sc[tid] = s * 0.08838834764831845f;
    }
    __syncthreads();

    float mx = -1e30f;
    #pragma unroll
    for (int t = 0; t < TS; t++) mx = fmaxf(mx, sc[t]);
    float p[TS], ssum = 0.0f;
    #pragma unroll
    for (int t = 0; t < TS; t++) { p[t] = expf(sc[t] - mx); ssum += p[t]; }
    float inv = 1.0f / ssum;

    float acc = 0.0f;
    #pragma unroll
    for (int t = 0; t < TS; t++)
        acc += p[t] * kv[((size_t)b * TS + t) * K2H + H + hd * DH + tid];
    float v = acc * inv;

    float pv = __shfl_down_sync(0xffffffffu, v, 1);
    if (!(tid & 1)) {
        float h0 = bf_hi(v), h1 = bf_hi(pv);
        const size_t w = (size_t)b * HW + hd * (DH / 2) + (tid >> 1);
        attH[w] = pack_bf(h0, h1);
        attL[w] = pack_bf(v - h0, pv - h1);
    }
}

// ---------------- bn2 + output head ----------------
__global__ __launch_bounds__(256) void head_kernel(
    const float* __restrict__ latent,
    const float* __restrict__ bn2_g, const float* __restrict__ bn2_b,
    const float* __restrict__ bn2_rm, const float* __restrict__ bn2_rv,
    const float* __restrict__ out_w, const float* __restrict__ out_b,
    float* __restrict__ out)
{
    __shared__ float lw[OUT * LAT];
    __shared__ float ls[16][LAT];
    __shared__ float scale[LAT], shift[LAT];
    const int b0 = blockIdx.x * 16;
    const int tid = threadIdx.x;

    if (tid < LAT) {
        float s = bn2_g[tid] * rsqrtf(bn2_rv[tid] + EPS);
        scale[tid] = s;
        shift[tid] = bn2_b[tid] - bn2_rm[tid] * s;
    }
    for (int i = tid; i < OUT * LAT; i += 256) lw[i] = out_w[i];
    __syncthreads();

    for (int i = tid; i < 16 * LAT; i += 256) {
        int r = i / LAT, j = i % LAT;
        ls[r][j] = latent[(size_t)(b0 + r) * LAT + j] * scale[j] + shift[j];
    }
    __syncthreads();

    for (int idx = tid; idx < 16 * OUT; idx += 256) {
        int r = idx / OUT, o = idx % OUT;
        float acc = out_b[o];
        #pragma unroll 16
        for (int j = 0; j < LAT; j++) acc += ls[r][j] * lw[o * LAT + j];
        out[(size_t)(b0 + r) * OUT + o] = acc;
    }
}

// ---------------- host launch ----------------
extern "C" void kernel_launch(void* const* d_in, const int* in_sizes, int n_in,
                              void* d_out, int out_size)
{
    const float* x        = (const float*)d_in[0];
    const float* conv1_w  = (const float*)d_in[1];
    const float* conv1_b  = (const float*)d_in[2];
    const float* bn1_g    = (const float*)d_in[3];
    const float* bn1_b    = (const float*)d_in[4];
    const float* bn1_rm   = (const float*)d_in[5];
    const float* bn1_rv   = (const float*)d_in[6];
    const float* comp_w   = (const float*)d_in[7];
    const float* comp_b   = (const float*)d_in[8];
    const float* proj_w   = (const float*)d_in[9];
    const float* proj_b   = (const float*)d_in[10];
    const float* gates_w  = (const float*)d_in[11];
    const float* gates_b  = (const float*)d_in[12];
    const float* retention= (const float*)d_in[13];
    const float* expln_g  = (const float*)d_in[14];
    const float* expln_b  = (const float*)d_in[15];
    const float* ln_g     = (const float*)d_in[16];
    const float* ln_b     = (const float*)d_in[17];
    const float* attn_in_w= (const float*)d_in[18];
    const float* attn_in_b= (const float*)d_in[19];
    const float* attn_out_w=(const float*)d_in[20];
    const float* attn_out_b=(const float*)d_in[21];
    const float* bneck_w  = (const float*)d_in[22];
    const float* bneck_b  = (const float*)d_in[23];
    const float* bn2_g    = (const float*)d_in[24];
    const float* bn2_b    = (const float*)d_in[25];
    const float* bn2_rm   = (const float*)d_in[26];
    const float* bn2_rv   = (const float*)d_in[27];
    const float* out_w    = (const float*)d_in[28];
    const float* out_b    = (const float*)d_in[29];
    float* out = (float*)d_out;

    cudaFuncSetAttribute(gemm_one, cudaFuncAttributeMaxDynamicSharedMemorySize,
                         GEMM_SMEM_BYTES);
    cudaFuncSetAttribute(gemm_quad, cudaFuncAttributeMaxDynamicSharedMemorySize,
                         GEMM_SMEM_BYTES);

    float *combined, *G0a, *G0b, *G1a, *G1b, *c, *kv, *q, *lat;
    uint32_t *combH, *combL, *seqH, *seqL, *hH, *hL, *attH, *attL, *finH, *finL, *Wh, *Wl;
    cudaGetSymbolAddress((void**)&combined, d_combined);
    cudaGetSymbolAddress((void**)&G0a,      d_G0a);
    cudaGetSymbolAddress((void**)&G0b,      d_G0b);
    cudaGetSymbolAddress((void**)&G1a,      d_G1a);
    cudaGetSymbolAddress((void**)&G1b,      d_G1b);
    cudaGetSymbolAddress((void**)&c,        d_c);
    cudaGetSymbolAddress((void**)&kv,       d_kv);
    cudaGetSymbolAddress((void**)&q,        d_q);
    cudaGetSymbolAddress((void**)&lat,      d_lat);
    cudaGetSymbolAddress((void**)&combH,    d_combH);
    cudaGetSymbolAddress((void**)&combL,    d_combL);
    cudaGetSymbolAddress((void**)&seqH,     d_seqH);
    cudaGetSymbolAddress((void**)&seqL,     d_seqL);
    cudaGetSymbolAddress((void**)&hH,       d_hH);
    cudaGetSymbolAddress((void**)&hL,       d_hL);
    cudaGetSymbolAddress((void**)&attH,     d_attH);
    cudaGetSymbolAddress((void**)&attL,     d_attL);
    cudaGetSymbolAddress((void**)&finH,     d_finH);
    cudaGetSymbolAddress((void**)&finL,     d_finL);
    cudaGetSymbolAddress((void**)&Wh,       d_Wh);
    cudaGetSymbolAddress((void**)&Wl,       d_Wl);

    uint32_t* h0H = hH;              uint32_t* h0L = hL;
    uint32_t* h1H = hH + (size_t)B * HW;
    uint32_t* h1L = hL + (size_t)B * HW;
    float* c0 = c;
    float* c1 = c + (size_t)B * H;

    // zero: c, packed h, G0b (so t=0's gate0 sees G0 = G0a + 0)
    zero4_kernel<<<2048, 512>>>(c, 2 * B * H,
                                (float*)hH, 2 * B * HW,
                                (float*)hL, 2 * B * HW,
                                G0b, B * NG);
    frontend_kernel<<<B, 256>>>(x, conv1_w, conv1_b, bn1_g, bn1_b, bn1_rm, bn1_rv,
                                comp_w, comp_b, proj_w, proj_b, combined);
    split5_kernel<<<8192, 256>>>(
        gates_w,    Wh + OFF_W0,   Wl + OFF_W0,   NG * K2H,
        combined,   combH,         combL,         B * TS * H / 2,
        attn_in_w,  Wh + OFF_AIN,  Wl + OFF_AIN,  3 * H * H / 2,
        attn_out_w, Wh + OFF_AOUT, Wl + OFF_AOUT, H * H / 2,
        bneck_w,    Wh + OFF_BNK,  Wl + OFF_BNK,  LAT * H / 2);

    const float* gb0 = gates_b;
    const float* gb1 = gates_b + NG;

    // prologue: G0a(0) = comb(0) @ W0[:, :H] + gb0  (G0b zeroed)
    gemm_one<<<dim3(B / 128, NG / 128), 256, GEMM_SMEM_BYTES>>>(
        combH, combL, TS * HW, Wh + OFF_W0, Wl + OFF_W0, 2 * HW, HW,
        gb0, G0a, nullptr, nullptr, NG);
    gate_kernel<<<B / 8, 256>>>(G0a, G0b, h0H, h0L, c0,
                                retention, expln_g, expln_b, ln_g, ln_b);

    // scan
    dim3 quad_grid(B / 128, NG / 128, 4);
    for (int t = 0; t < TS; t++) {
        const int has2 = (t + 1 < TS) ? 1 : 0;
        gemm_quad<<<quad_grid, 256, GEMM_SMEM_BYTES>>>(
            h0H, h0L, h1H, h1L,
            combH + (size_t)(t + 1) * HW, combL + (size_t)(t + 1) * HW,
            Wh, Wl, gb0, gb1, G0a, G0b, G1a, G1b, has2);
        gate_dual<<<dim3(B / 8, 2), 256>>>(
            G1a, G1b, h1H, h1L, c1,
            G0a, G0b, h0H, h0L, c0,
            retention, expln_g, expln_b, ln_g, ln_b,
            seqH + (size_t)t * HW, seqL + (size_t)t * HW, has2);
    }

    // k,v: (B*30, 512) @ (512, 1024)  [attn_in rows 512..1535]
    gemm_one<<<dim3(B * TS / 128, K2H / 128), 256, GEMM_SMEM_BYTES>>>(
        seqH, seqL, HW,
        Wh + OFF_AIN + (size_t)H * HW, Wl + OFF_AIN + (size_t)H * HW, HW, HW,
        attn_in_b + H, kv, nullptr, nullptr, K2H);
    // q at last timestep
    gemm_one<<<dim3(B / 128, H / 128), 256, GEMM_SMEM_BYTES>>>(
        seqH + (size_t)(TS - 1) * HW, seqL + (size_t)(TS - 1) * HW, TS * HW,
        Wh + OFF_AIN, Wl + OFF_AIN, HW, HW,
        attn_in_b, q, nullptr, nullptr, H);
    attn_kernel<<<dim3(B, NH), 128>>>(q, kv, attH, attL);
    gemm_one<<<dim3(B / 128, H / 128), 256, GEMM_SMEM_BYTES>>>(
        attH, attL, HW, Wh + OFF_AOUT, Wl + OFF_AOUT, HW, HW,
        attn_out_b, nullptr, finH, finL, H);
    gemm_one<<<dim3(B / 128, LAT / 128), 256, GEMM_SMEM_BYTES>>>(
        finH, finL, HW, Wh + OFF_BNK, Wl + OFF_BNK, HW, HW,
        bneck_b, lat, nullptr, nullptr, LAT);
    head_kernel<<<B / 16, 256>>>(lat, bn2_g, bn2_b, bn2_rm, bn2_rv, out_w, out_b, out);
}